// round 1
// baseline (speedup 1.0000x reference)
#include <cuda_runtime.h>
#include <math.h>

// Problem constants
#define Bn   64
#define Cc   256
#define Nn   4096
#define HIDn 512
#define Tt   128
#define Mm   128
#define Aa   128
#define NTOT 4224   // Nn + Tt

// -------- device scratch (allocation-free: __device__ globals) --------
__device__ float g_WimgT[Cc * Mm];        // [256][128]
__device__ float g_WtxtT[HIDn * Mm];      // [512][128]
__device__ float g_WipcT[Mm * Aa];        // [128][128]
__device__ float g_WqpcT[Mm * Aa];        // [128][128]
__device__ float g_inqfeat[Bn * Mm * Tt];     // 4 MB
__device__ float g_qfeatproj[Bn * Aa * Tt];   // 4 MB
__device__ float g_qfeatatt[Bn * Aa];
__device__ float g_inifeat[33554432];         // [64][128][4096] = 128 MB
__device__ float g_ipart[Bn * 32 * Mm];       // per-tile row-sum partials (no atomics)
__device__ float g_logits[Bn * Nn];

// ---------------- prep: transpose weights for coalesced GEMM loads ----------------
__global__ void prep_kernel(const float* __restrict__ Wimg, const float* __restrict__ Wtxt,
                            const float* __restrict__ Wipc, const float* __restrict__ Wqpc)
{
    int i = blockIdx.x * blockDim.x + threadIdx.x;
    if (i < Mm * Cc)   { int m = i / Cc,   k = i % Cc;   g_WimgT[k * Mm + m] = Wimg[i]; }
    if (i < Mm * HIDn) { int m = i / HIDn, k = i % HIDn; g_WtxtT[k * Mm + m] = Wtxt[i]; }
    if (i < Aa * Mm)   { int a = i / Mm,   k = i % Mm;
                         g_WipcT[k * Aa + a] = Wipc[i];
                         g_WqpcT[k * Aa + a] = Wqpc[i]; }
}

// ---------------- shared micro-kernel: one K-slice rank-1 style update ----------------
// 16x16 thread grid; each thread computes an 8x8 micro-tile split as (2x4)x(2x4)
// row groups at ty*4 and 64+ty*4, col groups at tx*4 and 64+tx*4 (conflict-free LDS.128)
__device__ __forceinline__ void mma_step(const float* __restrict__ Arow,
                                         const float* __restrict__ Brow,
                                         int tx, int ty, float acc[8][8])
{
    float a[8], bb[8];
    *(float4*)&a[0]  = *(const float4*)(Arow + ty * 4);
    *(float4*)&a[4]  = *(const float4*)(Arow + 64 + ty * 4);
    *(float4*)&bb[0] = *(const float4*)(Brow + tx * 4);
    *(float4*)&bb[4] = *(const float4*)(Brow + 64 + tx * 4);
#pragma unroll
    for (int i = 0; i < 8; i++)
#pragma unroll
        for (int j = 0; j < 8; j++)
            acc[i][j] = fmaf(a[i], bb[j], acc[i][j]);
}

// smem layout (floats): As[2048] | Bs[2048] | T1[128*132] | red[128*17] | extras[256]
#define SM_T1   4096
#define SM_RED  (4096 + 128 * 132)
#define SM_X0   (SM_RED + 128 * 17)
#define SMEM_FLOATS (SM_X0 + 256)

// ---------------- text branch: in_qfeat, qmean, qfeatproj, qfeatatt ----------------
__global__ void __launch_bounds__(256) text_kernel(const float* __restrict__ text,
                                                   const float* __restrict__ Wqfc)
{
    extern __shared__ float sm[];
    float* As  = sm;
    float* Bs  = sm + 2048;
    float* T1  = sm + SM_T1;
    float* red = sm + SM_RED;
    float* qm  = sm + SM_X0;

    const int tid = threadIdx.x;
    const int tx = tid & 15, ty = tid >> 4;
    const int b = blockIdx.x;
    const float* tb = text + (size_t)b * HIDn * Tt;

    float acc[8][8];
#pragma unroll
    for (int i = 0; i < 8; i++)
#pragma unroll
        for (int j = 0; j < 8; j++) acc[i][j] = 0.f;

    // GEMM1: in_qfeat[m][t] = tanh( sum_k WtxtT[k][m] * text[b][k][t] ), K=512
    for (int k0 = 0; k0 < HIDn; k0 += 16) {
        *(float4*)(As + tid * 8)     = *(const float4*)(g_WtxtT + k0 * 128 + tid * 8);
        *(float4*)(As + tid * 8 + 4) = *(const float4*)(g_WtxtT + k0 * 128 + tid * 8 + 4);
        *(float4*)(Bs + tid * 8)     = *(const float4*)(tb + k0 * 128 + tid * 8);
        *(float4*)(Bs + tid * 8 + 4) = *(const float4*)(tb + k0 * 128 + tid * 8 + 4);
        __syncthreads();
#pragma unroll
        for (int kk = 0; kk < 16; kk++)
            mma_step(As + kk * 128, Bs + kk * 128, tx, ty, acc);
        __syncthreads();
    }

    // tanh, store in_qfeat + T1, row partial sums for qmean
#pragma unroll
    for (int i = 0; i < 8; i++) {
#pragma unroll
        for (int j = 0; j < 8; j++) acc[i][j] = tanhf(acc[i][j]);
        int m = (i < 4 ? 0 : 64) + ty * 4 + (i & 3);
        float4 v0 = make_float4(acc[i][0], acc[i][1], acc[i][2], acc[i][3]);
        float4 v1 = make_float4(acc[i][4], acc[i][5], acc[i][6], acc[i][7]);
        float* grow = g_inqfeat + b * (Mm * Tt) + m * Tt;
        *(float4*)(grow + tx * 4)      = v0;
        *(float4*)(grow + 64 + tx * 4) = v1;
        float* trow = T1 + m * 132;
        *(float4*)(trow + tx * 4)      = v0;
        *(float4*)(trow + 64 + tx * 4) = v1;
        red[m * 17 + tx] = acc[i][0] + acc[i][1] + acc[i][2] + acc[i][3]
                         + acc[i][4] + acc[i][5] + acc[i][6] + acc[i][7];
    }
    __syncthreads();
    if (tid < 128) {
        float s = 0.f;
#pragma unroll
        for (int t = 0; t < 16; t++) s += red[tid * 17 + t];
        qm[tid] = s * (1.f / (float)Tt);
    }
    __syncthreads();

    // GEMM2: qfeatproj[a][t] = sum_k WqpcT[k][a] * T1[k][t], K=128
#pragma unroll
    for (int i = 0; i < 8; i++)
#pragma unroll
        for (int j = 0; j < 8; j++) acc[i][j] = 0.f;
    for (int k0 = 0; k0 < 128; k0 += 16) {
        *(float4*)(As + tid * 8)     = *(const float4*)(g_WqpcT + k0 * 128 + tid * 8);
        *(float4*)(As + tid * 8 + 4) = *(const float4*)(g_WqpcT + k0 * 128 + tid * 8 + 4);
        __syncthreads();
#pragma unroll
        for (int kk = 0; kk < 16; kk++)
            mma_step(As + kk * 128, T1 + (k0 + kk) * 132, tx, ty, acc);
        __syncthreads();
    }
#pragma unroll
    for (int i = 0; i < 8; i++) {
        int a = (i < 4 ? 0 : 64) + ty * 4 + (i & 3);
        float* grow = g_qfeatproj + b * (Aa * Tt) + a * Tt;
        *(float4*)(grow + tx * 4)      = make_float4(acc[i][0], acc[i][1], acc[i][2], acc[i][3]);
        *(float4*)(grow + 64 + tx * 4) = make_float4(acc[i][4], acc[i][5], acc[i][6], acc[i][7]);
    }

    // qfeatatt[a] = sum_m Wqfc[a][m] * qmean[m]
    if (tid < 128) {
        float s = 0.f;
        const float* w = Wqfc + tid * Mm;
#pragma unroll 8
        for (int m = 0; m < Mm; m++) s += w[m] * qm[m];
        g_qfeatatt[b * Aa + tid] = s;
    }
}

// ---------------- image branch: in_ifeat GEMM + ifeatproj GEMM + logits, fused per tile ----------------
__global__ void __launch_bounds__(256) img_kernel(const float* __restrict__ img,
                                                  const float* __restrict__ Watt)
{
    extern __shared__ float sm[];
    float* As   = sm;
    float* Bs   = sm + 2048;
    float* T1   = sm + SM_T1;
    float* red  = sm + SM_RED;
    float* qatt = sm + SM_X0;
    float* watt = sm + SM_X0 + 128;

    const int tid = threadIdx.x;
    const int tx = tid & 15, ty = tid >> 4;
    const int b  = blockIdx.y;
    const int nt = blockIdx.x;
    const int n0 = nt * 128;

    if (tid < 128) { qatt[tid] = g_qfeatatt[b * Aa + tid]; watt[tid] = Watt[tid]; }

    const float* xb = img + (size_t)b * Cc * Nn;

    float acc[8][8];
#pragma unroll
    for (int i = 0; i < 8; i++)
#pragma unroll
        for (int j = 0; j < 8; j++) acc[i][j] = 0.f;

    // GEMM1: in_ifeat tile [128m x 128n], K=256
    for (int k0 = 0; k0 < Cc; k0 += 16) {
        *(float4*)(As + tid * 8)     = *(const float4*)(g_WimgT + k0 * 128 + tid * 8);
        *(float4*)(As + tid * 8 + 4) = *(const float4*)(g_WimgT + k0 * 128 + tid * 8 + 4);
        {
            int kk = tid >> 4, nn = (tid & 15) * 8;
            const float* s = xb + (size_t)(k0 + kk) * Nn + n0 + nn;
            *(float4*)(Bs + tid * 8)     = *(const float4*)(s);
            *(float4*)(Bs + tid * 8 + 4) = *(const float4*)(s + 4);
        }
        __syncthreads();
#pragma unroll
        for (int kk = 0; kk < 16; kk++)
            mma_step(As + kk * 128, Bs + kk * 128, tx, ty, acc);
        __syncthreads();
    }

    // tanh, store to HBM + smem T1, per-row partial sums (for imean)
#pragma unroll
    for (int i = 0; i < 8; i++) {
#pragma unroll
        for (int j = 0; j < 8; j++) acc[i][j] = tanhf(acc[i][j]);
        int m = (i < 4 ? 0 : 64) + ty * 4 + (i & 3);
        float4 v0 = make_float4(acc[i][0], acc[i][1], acc[i][2], acc[i][3]);
        float4 v1 = make_float4(acc[i][4], acc[i][5], acc[i][6], acc[i][7]);
        float* grow = g_inifeat + ((size_t)(b * Mm + m)) * Nn + n0;
        *(float4*)(grow + tx * 4)      = v0;
        *(float4*)(grow + 64 + tx * 4) = v1;
        float* trow = T1 + m * 132;
        *(float4*)(trow + tx * 4)      = v0;
        *(float4*)(trow + 64 + tx * 4) = v1;
        red[m * 17 + tx] = acc[i][0] + acc[i][1] + acc[i][2] + acc[i][3]
                         + acc[i][4] + acc[i][5] + acc[i][6] + acc[i][7];
    }
    __syncthreads();
    if (tid < 128) {
        float s = 0.f;
#pragma unroll
        for (int t = 0; t < 16; t++) s += red[tid * 17 + t];
        g_ipart[(b * 32 + nt) * 128 + tid] = s;
    }
    __syncthreads();

    // GEMM2: ifeatproj tile [128a x 128n] = WipcT^T @ T1, K=128 (B operand straight from smem)
#pragma unroll
    for (int i = 0; i < 8; i++)
#pragma unroll
        for (int j = 0; j < 8; j++) acc[i][j] = 0.f;
    for (int k0 = 0; k0 < 128; k0 += 16) {
        *(float4*)(As + tid * 8)     = *(const float4*)(g_WipcT + k0 * 128 + tid * 8);
        *(float4*)(As + tid * 8 + 4) = *(const float4*)(g_WipcT + k0 * 128 + tid * 8 + 4);
        __syncthreads();
#pragma unroll
        for (int kk = 0; kk < 16; kk++)
            mma_step(As + kk * 128, T1 + (k0 + kk) * 132, tx, ty, acc);
        __syncthreads();
    }

    // logits_i[n] = sum_a watt[a] * tanh(qatt[a] + proj[a][n]), reduced over ty via smem
#pragma unroll
    for (int j = 0; j < 8; j++) {
        float p = 0.f;
#pragma unroll
        for (int i = 0; i < 8; i++) {
            int a = (i < 4 ? 0 : 64) + ty * 4 + (i & 3);
            p += watt[a] * tanhf(qatt[a] + acc[i][j]);
        }
        int n = (j < 4 ? 0 : 64) + tx * 4 + (j & 3);
        red[n * 17 + ty] = p;
    }
    __syncthreads();
    if (tid < 128) {
        float s = 0.f;
#pragma unroll
        for (int t = 0; t < 16; t++) s += red[tid * 17 + t];
        g_logits[b * Nn + n0 + tid] = s;
    }
}

// ---------------- k3: ifeatatt, text logits, softmax over 4224 ----------------
// dyn smem floats: qp[128*129] | im[128] | ia[128] | lq[128] | wa[128] | redd[256]
#define K3_QP   0
#define K3_IM   (128 * 129)
#define K3_IA   (K3_IM + 128)
#define K3_LQ   (K3_IA + 128)
#define K3_WA   (K3_LQ + 128)
#define K3_RED  (K3_WA + 128)
#define K3_FLOATS (K3_RED + 256)

__global__ void __launch_bounds__(256) k3_kernel(const float* __restrict__ Wifc,
                                                 const float* __restrict__ Watt,
                                                 float* __restrict__ out)
{
    extern __shared__ float sm[];
    float* qp   = sm + K3_QP;
    float* im   = sm + K3_IM;
    float* ia   = sm + K3_IA;
    float* lq   = sm + K3_LQ;
    float* wa   = sm + K3_WA;
    float* redd = sm + K3_RED;

    const int tid = threadIdx.x;
    const int b = blockIdx.x;

    if (tid < 128) {
        wa[tid] = Watt[tid];
        float s = 0.f;
#pragma unroll
        for (int p = 0; p < 32; p++) s += g_ipart[(b * 32 + p) * 128 + tid];
        im[tid] = s * (1.f / (float)Nn);
    }
    for (int idx = tid; idx < Aa * Tt; idx += 256) {
        int a = idx >> 7, t = idx & 127;
        qp[a * 129 + t] = g_qfeatproj[b * (Aa * Tt) + idx];
    }
    __syncthreads();

    if (tid < 128) {  // ifeatatt[a] = sum_m Wifc[a][m] * imean[m]
        float s = 0.f;
        const float* w = Wifc + tid * Mm;
#pragma unroll 8
        for (int m = 0; m < Mm; m++) s += w[m] * im[m];
        ia[tid] = s;
    }
    __syncthreads();

    if (tid < 128) {  // logits_q[t]
        float s = 0.f;
#pragma unroll 8
        for (int a = 0; a < Aa; a++) s += wa[a] * tanhf(ia[a] + qp[a * 129 + tid]);
        lq[tid] = s;
    }
    __syncthreads();

    // softmax over [g_logits[b][0..4095], lq[0..127]]
    float mx = -1e30f;
    for (int j = tid; j < Nn; j += 256) mx = fmaxf(mx, g_logits[b * Nn + j]);
    if (tid < 128) mx = fmaxf(mx, lq[tid]);
    redd[tid] = mx;
    __syncthreads();
    for (int s = 128; s > 0; s >>= 1) {
        if (tid < s) redd[tid] = fmaxf(redd[tid], redd[tid + s]);
        __syncthreads();
    }
    mx = redd[0];
    __syncthreads();

    float* att = out + Bn * Mm + b * NTOT;
    float sum = 0.f;
    for (int j = tid; j < Nn; j += 256) {
        float e = expf(g_logits[b * Nn + j] - mx);
        att[j] = e;
        sum += e;
    }
    if (tid < 128) {
        float e = expf(lq[tid] - mx);
        att[Nn + tid] = e;
        sum += e;
    }
    redd[tid] = sum;
    __syncthreads();
    for (int s = 128; s > 0; s >>= 1) {
        if (tid < s) redd[tid] += redd[tid + s];
        __syncthreads();
    }
    float inv = 1.f / redd[0];
    for (int j = tid; j < NTOT; j += 256) att[j] *= inv;
}

// ---------------- k4: att_feat[b][m] = sum_n joint[b][m][n] * att[b][n] ----------------
__global__ void __launch_bounds__(512) k4_kernel(float* __restrict__ out)
{
    __shared__ float att_s[NTOT];
    const int b = blockIdx.y, mq = blockIdx.x;
    const int tid = threadIdx.x;
    const float* att = out + Bn * Mm + b * NTOT;
    for (int j = tid; j < NTOT; j += 512) att_s[j] = att[j];
    __syncthreads();

    const int warp = tid >> 5, lane = tid & 31;
    for (int m = mq * 32 + warp; m < mq * 32 + 32; m += 16) {
        const float* row = g_inifeat + ((size_t)(b * Mm + m)) * Nn;
        float s = 0.f;
        for (int j = lane; j < Nn; j += 32) s += row[j] * att_s[j];
        const float* qrow = g_inqfeat + b * (Mm * Tt) + m * Tt;
        for (int j = lane; j < Tt; j += 32) s += qrow[j] * att_s[Nn + j];
#pragma unroll
        for (int o = 16; o; o >>= 1) s += __shfl_down_sync(0xffffffffu, s, o);
        if (lane == 0) out[b * Mm + m] = s;
    }
}

// ---------------- launch ----------------
extern "C" void kernel_launch(void* const* d_in, const int* in_sizes, int n_in,
                              void* d_out, int out_size)
{
    (void)in_sizes; (void)n_in; (void)out_size;
    const float* img  = (const float*)d_in[0];
    const float* text = (const float*)d_in[1];
    const float* Wimg = (const float*)d_in[2];
    const float* Wtxt = (const float*)d_in[3];
    const float* Wqfc = (const float*)d_in[4];
    const float* Wifc = (const float*)d_in[5];
    const float* Wipc = (const float*)d_in[6];
    const float* Wqpc = (const float*)d_in[7];
    const float* Watt = (const float*)d_in[8];
    float* out = (float*)d_out;

    const int smem_big = SMEM_FLOATS * (int)sizeof(float);      // ~94 KB
    const int smem_k3  = K3_FLOATS * (int)sizeof(float);        // ~69 KB
    cudaFuncSetAttribute(text_kernel, cudaFuncAttributeMaxDynamicSharedMemorySize, smem_big);
    cudaFuncSetAttribute(img_kernel,  cudaFuncAttributeMaxDynamicSharedMemorySize, smem_big);
    cudaFuncSetAttribute(k3_kernel,   cudaFuncAttributeMaxDynamicSharedMemorySize, smem_k3);

    prep_kernel<<<256, 256>>>(Wimg, Wtxt, Wipc, Wqpc);
    text_kernel<<<Bn, 256, smem_big>>>(text, Wqfc);
    img_kernel<<<dim3(32, Bn), 256, smem_big>>>(img, Watt);
    k3_kernel<<<Bn, 256, smem_k3>>>(Wifc, Watt, out);
    k4_kernel<<<dim3(4, Bn), 512>>>(out);
}

// round 2
// speedup vs baseline: 1.4464x; 1.4464x over previous
#include <cuda_runtime.h>
#include <math.h>

// Problem constants
#define Bn   64
#define Cc   256
#define Nn   4096
#define HIDn 512
#define Tt   128
#define Mm   128
#define Aa   128
#define NTOT 4224   // Nn + Tt

// -------- device scratch (allocation-free: __device__ globals) --------
__device__ float g_WtxtT[HIDn * Mm];      // [512][128] (text GEMM1, fp32)
__device__ float g_WqpcT[Mm * Aa];        // [128][128] (text GEMM2, fp32)
__device__ float g_Wimg32[Mm * Cc];       // W_img tf32-rounded, [m][k] row-major
__device__ float g_Wipc32[Aa * Mm];       // W_ipc tf32-rounded, [a][m] row-major
__device__ float g_inqfeat[Bn * Mm * Tt];     // 4 MB
__device__ float g_qfeatproj[Bn * Aa * Tt];   // 4 MB
__device__ float g_qfeatatt[Bn * Aa];
__device__ float g_inifeat[33554432];         // [64][128][4096] = 128 MB fp32
__device__ float g_ipart[Bn * 32 * Mm];       // per-tile row-sum partials
__device__ float g_logits[Bn * Nn];

__device__ __forceinline__ float tf32_rna(float x) {
    unsigned r;
    asm("cvt.rna.tf32.f32 %0, %1;" : "=r"(r) : "f"(x));
    return __uint_as_float(r);
}

__device__ __forceinline__ void mma_tf32(float d[4], const unsigned a[4], const unsigned b[2]) {
    asm volatile("mma.sync.aligned.m16n8k8.row.col.f32.tf32.tf32.f32 "
                 "{%0,%1,%2,%3}, {%4,%5,%6,%7}, {%8,%9}, {%0,%1,%2,%3};"
                 : "+f"(d[0]), "+f"(d[1]), "+f"(d[2]), "+f"(d[3])
                 : "r"(a[0]), "r"(a[1]), "r"(a[2]), "r"(a[3]), "r"(b[0]), "r"(b[1]));
}

// ---------------- prep: weight transposes + tf32 rounding ----------------
__global__ void prep_kernel(const float* __restrict__ Wimg, const float* __restrict__ Wtxt,
                            const float* __restrict__ Wipc, const float* __restrict__ Wqpc)
{
    int i = blockIdx.x * blockDim.x + threadIdx.x;
    if (i < Mm * Cc)   g_Wimg32[i] = tf32_rna(Wimg[i]);
    if (i < Mm * HIDn) { int m = i / HIDn, k = i % HIDn; g_WtxtT[k * Mm + m] = Wtxt[i]; }
    if (i < Aa * Mm)   { int a = i / Mm,   k = i % Mm;
                         g_Wipc32[i] = tf32_rna(Wipc[i]);
                         g_WqpcT[k * Aa + a] = Wqpc[i]; }
}

// ================= fp32 micro-kernel (text branch only) =================
__device__ __forceinline__ void mma_step(const float* __restrict__ Arow,
                                         const float* __restrict__ Brow,
                                         int tx, int ty, float acc[8][8])
{
    float a[8], bb[8];
    *(float4*)&a[0]  = *(const float4*)(Arow + ty * 4);
    *(float4*)&a[4]  = *(const float4*)(Arow + 64 + ty * 4);
    *(float4*)&bb[0] = *(const float4*)(Brow + tx * 4);
    *(float4*)&bb[4] = *(const float4*)(Brow + 64 + tx * 4);
#pragma unroll
    for (int i = 0; i < 8; i++)
#pragma unroll
        for (int j = 0; j < 8; j++)
            acc[i][j] = fmaf(a[i], bb[j], acc[i][j]);
}

// text smem layout (floats): As[2048] | Bs[2048] | T1[128*132] | red[128*17] | extras[256]
#define SM_T1   4096
#define SM_RED  (4096 + 128 * 132)
#define SM_X0   (SM_RED + 128 * 17)
#define SMEM_FLOATS (SM_X0 + 256)

__global__ void __launch_bounds__(256) text_kernel(const float* __restrict__ text,
                                                   const float* __restrict__ Wqfc)
{
    extern __shared__ float sm[];
    float* As  = sm;
    float* Bs  = sm + 2048;
    float* T1  = sm + SM_T1;
    float* red = sm + SM_RED;
    float* qm  = sm + SM_X0;

    const int tid = threadIdx.x;
    const int tx = tid & 15, ty = tid >> 4;
    const int b = blockIdx.x;
    const float* tb = text + (size_t)b * HIDn * Tt;

    float acc[8][8];
#pragma unroll
    for (int i = 0; i < 8; i++)
#pragma unroll
        for (int j = 0; j < 8; j++) acc[i][j] = 0.f;

    for (int k0 = 0; k0 < HIDn; k0 += 16) {
        *(float4*)(As + tid * 8)     = *(const float4*)(g_WtxtT + k0 * 128 + tid * 8);
        *(float4*)(As + tid * 8 + 4) = *(const float4*)(g_WtxtT + k0 * 128 + tid * 8 + 4);
        *(float4*)(Bs + tid * 8)     = *(const float4*)(tb + k0 * 128 + tid * 8);
        *(float4*)(Bs + tid * 8 + 4) = *(const float4*)(tb + k0 * 128 + tid * 8 + 4);
        __syncthreads();
#pragma unroll
        for (int kk = 0; kk < 16; kk++)
            mma_step(As + kk * 128, Bs + kk * 128, tx, ty, acc);
        __syncthreads();
    }

#pragma unroll
    for (int i = 0; i < 8; i++) {
#pragma unroll
        for (int j = 0; j < 8; j++) acc[i][j] = tanhf(acc[i][j]);
        int m = (i < 4 ? 0 : 64) + ty * 4 + (i & 3);
        float4 v0 = make_float4(acc[i][0], acc[i][1], acc[i][2], acc[i][3]);
        float4 v1 = make_float4(acc[i][4], acc[i][5], acc[i][6], acc[i][7]);
        float* grow = g_inqfeat + b * (Mm * Tt) + m * Tt;
        *(float4*)(grow + tx * 4)      = v0;
        *(float4*)(grow + 64 + tx * 4) = v1;
        float* trow = T1 + m * 132;
        *(float4*)(trow + tx * 4)      = v0;
        *(float4*)(trow + 64 + tx * 4) = v1;
        red[m * 17 + tx] = acc[i][0] + acc[i][1] + acc[i][2] + acc[i][3]
                         + acc[i][4] + acc[i][5] + acc[i][6] + acc[i][7];
    }
    __syncthreads();
    if (tid < 128) {
        float s = 0.f;
#pragma unroll
        for (int t = 0; t < 16; t++) s += red[tid * 17 + t];
        qm[tid] = s * (1.f / (float)Tt);
    }
    __syncthreads();

#pragma unroll
    for (int i = 0; i < 8; i++)
#pragma unroll
        for (int j = 0; j < 8; j++) acc[i][j] = 0.f;
    for (int k0 = 0; k0 < 128; k0 += 16) {
        *(float4*)(As + tid * 8)     = *(const float4*)(g_WqpcT + k0 * 128 + tid * 8);
        *(float4*)(As + tid * 8 + 4) = *(const float4*)(g_WqpcT + k0 * 128 + tid * 8 + 4);
        __syncthreads();
#pragma unroll
        for (int kk = 0; kk < 16; kk++)
            mma_step(As + kk * 128, T1 + (k0 + kk) * 132, tx, ty, acc);
        __syncthreads();
    }
#pragma unroll
    for (int i = 0; i < 8; i++) {
        int a = (i < 4 ? 0 : 64) + ty * 4 + (i & 3);
        float* grow = g_qfeatproj + b * (Aa * Tt) + a * Tt;
        *(float4*)(grow + tx * 4)      = make_float4(acc[i][0], acc[i][1], acc[i][2], acc[i][3]);
        *(float4*)(grow + 64 + tx * 4) = make_float4(acc[i][4], acc[i][5], acc[i][6], acc[i][7]);
    }

    if (tid < 128) {
        float s = 0.f;
        const float* w = Wqfc + tid * Mm;
#pragma unroll 8
        for (int m = 0; m < Mm; m++) s += w[m] * qm[m];
        g_qfeatatt[b * Aa + tid] = s;
    }
}

// ================= image branch: tf32 tensor-core fused kernel =================
// smem float offsets
#define IA_S  0                   // 2 x [128][20]
#define IB_S  5120                // 2 x [16][136]
#define IT1   9472                // [128][136]
#define IA2   26880               // [128][132]
#define IRED  43776               // 640 floats (red / red2)
#define IQATT 44416               // 128
#define IWATT 44544               // 128
#define IMG_FLOATS 44672

__global__ void __launch_bounds__(256) img_kernel(const float* __restrict__ img,
                                                  const float* __restrict__ Watt)
{
    extern __shared__ float sm[];
    float* red  = sm + IRED;
    float* qatt = sm + IQATT;
    float* watt = sm + IWATT;

    const int tid  = threadIdx.x;
    const int lane = tid & 31;
    const int w    = tid >> 5;
    const int g    = lane >> 2;       // groupID 0..7
    const int tig  = lane & 3;        // thread in group
    const int wm   = w >> 2;          // 0..1
    const int wn   = w & 3;           // 0..3
    const int mb   = wm * 64;
    const int nb   = wn * 32;
    const int b    = blockIdx.y;
    const int nt   = blockIdx.x;
    const int n0   = nt * 128;

    if (tid < 128) { qatt[tid] = g_qfeatatt[b * Aa + tid]; watt[tid] = Watt[tid]; }

    const float* xb = img + (size_t)b * Cc * Nn;

    float acc[4][4][4];
#pragma unroll
    for (int i = 0; i < 4; i++)
#pragma unroll
        for (int j = 0; j < 4; j++)
#pragma unroll
            for (int q = 0; q < 4; q++) acc[i][j][q] = 0.f;

    // ---- GEMM1: in_ifeat tile = W_img[128x256] @ x[256 x 128n], tf32 ----
    const int am = tid >> 1, akk = (tid & 1) * 8;            // A slice load coords
    const int bkk = tid >> 4, bnn = (tid & 15) * 8;          // B slice load coords

    float ar[8], br[8];
    // preload slice 0
    {
        const float* ap = g_Wimg32 + am * Cc + akk;
        *(float4*)&ar[0] = *(const float4*)(ap);
        *(float4*)&ar[4] = *(const float4*)(ap + 4);
        const float* bp = xb + (size_t)bkk * Nn + n0 + bnn;
        *(float4*)&br[0] = *(const float4*)(bp);
        *(float4*)&br[4] = *(const float4*)(bp + 4);
    }

    for (int ks = 0; ks < 16; ks++) {
        float* As = sm + IA_S + (ks & 1) * 2560;
        float* Bs = sm + IB_S + (ks & 1) * 2176;
        // store slice (B gets tf32 rounding here; A pre-rounded)
        *(float4*)(As + am * 20 + akk)     = *(const float4*)&ar[0];
        *(float4*)(As + am * 20 + akk + 4) = *(const float4*)&ar[4];
        {
            float t[8];
#pragma unroll
            for (int q = 0; q < 8; q++) t[q] = tf32_rna(br[q]);
            *(float4*)(Bs + bkk * 136 + bnn)     = *(const float4*)&t[0];
            *(float4*)(Bs + bkk * 136 + bnn + 4) = *(const float4*)&t[4];
        }
        __syncthreads();
        if (ks < 15) {
            int k0 = (ks + 1) * 16;
            const float* ap = g_Wimg32 + am * Cc + k0 + akk;
            *(float4*)&ar[0] = *(const float4*)(ap);
            *(float4*)&ar[4] = *(const float4*)(ap + 4);
            const float* bp = xb + (size_t)(k0 + bkk) * Nn + n0 + bnn;
            *(float4*)&br[0] = *(const float4*)(bp);
            *(float4*)&br[4] = *(const float4*)(bp + 4);
        }
#pragma unroll
        for (int kh = 0; kh < 16; kh += 8) {
            unsigned af[4][4], bf[4][2];
#pragma unroll
            for (int mf = 0; mf < 4; mf++) {
                const float* base = As + (mb + mf * 16 + g) * 20 + kh + tig;
                af[mf][0] = __float_as_uint(base[0]);
                af[mf][1] = __float_as_uint(base[8 * 20]);
                af[mf][2] = __float_as_uint(base[4]);
                af[mf][3] = __float_as_uint(base[8 * 20 + 4]);
            }
#pragma unroll
            for (int nf = 0; nf < 4; nf++) {
                const float* base = Bs + (kh + tig) * 136 + nb + nf * 8 + g;
                bf[nf][0] = __float_as_uint(base[0]);
                bf[nf][1] = __float_as_uint(base[4 * 136]);
            }
#pragma unroll
            for (int mf = 0; mf < 4; mf++)
#pragma unroll
                for (int nf = 0; nf < 4; nf++)
                    mma_tf32(acc[mf][nf], af[mf], bf[nf]);
        }
        __syncthreads();
    }

    // ---- tanh, store to HBM fp32 + smem T1 (tf32-rounded), row partials ----
    float* T1 = sm + IT1;
    float rp[8];
#pragma unroll
    for (int q = 0; q < 8; q++) rp[q] = 0.f;

#pragma unroll
    for (int mf = 0; mf < 4; mf++) {
        int m0 = mb + mf * 16 + g;
#pragma unroll
        for (int nf = 0; nf < 4; nf++) {
            int nl = nb + nf * 8 + tig * 2;
            float v00 = tanhf(acc[mf][nf][0]);
            float v01 = tanhf(acc[mf][nf][1]);
            float v10 = tanhf(acc[mf][nf][2]);
            float v11 = tanhf(acc[mf][nf][3]);
            float* gr0 = g_inifeat + ((size_t)(b * Mm + m0)) * Nn + n0 + nl;
            float* gr1 = g_inifeat + ((size_t)(b * Mm + m0 + 8)) * Nn + n0 + nl;
            *(float2*)gr0 = make_float2(v00, v01);
            *(float2*)gr1 = make_float2(v10, v11);
            *(float2*)(T1 + m0 * 136 + nl)       = make_float2(tf32_rna(v00), tf32_rna(v01));
            *(float2*)(T1 + (m0 + 8) * 136 + nl) = make_float2(tf32_rna(v10), tf32_rna(v11));
            rp[mf * 2]     += v00 + v01;
            rp[mf * 2 + 1] += v10 + v11;
        }
    }
    // reduce row partials over tig (lane bits 0,1)
#pragma unroll
    for (int q = 0; q < 8; q++) {
        rp[q] += __shfl_xor_sync(0xffffffffu, rp[q], 1);
        rp[q] += __shfl_xor_sync(0xffffffffu, rp[q], 2);
    }
    if (tig == 0) {
#pragma unroll
        for (int mf = 0; mf < 4; mf++) {
            red[(mb + mf * 16 + g) * 5 + wn]     = rp[mf * 2];
            red[(mb + mf * 16 + g + 8) * 5 + wn] = rp[mf * 2 + 1];
        }
    }
    __syncthreads();
    if (tid < 128) {
        float s = red[tid * 5] + red[tid * 5 + 1] + red[tid * 5 + 2] + red[tid * 5 + 3];
        g_ipart[(b * 32 + nt) * 128 + tid] = s;
    }
    // load A2 = W_ipc tf32 (whole) while ipart finishes
    {
        float* A2 = sm + IA2;
        int a = tid >> 1, h = (tid & 1) * 64;
        const float* src = g_Wipc32 + a * 128 + h;
        float* dst = A2 + a * 132 + h;
#pragma unroll
        for (int j = 0; j < 64; j += 4)
            *(float4*)(dst + j) = *(const float4*)(src + j);
    }
    __syncthreads();

    // ---- GEMM2: proj tile = W_ipc[128x128] @ T1[128 x 128n], tf32 ----
#pragma unroll
    for (int i = 0; i < 4; i++)
#pragma unroll
        for (int j = 0; j < 4; j++)
#pragma unroll
            for (int q = 0; q < 4; q++) acc[i][j][q] = 0.f;

    const float* A2 = sm + IA2;
    for (int k0 = 0; k0 < 128; k0 += 16) {
#pragma unroll
        for (int kh = 0; kh < 16; kh += 8) {
            int k = k0 + kh;
            unsigned af[4][4], bf[4][2];
#pragma unroll
            for (int mf = 0; mf < 4; mf++) {
                const float* base = A2 + (mb + mf * 16 + g) * 132 + k + tig;
                af[mf][0] = __float_as_uint(base[0]);
                af[mf][1] = __float_as_uint(base[8 * 132]);
                af[mf][2] = __float_as_uint(base[4]);
                af[mf][3] = __float_as_uint(base[8 * 132 + 4]);
            }
#pragma unroll
            for (int nf = 0; nf < 4; nf++) {
                const float* base = T1 + (k + tig) * 136 + nb + nf * 8 + g;
                bf[nf][0] = __float_as_uint(base[0]);
                bf[nf][1] = __float_as_uint(base[4 * 136]);
            }
#pragma unroll
            for (int mf = 0; mf < 4; mf++)
#pragma unroll
                for (int nf = 0; nf < 4; nf++)
                    mma_tf32(acc[mf][nf], af[mf], bf[nf]);
        }
    }

    // ---- logits: sum_a watt[a]*tanh(qatt[a]+proj[a][n]) ----
    float p[4][2];
#pragma unroll
    for (int nf = 0; nf < 4; nf++) { p[nf][0] = 0.f; p[nf][1] = 0.f; }
#pragma unroll
    for (int mf = 0; mf < 4; mf++) {
        int a0 = mb + mf * 16 + g, a1 = a0 + 8;
        float w0 = watt[a0], q0 = qatt[a0];
        float w1 = watt[a1], q1 = qatt[a1];
#pragma unroll
        for (int nf = 0; nf < 4; nf++) {
            p[nf][0] += w0 * tanhf(q0 + acc[mf][nf][0]) + w1 * tanhf(q1 + acc[mf][nf][2]);
            p[nf][1] += w0 * tanhf(q0 + acc[mf][nf][1]) + w1 * tanhf(q1 + acc[mf][nf][3]);
        }
    }
    // reduce over g (lane bits 2,3,4)
#pragma unroll
    for (int nf = 0; nf < 4; nf++)
#pragma unroll
        for (int q = 0; q < 2; q++) {
            p[nf][q] += __shfl_xor_sync(0xffffffffu, p[nf][q], 4);
            p[nf][q] += __shfl_xor_sync(0xffffffffu, p[nf][q], 8);
            p[nf][q] += __shfl_xor_sync(0xffffffffu, p[nf][q], 16);
        }
    if (g == 0) {
#pragma unroll
        for (int nf = 0; nf < 4; nf++) {
            int n = nb + nf * 8 + tig * 2;
            red[n * 2 + wm]       = p[nf][0];
            red[(n + 1) * 2 + wm] = p[nf][1];
        }
    }
    __syncthreads();
    if (tid < 128)
        g_logits[b * Nn + n0 + tid] = red[tid * 2] + red[tid * 2 + 1];
}

// ---------------- k3: ifeatatt, text logits, softmax (1024 threads) ----------------
__global__ void __launch_bounds__(1024) k3_kernel(const float* __restrict__ Wifc,
                                                  const float* __restrict__ Watt,
                                                  float* __restrict__ out)
{
    __shared__ float red[1024];
    __shared__ float im[128], ia[128], lq[128], wa[128];
    __shared__ float r2[32];

    const int tid = threadIdx.x;
    const int b = blockIdx.x;
    const int m = tid & 127, c = tid >> 7;   // c 0..7

    // imean partials
    {
        float s = 0.f;
#pragma unroll
        for (int j = c * 4; j < c * 4 + 4; j++) s += g_ipart[(b * 32 + j) * 128 + m];
        red[tid] = s;
    }
    if (tid < 128) wa[tid] = Watt[tid];
    __syncthreads();
    if (tid < 128) {
        float t = 0.f;
#pragma unroll
        for (int cc = 0; cc < 8; cc++) t += red[cc * 128 + tid];
        im[tid] = t * (1.f / (float)Nn);
    }
    __syncthreads();

    // ifeatatt[a] = sum_m Wifc[a][m]*im[m]  (a=m index, chunk c of 16 m's)
    {
        float t = 0.f;
        const float* wp = Wifc + m * Mm + c * 16;
#pragma unroll
        for (int j = 0; j < 16; j++) t += wp[j] * im[c * 16 + j];
        red[tid] = t;
    }
    __syncthreads();
    if (tid < 128) {
        float t = 0.f;
#pragma unroll
        for (int cc = 0; cc < 8; cc++) t += red[cc * 128 + tid];
        ia[tid] = t;
    }
    __syncthreads();

    // logits_q[t] = sum_a wa[a]*tanh(ia[a]+qproj[a][t])
    {
        float t = 0.f;
        const float* qp = g_qfeatproj + b * (Aa * Tt) + (c * 16) * Tt + m;
#pragma unroll
        for (int j = 0; j < 16; j++)
            t += wa[c * 16 + j] * tanhf(ia[c * 16 + j] + qp[j * Tt]);
        red[tid] = t;
    }
    __syncthreads();
    if (tid < 128) {
        float t = 0.f;
#pragma unroll
        for (int cc = 0; cc < 8; cc++) t += red[cc * 128 + tid];
        lq[tid] = t;
    }
    __syncthreads();

    // softmax over [g_logits[b][0..4095], lq[0..127]]
    float mx = -1e30f;
    for (int j = tid; j < NTOT; j += 1024) {
        float v = (j < Nn) ? g_logits[b * Nn + j] : lq[j - Nn];
        mx = fmaxf(mx, v);
    }
#pragma unroll
    for (int o = 16; o; o >>= 1) mx = fmaxf(mx, __shfl_xor_sync(0xffffffffu, mx, o));
    if ((tid & 31) == 0) r2[tid >> 5] = mx;
    __syncthreads();
    if (tid < 32) {
        float v = r2[tid];
#pragma unroll
        for (int o = 16; o; o >>= 1) v = fmaxf(v, __shfl_xor_sync(0xffffffffu, v, o));
        r2[tid] = v;
    }
    __syncthreads();
    mx = r2[0];
    __syncthreads();

    float* att = out + Bn * Mm + b * NTOT;
    float sum = 0.f;
    for (int j = tid; j < NTOT; j += 1024) {
        float v = (j < Nn) ? g_logits[b * Nn + j] : lq[j - Nn];
        float e = expf(v - mx);
        att[j] = e;
        sum += e;
    }
#pragma unroll
    for (int o = 16; o; o >>= 1) sum += __shfl_xor_sync(0xffffffffu, sum, o);
    if ((tid & 31) == 0) r2[tid >> 5] = sum;
    __syncthreads();
    if (tid < 32) {
        float v = r2[tid];
#pragma unroll
        for (int o = 16; o; o >>= 1) v += __shfl_xor_sync(0xffffffffu, v, o);
        r2[tid] = v;
    }
    __syncthreads();
    float inv = 1.f / r2[0];
    for (int j = tid; j < NTOT; j += 1024) att[j] *= inv;
}

// ---------------- k4: att_feat[b][m] = sum_n joint[b][m][n] * att[b][n] ----------------
__global__ void __launch_bounds__(512) k4_kernel(float* __restrict__ out)
{
    __shared__ float att_s[NTOT];
    const int b = blockIdx.y, mq = blockIdx.x;
    const int tid = threadIdx.x;
    const float* att = out + Bn * Mm + b * NTOT;
    for (int j = tid; j < NTOT; j += 512) att_s[j] = att[j];
    __syncthreads();

    const int warp = tid >> 5, lane = tid & 31;
    for (int m = mq * 32 + warp; m < mq * 32 + 32; m += 16) {
        const float* row = g_inifeat + ((size_t)(b * Mm + m)) * Nn;
        float s = 0.f;
        for (int j = lane; j < Nn; j += 32) s += row[j] * att_s[j];
        const float* qrow = g_inqfeat + b * (Mm * Tt) + m * Tt;
        for (int j = lane; j < Tt; j += 32) s += qrow[j] * att_s[Nn + j];
#pragma unroll
        for (int o = 16; o; o >>= 1) s += __shfl_down_sync(0xffffffffu, s, o);
        if (lane == 0) out[b * Mm + m] = s;
    }
}

// ---------------- launch ----------------
extern "C" void kernel_launch(void* const* d_in, const int* in_sizes, int n_in,
                              void* d_out, int out_size)
{
    (void)in_sizes; (void)n_in; (void)out_size;
    const float* img  = (const float*)d_in[0];
    const float* text = (const float*)d_in[1];
    const float* Wimg = (const float*)d_in[2];
    const float* Wtxt = (const float*)d_in[3];
    const float* Wqfc = (const float*)d_in[4];
    const float* Wifc = (const float*)d_in[5];
    const float* Wipc = (const float*)d_in[6];
    const float* Wqpc = (const float*)d_in[7];
    const float* Watt = (const float*)d_in[8];
    float* out = (float*)d_out;

    const int smem_text = SMEM_FLOATS * (int)sizeof(float);    // ~94 KB
    const int smem_img  = IMG_FLOATS * (int)sizeof(float);     // ~175 KB
    cudaFuncSetAttribute(text_kernel, cudaFuncAttributeMaxDynamicSharedMemorySize, smem_text);
    cudaFuncSetAttribute(img_kernel,  cudaFuncAttributeMaxDynamicSharedMemorySize, smem_img);

    prep_kernel<<<256, 256>>>(Wimg, Wtxt, Wipc, Wqpc);
    text_kernel<<<Bn, 256, smem_text>>>(text, Wqfc);
    img_kernel<<<dim3(32, Bn), 256, smem_img>>>(img, Watt);
    k3_kernel<<<Bn, 1024>>>(Wifc, Watt, out);
    k4_kernel<<<dim3(4, Bn), 512>>>(out);
}

// round 3
// speedup vs baseline: 1.9468x; 1.3459x over previous
#include <cuda_runtime.h>
#include <math.h>

// Problem constants
#define Bn   64
#define Cc   256
#define Nn   4096
#define HIDn 512
#define Tt   128
#define Mm   128
#define Aa   128
#define NTOT 4224   // Nn + Tt

// -------- device scratch (allocation-free: __device__ globals) --------
__device__ float g_WimgP[Mm * Cc];        // permuted tf32 A for img GEMM1 (32768)
__device__ float g_WtxtP[Mm * HIDn];      // permuted tf32 A for text GEMM1 (65536)
__device__ float g_WipcP[Aa * Mm];        // permuted tf32 A for img GEMM2 (16384)
__device__ float g_WqpcP[Aa * Mm];        // permuted tf32 A for text GEMM2 (16384)
__device__ float g_inqfeat[Bn * Mm * Tt];     // 4 MB
__device__ float g_qfeatproj[Bn * Aa * Tt];   // 4 MB
__device__ float g_qfeatatt[Bn * Aa];
__device__ float g_inifeat[33554432];         // [64][128][4096] = 128 MB fp32
__device__ float g_ipart[Bn * 32 * Mm];       // per-tile row-sum partials
__device__ float g_logits[Bn * Nn];

__device__ __forceinline__ float tf32_rna(float x) {
    unsigned r;
    asm("cvt.rna.tf32.f32 %0, %1;" : "=r"(r) : "f"(x));
    return __uint_as_float(r);
}

__device__ __forceinline__ void mma_tf32(float d[4], const unsigned* a, const unsigned* b) {
    asm volatile("mma.sync.aligned.m16n8k8.row.col.f32.tf32.tf32.f32 "
                 "{%0,%1,%2,%3}, {%4,%5,%6,%7}, {%8,%9}, {%0,%1,%2,%3};"
                 : "+f"(d[0]), "+f"(d[1]), "+f"(d[2]), "+f"(d[3])
                 : "r"(a[0]), "r"(a[1]), "r"(a[2]), "r"(a[3]), "r"(b[0]), "r"(b[1]));
}

// Permuted A index: element (m,k) -> fragment-contiguous layout.
// slice s=k>>4 (2048 floats each); within slice, a thread's 4 A-regs for
// (m16-block mi, kh) are one aligned float4.
__device__ __forceinline__ int perm_idx(int m, int k) {
    int s = k >> 4, kk = k & 15;
    int kh = kk >> 3, kl = kk & 7, tg = kl & 3, khalf = kl >> 2;
    int mi = m >> 4, rl = m & 15, gg = rl & 7, h = rl >> 3;
    return s * 2048 + ((mi * 2 + kh) * 32 + gg * 4 + tg) * 4 + khalf * 2 + h;
}

// ---------------- prep: build permuted tf32 weight arrays ----------------
__global__ void prep_kernel(const float* __restrict__ Wimg, const float* __restrict__ Wtxt,
                            const float* __restrict__ Wipc, const float* __restrict__ Wqpc)
{
    int i = blockIdx.x * blockDim.x + threadIdx.x;   // 0..65535
    { int m = i >> 9, k = i & 511; g_WtxtP[perm_idx(m, k)] = tf32_rna(Wtxt[i]); }
    if (i < Mm * Cc) { int m = i >> 8, k = i & 255; g_WimgP[perm_idx(m, k)] = tf32_rna(Wimg[i]); }
    if (i < Aa * Mm) {
        int m = i >> 7, k = i & 127;
        g_WipcP[perm_idx(m, k)] = tf32_rna(Wipc[i]);
        g_WqpcP[perm_idx(m, k)] = tf32_rna(Wqpc[i]);
    }
}

// ---------------- fused dual-GEMM kernel (text MODE=0, img MODE=1) ----------------
// smem float offsets
#define S_APR 0        // 2 x 2048
#define S_BPR 4096     // 2 x 2112  (32 groups x 66)
#define S_T1  8320     // 256 groups x 66 = 16896
#define S_RED 25216    // 640
#define S_Q   25856    // 128 (qatt for img / qmean for text)
#define S_W   25984    // 128 (watt for img)
#define S_TOT 26112    // 104448 bytes

template<int K1, int LDB, int MODE>
__global__ void __launch_bounds__(256, 2) fused_kernel(
    const float* __restrict__ Bsrc,   // img_feat or text_feat
    const float* __restrict__ Wx,     // Watt (img) / Wqfc (text)
    float* __restrict__ out1)         // g_inifeat / g_inqfeat
{
    extern __shared__ float sm[];
    float* redm = sm + S_RED;
    float* qbuf = sm + S_Q;
    float* wbuf = sm + S_W;

    const int tid  = threadIdx.x;
    const int lane = tid & 31;
    const int w    = tid >> 5;
    const int g    = lane >> 2;
    const int tig  = lane & 3;
    const int wm   = w >> 2;          // 0..1
    const int wn   = w & 3;           // 0..3
    const int mb   = wm * 64;
    const int nb   = wn * 32;

    const int b  = (MODE == 1) ? blockIdx.y : blockIdx.x;
    const int nt = (MODE == 1) ? blockIdx.x : 0;
    const int n0 = nt * 128;

    const float* A1P = (MODE == 1) ? g_WimgP : g_WtxtP;
    const float* A2P = (MODE == 1) ? g_WipcP : g_WqpcP;
    const float* Bb0 = Bsrc + (size_t)b * K1 * LDB + n0;

    if (MODE == 1 && tid < 128) {
        qbuf[tid] = g_qfeatatt[b * Aa + tid];
        wbuf[tid] = Wx[tid];
    }

    // B producer coords
    const int bkk = tid >> 4;                 // 0..15 (k within slice)
    const int bnn = (tid & 15) * 8;           // n offset
    const int bnj = tid & 15;
    const int bkh = bkk >> 3, bkl = bkk & 7;
    const int baddr = ((bkh * 16 + bnj) * 66) + (bkl & 3) * 16 + (bkl >> 2);

    float acc[4][4][4];
#pragma unroll
    for (int i = 0; i < 4; i++)
#pragma unroll
        for (int j = 0; j < 4; j++)
#pragma unroll
            for (int q = 0; q < 4; q++) acc[i][j][q] = 0.f;

    // ================= GEMM1 =================
    const int NS1 = K1 / 16;
    float4 ar0, ar1;
    float br[8];
    // prefetch slice 0
    ar0 = *(const float4*)(A1P + tid * 4);
    ar1 = *(const float4*)(A1P + 1024 + tid * 4);
    {
        const float* bp = Bb0 + (size_t)bkk * LDB + bnn;
        *(float4*)&br[0] = *(const float4*)(bp);
        *(float4*)&br[4] = *(const float4*)(bp + 4);
    }

    for (int s = 0; s < NS1; s++) {
        float* Ab = sm + S_APR + (s & 1) * 2048;
        float* Bb = sm + S_BPR + (s & 1) * 2112;
        *(float4*)(Ab + tid * 4)        = ar0;
        *(float4*)(Ab + 1024 + tid * 4) = ar1;
#pragma unroll
        for (int j = 0; j < 8; j++) Bb[baddr + 2 * j] = tf32_rna(br[j]);
        __syncthreads();
        if (s + 1 < NS1) {
            ar0 = *(const float4*)(A1P + (s + 1) * 2048 + tid * 4);
            ar1 = *(const float4*)(A1P + (s + 1) * 2048 + 1024 + tid * 4);
            const float* bp = Bb0 + (size_t)((s + 1) * 16 + bkk) * LDB + bnn;
            *(float4*)&br[0] = *(const float4*)(bp);
            *(float4*)&br[4] = *(const float4*)(bp + 4);
        }
#pragma unroll
        for (int kh = 0; kh < 2; kh++) {
            uint4 af[4]; uint2 bf[4];
#pragma unroll
            for (int mf = 0; mf < 4; mf++) {
                int mi = wm * 4 + mf;
                af[mf] = *(const uint4*)(Ab + ((mi * 2 + kh) * 32 + lane) * 4);
            }
#pragma unroll
            for (int nf = 0; nf < 4; nf++)
                bf[nf] = *(const uint2*)(Bb + (kh * 16 + wn * 4 + nf) * 66 + (tig * 8 + g) * 2);
#pragma unroll
            for (int mf = 0; mf < 4; mf++)
#pragma unroll
                for (int nf = 0; nf < 4; nf++)
                    mma_tf32(acc[mf][nf], (const unsigned*)&af[mf], (const unsigned*)&bf[nf]);
        }
        __syncthreads();
    }

    // ============ mid-epilogue: tanh, store out1 + T1(permuted tf32), row sums ============
    float* T1 = sm + S_T1;
    float rp[8];
#pragma unroll
    for (int q = 0; q < 8; q++) rp[q] = 0.f;

#pragma unroll
    for (int mf = 0; mf < 4; mf++) {
        int m0 = mb + mf * 16 + g;
        int khg0 = m0 >> 3;                 // group row for m0 (m0&7 == g&7)
        int tigb = g & 3, qb = g >> 2;
#pragma unroll
        for (int nf = 0; nf < 4; nf++) {
            int nl = nb + nf * 8 + tig * 2;
            int nj = (nb + nf * 8) >> 3;
            float v00 = tanhf(acc[mf][nf][0]);
            float v01 = tanhf(acc[mf][nf][1]);
            float v10 = tanhf(acc[mf][nf][2]);
            float v11 = tanhf(acc[mf][nf][3]);
            float* gr0 = out1 + ((size_t)(b * Mm + m0)) * LDB + n0 + nl;
            float* gr1 = out1 + ((size_t)(b * Mm + m0 + 8)) * LDB + n0 + nl;
            *(float2*)gr0 = make_float2(v00, v01);
            *(float2*)gr1 = make_float2(v10, v11);
            int a0 = (khg0 * 16 + nj) * 66 + (tigb * 8 + tig * 2) * 2 + qb;
            T1[a0]     = tf32_rna(v00);
            T1[a0 + 2] = tf32_rna(v01);
            int a1 = a0 + 16 * 66;          // row m0+8 -> next kh group
            T1[a1]     = tf32_rna(v10);
            T1[a1 + 2] = tf32_rna(v11);
            rp[mf * 2]     += v00 + v01;
            rp[mf * 2 + 1] += v10 + v11;
        }
    }
#pragma unroll
    for (int q = 0; q < 8; q++) {
        rp[q] += __shfl_xor_sync(0xffffffffu, rp[q], 1);
        rp[q] += __shfl_xor_sync(0xffffffffu, rp[q], 2);
    }
    if (tig == 0) {
#pragma unroll
        for (int mf = 0; mf < 4; mf++) {
            redm[(mb + mf * 16 + g) * 5 + wn]     = rp[mf * 2];
            redm[(mb + mf * 16 + g + 8) * 5 + wn] = rp[mf * 2 + 1];
        }
    }
    __syncthreads();
    if (tid < 128) {
        float s = redm[tid * 5] + redm[tid * 5 + 1] + redm[tid * 5 + 2] + redm[tid * 5 + 3];
        if (MODE == 1) g_ipart[(b * 32 + nt) * 128 + tid] = s;
        else           qbuf[tid] = s * (1.f / (float)Tt);
    }
    __syncthreads();
    if (MODE == 0 && tid < 128) {  // qfeatatt[a] = Wqfc[a,:] . qmean
        float s = 0.f;
        const float* wp = Wx + tid * Mm;
#pragma unroll 8
        for (int m = 0; m < Mm; m++) s += wp[m] * qbuf[m];
        g_qfeatatt[b * Aa + tid] = s;
    }

    // ================= GEMM2 (K=128): A=A2P staged, B=T1 =================
#pragma unroll
    for (int i = 0; i < 4; i++)
#pragma unroll
        for (int j = 0; j < 4; j++)
#pragma unroll
            for (int q = 0; q < 4; q++) acc[i][j][q] = 0.f;

    ar0 = *(const float4*)(A2P + tid * 4);
    ar1 = *(const float4*)(A2P + 1024 + tid * 4);
    for (int s2 = 0; s2 < 8; s2++) {
        float* Ab = sm + S_APR + (s2 & 1) * 2048;
        *(float4*)(Ab + tid * 4)        = ar0;
        *(float4*)(Ab + 1024 + tid * 4) = ar1;
        __syncthreads();
        if (s2 < 7) {
            ar0 = *(const float4*)(A2P + (s2 + 1) * 2048 + tid * 4);
            ar1 = *(const float4*)(A2P + (s2 + 1) * 2048 + 1024 + tid * 4);
        }
#pragma unroll
        for (int kh = 0; kh < 2; kh++) {
            int khg = s2 * 2 + kh;
            uint4 af[4]; uint2 bf[4];
#pragma unroll
            for (int mf = 0; mf < 4; mf++) {
                int mi = wm * 4 + mf;
                af[mf] = *(const uint4*)(Ab + ((mi * 2 + kh) * 32 + lane) * 4);
            }
#pragma unroll
            for (int nf = 0; nf < 4; nf++)
                bf[nf] = *(const uint2*)(T1 + (khg * 16 + wn * 4 + nf) * 66 + (tig * 8 + g) * 2);
#pragma unroll
            for (int mf = 0; mf < 4; mf++)
#pragma unroll
                for (int nf = 0; nf < 4; nf++)
                    mma_tf32(acc[mf][nf], (const unsigned*)&af[mf], (const unsigned*)&bf[nf]);
        }
    }
    __syncthreads();

    // ================= final epilogue =================
    if (MODE == 1) {
        // logits_i[n] = sum_a watt[a]*tanh(qatt[a]+proj[a][n])
        float p[4][2];
#pragma unroll
        for (int nf = 0; nf < 4; nf++) { p[nf][0] = 0.f; p[nf][1] = 0.f; }
#pragma unroll
        for (int mf = 0; mf < 4; mf++) {
            int a0 = mb + mf * 16 + g, a1 = a0 + 8;
            float w0 = wbuf[a0], q0 = qbuf[a0];
            float w1 = wbuf[a1], q1 = qbuf[a1];
#pragma unroll
            for (int nf = 0; nf < 4; nf++) {
                p[nf][0] += w0 * tanhf(q0 + acc[mf][nf][0]) + w1 * tanhf(q1 + acc[mf][nf][2]);
                p[nf][1] += w0 * tanhf(q0 + acc[mf][nf][1]) + w1 * tanhf(q1 + acc[mf][nf][3]);
            }
        }
#pragma unroll
        for (int nf = 0; nf < 4; nf++)
#pragma unroll
            for (int q = 0; q < 2; q++) {
                p[nf][q] += __shfl_xor_sync(0xffffffffu, p[nf][q], 4);
                p[nf][q] += __shfl_xor_sync(0xffffffffu, p[nf][q], 8);
                p[nf][q] += __shfl_xor_sync(0xffffffffu, p[nf][q], 16);
            }
        if (g == 0) {
#pragma unroll
            for (int nf = 0; nf < 4; nf++) {
                int n = nb + nf * 8 + tig * 2;
                redm[n * 2 + wm]       = p[nf][0];
                redm[(n + 1) * 2 + wm] = p[nf][1];
            }
        }
        __syncthreads();
        if (tid < 128)
            g_logits[b * Nn + n0 + tid] = redm[tid * 2] + redm[tid * 2 + 1];
    } else {
        // store qfeatproj fp32 [a][t]
#pragma unroll
        for (int mf = 0; mf < 4; mf++) {
            int a0 = mb + mf * 16 + g;
#pragma unroll
            for (int nf = 0; nf < 4; nf++) {
                int t = nb + nf * 8 + tig * 2;
                float* p0 = g_qfeatproj + b * (Aa * Tt) + a0 * Tt + t;
                float* p1 = g_qfeatproj + b * (Aa * Tt) + (a0 + 8) * Tt + t;
                *(float2*)p0 = make_float2(acc[mf][nf][0], acc[mf][nf][1]);
                *(float2*)p1 = make_float2(acc[mf][nf][2], acc[mf][nf][3]);
            }
        }
    }
}

// ---------------- kfinal: imean, ifeatatt, lq, softmax, att_feat ----------------
__global__ void __launch_bounds__(1024) kfinal_kernel(const float* __restrict__ Wifc,
                                                      const float* __restrict__ Watt,
                                                      float* __restrict__ out)
{
    __shared__ __align__(16) float att_s[NTOT];
    __shared__ float im[128], ia[128], lq[128];
    __shared__ float red[1024];
    __shared__ float r2[32];

    const int tid = threadIdx.x;
    const int b = blockIdx.x;
    const int m = tid & 127, c = tid >> 7;   // c 0..7

    // imean
    {
        float s = 0.f;
#pragma unroll
        for (int j = c * 4; j < c * 4 + 4; j++) s += g_ipart[(b * 32 + j) * 128 + m];
        red[tid] = s;
    }
    __syncthreads();
    if (tid < 128) {
        float t = 0.f;
#pragma unroll
        for (int cc = 0; cc < 8; cc++) t += red[cc * 128 + tid];
        im[tid] = t * (1.f / (float)Nn);
    }
    __syncthreads();

    // ifeatatt
    {
        float t = 0.f;
        const float* wp = Wifc + m * Mm + c * 16;
#pragma unroll
        for (int j = 0; j < 16; j++) t += wp[j] * im[c * 16 + j];
        red[tid] = t;
    }
    __syncthreads();
    if (tid < 128) {
        float t = 0.f;
#pragma unroll
        for (int cc = 0; cc < 8; cc++) t += red[cc * 128 + tid];
        ia[tid] = t;
    }
    __syncthreads();

    // logits_q[t]
    {
        float t = 0.f;
        const float* qp = g_qfeatproj + b * (Aa * Tt) + (c * 16) * Tt + m;
#pragma unroll
        for (int j = 0; j < 16; j++)
            t += Watt[c * 16 + j] * tanhf(ia[c * 16 + j] + qp[j * Tt]);
        red[tid] = t;
    }
    __syncthreads();
    if (tid < 128) {
        float t = 0.f;
#pragma unroll
        for (int cc = 0; cc < 8; cc++) t += red[cc * 128 + tid];
        lq[tid] = t;
    }
    __syncthreads();

    // softmax over [g_logits[b][:], lq[:]]
    float mx = -1e30f;
    for (int j = tid; j < NTOT; j += 1024) {
        float v = (j < Nn) ? g_logits[b * Nn + j] : lq[j - Nn];
        mx = fmaxf(mx, v);
    }
#pragma unroll
    for (int o = 16; o; o >>= 1) mx = fmaxf(mx, __shfl_xor_sync(0xffffffffu, mx, o));
    if ((tid & 31) == 0) r2[tid >> 5] = mx;
    __syncthreads();
    if (tid < 32) {
        float v = r2[tid];
#pragma unroll
        for (int o = 16; o; o >>= 1) v = fmaxf(v, __shfl_xor_sync(0xffffffffu, v, o));
        r2[tid] = v;
    }
    __syncthreads();
    mx = r2[0];
    __syncthreads();

    float sum = 0.f;
    for (int j = tid; j < NTOT; j += 1024) {
        float v = (j < Nn) ? g_logits[b * Nn + j] : lq[j - Nn];
        float e = expf(v - mx);
        att_s[j] = e;
        sum += e;
    }
#pragma unroll
    for (int o = 16; o; o >>= 1) sum += __shfl_xor_sync(0xffffffffu, sum, o);
    if ((tid & 31) == 0) r2[tid >> 5] = sum;
    __syncthreads();
    if (tid < 32) {
        float v = r2[tid];
#pragma unroll
        for (int o = 16; o; o >>= 1) v += __shfl_xor_sync(0xffffffffu, v, o);
        r2[tid] = v;
    }
    __syncthreads();
    float inv = 1.f / r2[0];
    float* att_g = out + Bn * Mm + b * NTOT;
    for (int j = tid; j < NTOT; j += 1024) {
        float v = att_s[j] * inv;
        att_s[j] = v;
        att_g[j] = v;
    }
    __syncthreads();

    // att_feat[b][m] = joint_feat[b][m][:] . att
    const int warp = tid >> 5, lane = tid & 31;
    const float4* as4 = (const float4*)att_s;
    for (int mm = warp; mm < Mm; mm += 32) {
        const float4* row = (const float4*)(g_inifeat + ((size_t)(b * Mm + mm)) * Nn);
        float s = 0.f;
        for (int j = lane; j < Nn / 4; j += 32) {
            float4 v = row[j], a = as4[j];
            s += v.x * a.x + v.y * a.y + v.z * a.z + v.w * a.w;
        }
        {
            const float4* qr = (const float4*)(g_inqfeat + b * (Mm * Tt) + mm * Tt);
            float4 v = qr[lane], a = as4[Nn / 4 + lane];
            s += v.x * a.x + v.y * a.y + v.z * a.z + v.w * a.w;
        }
#pragma unroll
        for (int o = 16; o; o >>= 1) s += __shfl_down_sync(0xffffffffu, s, o);
        if (lane == 0) out[b * Mm + mm] = s;
    }
}

// ---------------- launch ----------------
extern "C" void kernel_launch(void* const* d_in, const int* in_sizes, int n_in,
                              void* d_out, int out_size)
{
    (void)in_sizes; (void)n_in; (void)out_size;
    const float* img  = (const float*)d_in[0];
    const float* text = (const float*)d_in[1];
    const float* Wimg = (const float*)d_in[2];
    const float* Wtxt = (const float*)d_in[3];
    const float* Wqfc = (const float*)d_in[4];
    const float* Wifc = (const float*)d_in[5];
    const float* Wipc = (const float*)d_in[6];
    const float* Wqpc = (const float*)d_in[7];
    const float* Watt = (const float*)d_in[8];
    float* out = (float*)d_out;

    const int smem = S_TOT * (int)sizeof(float);   // 104448 B
    cudaFuncSetAttribute(fused_kernel<HIDn, Tt, 0>, cudaFuncAttributeMaxDynamicSharedMemorySize, smem);
    cudaFuncSetAttribute(fused_kernel<Cc, Nn, 1>,   cudaFuncAttributeMaxDynamicSharedMemorySize, smem);

    prep_kernel<<<256, 256>>>(Wimg, Wtxt, Wipc, Wqpc);

    // text branch: fills g_inqfeat, g_qfeatproj, g_qfeatatt
    float* inq = nullptr; cudaGetSymbolAddress((void**)&inq, g_inqfeat);
    float* inf = nullptr; cudaGetSymbolAddress((void**)&inf, g_inifeat);

    fused_kernel<HIDn, Tt, 0><<<Bn, 256, smem>>>(text, Wqfc, inq);
    fused_kernel<Cc, Nn, 1><<<dim3(32, Bn), 256, smem>>>(img, Watt, inf);
    kfinal_kernel<<<Bn, 1024>>>(Wifc, Watt, out);
}

// round 4
// speedup vs baseline: 2.4386x; 1.2526x over previous
#include <cuda_runtime.h>
#include <cuda_fp16.h>
#include <math.h>

// Problem constants
#define Bn   64
#define Cc   256
#define Nn   4096
#define HIDn 512
#define Tt   128
#define Mm   128
#define Aa   128
#define NTOT 4224   // Nn + Tt

// -------- device scratch (allocation-free: __device__ globals) --------
__device__ __half g_WimgP[Mm * Cc];       // permuted fp16 A, img GEMM1 (16 slices)
__device__ __half g_WtxtP[Mm * HIDn];     // permuted fp16 A, text GEMM1 (32 slices)
__device__ __half g_WipcP[Aa * Mm];       // permuted fp16 A, img GEMM2 (8 slices)
__device__ __half g_WqpcP[Aa * Mm];       // permuted fp16 A, text GEMM2 (8 slices)
__device__ float g_inqfeat[Bn * Mm * Tt];     // 4 MB
__device__ float g_qfeatproj[Bn * Aa * Tt];   // 4 MB
__device__ float g_qfeatatt[Bn * Aa];
__device__ float g_inifeat[33554432];         // [64][128][4096] = 128 MB fp32
__device__ float g_ipart[Bn * 32 * Mm];       // per-tile row-sum partials
__device__ float g_logits[Bn * Nn];
__device__ float g_afpart[Bn * 16 * Mm];      // att_feat partials

// fast tanh: rel err ~1e-6
__device__ __forceinline__ float ftanh(float x) {
    x = fminf(fmaxf(x, -15.f), 15.f);
    float e = __expf(2.f * x);
    return __fdividef(e - 1.f, e + 1.f);
}

__device__ __forceinline__ void mma_f16(float d[4], const unsigned* a, const unsigned* b) {
    asm volatile("mma.sync.aligned.m16n8k16.row.col.f32.f16.f16.f32 "
                 "{%0,%1,%2,%3}, {%4,%5,%6,%7}, {%8,%9}, {%0,%1,%2,%3};"
                 : "+f"(d[0]), "+f"(d[1]), "+f"(d[2]), "+f"(d[3])
                 : "r"(a[0]), "r"(a[1]), "r"(a[2]), "r"(a[3]), "r"(b[0]), "r"(b[1]));
}

// permuted A half index for m16n8k16: per slice (16 k), per mi (16 m), per lane,
// one uint4 = [a0.lo a0.hi a1.lo a1.hi a2.lo a2.hi a3.lo a3.hi]
__device__ __forceinline__ int permh_idx(int m, int k) {
    int s = k >> 4, kk = k & 15;
    int khalf = kk >> 3, tig = (kk & 7) >> 1, kp = kk & 1;
    int mi = m >> 4, ml = m & 15, h = ml >> 3, g = ml & 7;
    return ((s * 8 + mi) * 32 + g * 4 + tig) * 8 + khalf * 4 + h * 2 + kp;
}

// ---------------- prep ----------------
__global__ void prep_kernel(const float* __restrict__ Wimg, const float* __restrict__ Wtxt,
                            const float* __restrict__ Wipc, const float* __restrict__ Wqpc)
{
    int i = blockIdx.x * blockDim.x + threadIdx.x;   // 0..65535
    { int m = i >> 9, k = i & 511; g_WtxtP[permh_idx(m, k)] = __float2half(Wtxt[i]); }
    if (i < Mm * Cc) { int m = i >> 8, k = i & 255; g_WimgP[permh_idx(m, k)] = __float2half(Wimg[i]); }
    if (i < Aa * Mm) {
        int m = i >> 7, k = i & 127;
        g_WipcP[permh_idx(m, k)] = __float2half(Wipc[i]);
        g_WqpcP[permh_idx(m, k)] = __float2half(Wqpc[i]);
    }
}

// ---------------- fused dual-GEMM kernel (text MODE=0, img MODE=1) ----------------
// smem byte offsets
#define SB_B0  0        // B slice buf 0: 8*134 half2 = 4288 B
#define SB_B1  4288
#define SB_T1  8576     // 64*134 half2 = 34304 B
#define SB_RED 42880    // 640 floats = 2560 B
#define SB_Q   45440    // 128 floats
#define SB_W   45952    // 128 floats
#define SB_TOT 46464

template<int K1, int LDB, int MODE>
__global__ void __launch_bounds__(256, 2) fused_kernel(
    const float* __restrict__ Bsrc,   // img_feat or text_feat
    const float* __restrict__ Wx,     // Watt (img) / Wqfc (text)
    float* __restrict__ out1)         // g_inifeat / g_inqfeat
{
    extern __shared__ char smc[];
    __half2* Bh0 = (__half2*)(smc + SB_B0);
    __half2* Bh1 = (__half2*)(smc + SB_B1);
    __half2* T1  = (__half2*)(smc + SB_T1);
    float* redm = (float*)(smc + SB_RED);
    float* qbuf = (float*)(smc + SB_Q);
    float* wbuf = (float*)(smc + SB_W);

    const int tid  = threadIdx.x;
    const int lane = tid & 31;
    const int w    = tid >> 5;
    const int g    = lane >> 2;
    const int tig  = lane & 3;
    const int wm   = w >> 2;          // 0..1
    const int wn   = w & 3;           // 0..3
    const int mb   = wm * 64;
    const int nb   = wn * 32;

    const int b  = (MODE == 1) ? blockIdx.y : blockIdx.x;
    const int nt = (MODE == 1) ? blockIdx.x : 0;
    const int n0 = nt * 128;

    const uint4* A1P = (const uint4*)((MODE == 1) ? g_WimgP : g_WtxtP);
    const uint4* A2P = (const uint4*)((MODE == 1) ? g_WipcP : g_WqpcP);
    const float* Bb0 = Bsrc + (size_t)b * K1 * LDB + n0;

    if (MODE == 1 && tid < 128) {
        qbuf[tid] = g_qfeatatt[b * Aa + tid];
        wbuf[tid] = Wx[tid];
    }

    // B producer coords: kk2 = k-pair 0..7, nq = n quad
    const int kk2 = tid & 7;
    const int nq  = (tid >> 3) * 4;

    const int mi0 = wm * 4;
    const int nn0 = nb + g;

    float acc[4][4][4];
#pragma unroll
    for (int i = 0; i < 4; i++)
#pragma unroll
        for (int j = 0; j < 4; j++)
#pragma unroll
            for (int q = 0; q < 4; q++) acc[i][j][q] = 0.f;

    // ================= GEMM1 =================
    const int NS1 = K1 / 16;
    float4 bx0, bx1;
    {
        const float* bp = Bb0 + (size_t)(2 * kk2) * LDB + nq;
        bx0 = *(const float4*)bp;
        bx1 = *(const float4*)(bp + LDB);
    }

    for (int s = 0; s < NS1; s++) {
        __half2* Bb = (s & 1) ? Bh1 : Bh0;
        Bb[kk2 * 134 + nq]     = __floats2half2_rn(bx0.x, bx1.x);
        Bb[kk2 * 134 + nq + 1] = __floats2half2_rn(bx0.y, bx1.y);
        Bb[kk2 * 134 + nq + 2] = __floats2half2_rn(bx0.z, bx1.z);
        Bb[kk2 * 134 + nq + 3] = __floats2half2_rn(bx0.w, bx1.w);
        __syncthreads();
        if (s + 1 < NS1) {
            const float* bp = Bb0 + (size_t)((s + 1) * 16 + 2 * kk2) * LDB + nq;
            bx0 = *(const float4*)bp;
            bx1 = *(const float4*)(bp + LDB);
        }
        uint4 af[4];
#pragma unroll
        for (int mf = 0; mf < 4; mf++)
            af[mf] = A1P[(s * 8 + mi0 + mf) * 32 + lane];
        const unsigned* Bu = (const unsigned*)Bb;
#pragma unroll
        for (int nf = 0; nf < 4; nf++) {
            unsigned bf[2];
            int nn = nn0 + nf * 8;
            bf[0] = Bu[tig * 134 + nn];
            bf[1] = Bu[(tig + 4) * 134 + nn];
#pragma unroll
            for (int mf = 0; mf < 4; mf++)
                mma_f16(acc[mf][nf], (const unsigned*)&af[mf], bf);
        }
        __syncthreads();
    }

    // ============ mid-epilogue: tanh, store out1 fp32 + T1 fp16(k-major), row sums ============
    float rp[8];
#pragma unroll
    for (int q = 0; q < 8; q++) rp[q] = 0.f;

#pragma unroll
    for (int mf = 0; mf < 4; mf++) {
        int m0 = mb + mf * 16 + g;
        int kp0 = m0 >> 1;
        int kp1 = (m0 + 8) >> 1;   // works for odd g too ((m0+7)>>1 == (m0+8)>>1 when m0 odd)
#pragma unroll
        for (int nf = 0; nf < 4; nf++) {
            int nl = nb + nf * 8 + tig * 2;
            float v0 = ftanh(acc[mf][nf][0]);
            float v1 = ftanh(acc[mf][nf][1]);
            float v2 = ftanh(acc[mf][nf][2]);
            float v3 = ftanh(acc[mf][nf][3]);
            float* gr0 = out1 + ((size_t)(b * Mm + m0)) * LDB + n0 + nl;
            float* gr1 = out1 + ((size_t)(b * Mm + m0 + 8)) * LDB + n0 + nl;
            *(float2*)gr0 = make_float2(v0, v1);
            *(float2*)gr1 = make_float2(v2, v3);
            __half2 h01 = __floats2half2_rn(v0, v1);
            __half2 h23 = __floats2half2_rn(v2, v3);
            unsigned u01 = __shfl_xor_sync(0xffffffffu, *(unsigned*)&h01, 4);
            unsigned u23 = __shfl_xor_sync(0xffffffffu, *(unsigned*)&h23, 4);
            __half2 p01 = *(__half2*)&u01;
            __half2 p23 = *(__half2*)&u23;
            if ((g & 1) == 0) {
                // rows (m0, m0+1) at kp0
                __half2 c0 = __lows2half2(h01, p01);
                __half2 c1 = __highs2half2(h01, p01);
                uint2 st; st.x = *(unsigned*)&c0; st.y = *(unsigned*)&c1;
                *(uint2*)(T1 + kp0 * 134 + nl) = st;
            } else {
                // rows (m0+7, m0+8) at kp1
                __half2 c0 = __lows2half2(p23, h23);
                __half2 c1 = __highs2half2(p23, h23);
                uint2 st; st.x = *(unsigned*)&c0; st.y = *(unsigned*)&c1;
                *(uint2*)(T1 + kp1 * 134 + nl) = st;
            }
            rp[mf * 2]     += v0 + v1;
            rp[mf * 2 + 1] += v2 + v3;
        }
    }
#pragma unroll
    for (int q = 0; q < 8; q++) {
        rp[q] += __shfl_xor_sync(0xffffffffu, rp[q], 1);
        rp[q] += __shfl_xor_sync(0xffffffffu, rp[q], 2);
    }
    if (tig == 0) {
#pragma unroll
        for (int mf = 0; mf < 4; mf++) {
            redm[(mb + mf * 16 + g) * 5 + wn]     = rp[mf * 2];
            redm[(mb + mf * 16 + g + 8) * 5 + wn] = rp[mf * 2 + 1];
        }
    }
    __syncthreads();
    if (tid < 128) {
        float s = redm[tid * 5] + redm[tid * 5 + 1] + redm[tid * 5 + 2] + redm[tid * 5 + 3];
        if (MODE == 1) g_ipart[(b * 32 + nt) * 128 + tid] = s;
        else           qbuf[tid] = s * (1.f / (float)Tt);
    }
    __syncthreads();
    if (MODE == 0 && tid < 128) {  // qfeatatt[a] = Wqfc[a,:] . qmean
        float s = 0.f;
        const float* wp = Wx + tid * Mm;
#pragma unroll 8
        for (int m = 0; m < Mm; m++) s += wp[m] * qbuf[m];
        g_qfeatatt[b * Aa + tid] = s;
    }

    // ================= GEMM2 (K=128): A from global (L2-hot), B = T1, sync-free =================
#pragma unroll
    for (int i = 0; i < 4; i++)
#pragma unroll
        for (int j = 0; j < 4; j++)
#pragma unroll
            for (int q = 0; q < 4; q++) acc[i][j][q] = 0.f;

    const unsigned* T1u = (const unsigned*)T1;
    for (int s2 = 0; s2 < 8; s2++) {
        uint4 af[4];
#pragma unroll
        for (int mf = 0; mf < 4; mf++)
            af[mf] = A2P[(s2 * 8 + mi0 + mf) * 32 + lane];
#pragma unroll
        for (int nf = 0; nf < 4; nf++) {
            unsigned bf[2];
            int nn = nn0 + nf * 8;
            bf[0] = T1u[(s2 * 8 + tig) * 134 + nn];
            bf[1] = T1u[(s2 * 8 + tig + 4) * 134 + nn];
#pragma unroll
            for (int mf = 0; mf < 4; mf++)
                mma_f16(acc[mf][nf], (const unsigned*)&af[mf], bf);
        }
    }
    __syncthreads();

    // ================= final epilogue =================
    if (MODE == 1) {
        float p[4][2];
#pragma unroll
        for (int nf = 0; nf < 4; nf++) { p[nf][0] = 0.f; p[nf][1] = 0.f; }
#pragma unroll
        for (int mf = 0; mf < 4; mf++) {
            int a0 = mb + mf * 16 + g, a1 = a0 + 8;
            float w0 = wbuf[a0], q0 = qbuf[a0];
            float w1 = wbuf[a1], q1 = qbuf[a1];
#pragma unroll
            for (int nf = 0; nf < 4; nf++) {
                p[nf][0] += w0 * ftanh(q0 + acc[mf][nf][0]) + w1 * ftanh(q1 + acc[mf][nf][2]);
                p[nf][1] += w0 * ftanh(q0 + acc[mf][nf][1]) + w1 * ftanh(q1 + acc[mf][nf][3]);
            }
        }
#pragma unroll
        for (int nf = 0; nf < 4; nf++)
#pragma unroll
            for (int q = 0; q < 2; q++) {
                p[nf][q] += __shfl_xor_sync(0xffffffffu, p[nf][q], 4);
                p[nf][q] += __shfl_xor_sync(0xffffffffu, p[nf][q], 8);
                p[nf][q] += __shfl_xor_sync(0xffffffffu, p[nf][q], 16);
            }
        if (g == 0) {
#pragma unroll
            for (int nf = 0; nf < 4; nf++) {
                int n = nb + nf * 8 + tig * 2;
                redm[n * 2 + wm]       = p[nf][0];
                redm[(n + 1) * 2 + wm] = p[nf][1];
            }
        }
        __syncthreads();
        if (tid < 128)
            g_logits[b * Nn + n0 + tid] = redm[tid * 2] + redm[tid * 2 + 1];
    } else {
        // store qfeatproj fp32 [a][t]
#pragma unroll
        for (int mf = 0; mf < 4; mf++) {
            int a0 = mb + mf * 16 + g;
#pragma unroll
            for (int nf = 0; nf < 4; nf++) {
                int t = nb + nf * 8 + tig * 2;
                float* p0 = g_qfeatproj + b * (Aa * Tt) + a0 * Tt + t;
                float* p1 = g_qfeatproj + b * (Aa * Tt) + (a0 + 8) * Tt + t;
                *(float2*)p0 = make_float2(acc[mf][nf][0], acc[mf][nf][1]);
                *(float2*)p1 = make_float2(acc[mf][nf][2], acc[mf][nf][3]);
            }
        }
    }
}

// ---------------- k3: imean, ifeatatt, lq, softmax -> att in out ----------------
__global__ void __launch_bounds__(1024) k3_kernel(const float* __restrict__ Wifc,
                                                  const float* __restrict__ Watt,
                                                  float* __restrict__ out)
{
    __shared__ __align__(16) float att_s[NTOT];
    __shared__ float im[128], ia[128], lq[128];
    __shared__ float red[1024];
    __shared__ float r2[32];

    const int tid = threadIdx.x;
    const int b = blockIdx.x;
    const int m = tid & 127, c = tid >> 7;   // c 0..7

    // imean
    {
        float s = 0.f;
#pragma unroll
        for (int j = c * 4; j < c * 4 + 4; j++) s += g_ipart[(b * 32 + j) * 128 + m];
        red[tid] = s;
    }
    __syncthreads();
    if (tid < 128) {
        float t = 0.f;
#pragma unroll
        for (int cc = 0; cc < 8; cc++) t += red[cc * 128 + tid];
        im[tid] = t * (1.f / (float)Nn);
    }
    __syncthreads();

    // ifeatatt
    {
        float t = 0.f;
        const float* wp = Wifc + m * Mm + c * 16;
#pragma unroll
        for (int j = 0; j < 16; j++) t += wp[j] * im[c * 16 + j];
        red[tid] = t;
    }
    __syncthreads();
    if (tid < 128) {
        float t = 0.f;
#pragma unroll
        for (int cc = 0; cc < 8; cc++) t += red[cc * 128 + tid];
        ia[tid] = t;
    }
    __syncthreads();

    // logits_q[t]
    {
        float t = 0.f;
        const float* qp = g_qfeatproj + b * (Aa * Tt) + (c * 16) * Tt + m;
#pragma unroll
        for (int j = 0; j < 16; j++)
            t += Watt[c * 16 + j] * ftanh(ia[c * 16 + j] + qp[j * Tt]);
        red[tid] = t;
    }
    __syncthreads();
    if (tid < 128) {
        float t = 0.f;
#pragma unroll
        for (int cc = 0; cc < 8; cc++) t += red[cc * 128 + tid];
        lq[tid] = t;
    }
    __syncthreads();

    // softmax over [g_logits[b][:], lq[:]]
    float mx = -1e30f;
    for (int j = tid; j < NTOT; j += 1024) {
        float v = (j < Nn) ? g_logits[b * Nn + j] : lq[j - Nn];
        mx = fmaxf(mx, v);
    }
#pragma unroll
    for (int o = 16; o; o >>= 1) mx = fmaxf(mx, __shfl_xor_sync(0xffffffffu, mx, o));
    if ((tid & 31) == 0) r2[tid >> 5] = mx;
    __syncthreads();
    if (tid < 32) {
        float v = r2[tid];
#pragma unroll
        for (int o = 16; o; o >>= 1) v = fmaxf(v, __shfl_xor_sync(0xffffffffu, v, o));
        r2[tid] = v;
    }
    __syncthreads();
    mx = r2[0];
    __syncthreads();

    float sum = 0.f;
    for (int j = tid; j < NTOT; j += 1024) {
        float v = (j < Nn) ? g_logits[b * Nn + j] : lq[j - Nn];
        float e = expf(v - mx);
        att_s[j] = e;
        sum += e;
    }
#pragma unroll
    for (int o = 16; o; o >>= 1) sum += __shfl_xor_sync(0xffffffffu, sum, o);
    if ((tid & 31) == 0) r2[tid >> 5] = sum;
    __syncthreads();
    if (tid < 32) {
        float v = r2[tid];
#pragma unroll
        for (int o = 16; o; o >>= 1) v += __shfl_xor_sync(0xffffffffu, v, o);
        r2[tid] = v;
    }
    __syncthreads();
    float inv = 1.f / r2[0];
    float* att_g = out + Bn * Mm + b * NTOT;
    for (int j = tid; j < NTOT; j += 1024) att_g[j] = att_s[j] * inv;
}

// ---------------- k4: att_feat partials over n-chunks ----------------
__global__ void __launch_bounds__(256) k4_kernel(const float* __restrict__ out)
{
    __shared__ __align__(16) float att_s[256 + 128];
    const int ch = blockIdx.x;      // 0..15
    const int b  = blockIdx.y;
    const int tid = threadIdx.x;

    const float* att = out + Bn * Mm + b * NTOT;
    att_s[tid] = att[ch * 256 + tid];
    if (ch == 15 && tid < 128) att_s[256 + tid] = att[Nn + tid];
    __syncthreads();

    const int warp = tid >> 5, lane = tid & 31;
    const float4* a4 = (const float4*)att_s;
#pragma unroll 1
    for (int i = 0; i < 16; i++) {
        int m = warp * 16 + i;
        const float4* row = (const float4*)(g_inifeat + ((size_t)(b * Mm + m)) * Nn + ch * 256);
        float4 v0 = row[lane],      w0 = a4[lane];
        float4 v1 = row[lane + 32], w1 = a4[lane + 32];
        float s = v0.x * w0.x + v0.y * w0.y + v0.z * w0.z + v0.w * w0.w
                + v1.x * w1.x + v1.y * w1.y + v1.z * w1.z + v1.w * w1.w;
        if (ch == 15) {
            const float4* qr = (const float4*)(g_inqfeat + b * (Mm * Tt) + m * Tt);
            float4 v = qr[lane], a = a4[64 + lane];
            s += v.x * a.x + v.y * a.y + v.z * a.z + v.w * a.w;
        }
#pragma unroll
        for (int o = 16; o; o >>= 1) s += __shfl_down_sync(0xffffffffu, s, o);
        if (lane == 0) g_afpart[(b * 16 + ch) * 128 + m] = s;
    }
}

// ---------------- k5: reduce partials ----------------
__global__ void __launch_bounds__(128) k5_kernel(float* __restrict__ out)
{
    const int b = blockIdx.x, m = threadIdx.x;
    float s = 0.f;
#pragma unroll
    for (int ch = 0; ch < 16; ch++) s += g_afpart[(b * 16 + ch) * 128 + m];
    out[b * Mm + m] = s;
}

// ---------------- launch ----------------
extern "C" void kernel_launch(void* const* d_in, const int* in_sizes, int n_in,
                              void* d_out, int out_size)
{
    (void)in_sizes; (void)n_in; (void)out_size;
    const float* img  = (const float*)d_in[0];
    const float* text = (const float*)d_in[1];
    const float* Wimg = (const float*)d_in[2];
    const float* Wtxt = (const float*)d_in[3];
    const float* Wqfc = (const float*)d_in[4];
    const float* Wifc = (const float*)d_in[5];
    const float* Wipc = (const float*)d_in[6];
    const float* Wqpc = (const float*)d_in[7];
    const float* Watt = (const float*)d_in[8];
    float* out = (float*)d_out;

    float* inq = nullptr; cudaGetSymbolAddress((void**)&inq, g_inqfeat);
    float* inf = nullptr; cudaGetSymbolAddress((void**)&inf, g_inifeat);

    prep_kernel<<<256, 256>>>(Wimg, Wtxt, Wipc, Wqpc);
    fused_kernel<HIDn, Tt, 0><<<Bn, 256, SB_TOT>>>(text, Wqfc, inq);
    fused_kernel<Cc, Nn, 1><<<dim3(32, Bn), 256, SB_TOT>>>(img, Watt, inf);
    k3_kernel<<<Bn, 1024>>>(Wifc, Watt, out);
    k4_kernel<<<dim3(16, Bn), 256>>>(out);
    k5_kernel<<<Bn, 128>>>(out);
}

// round 6
// speedup vs baseline: 2.5094x; 1.0290x over previous
#include <cuda_runtime.h>
#include <cuda_fp16.h>
#include <math.h>
#include <cstdint>

// Problem constants
#define Bn   64
#define Cc   256
#define Nn   4096
#define HIDn 512
#define Tt   128
#define Mm   128
#define Aa   128
#define NTOT 4224   // Nn + Tt

// -------- device scratch (allocation-free: __device__ globals) --------
__device__ __half g_WimgP[Mm * Cc];       // permuted fp16 A, img GEMM1
__device__ __half g_WtxtP[Mm * HIDn];     // permuted fp16 A, text GEMM1
__device__ __half g_WipcP[Aa * Mm];       // permuted fp16 A, img GEMM2
__device__ __half g_WqpcP[Aa * Mm];       // permuted fp16 A, text GEMM2
__device__ __half g_inqfeat[Bn * Mm * Tt];    // 2 MB fp16
__device__ float  g_qfeatproj[Bn * Aa * Tt];  // 4 MB
__device__ float  g_qfeatatt[Bn * Aa];
__device__ __half g_inifeat[33554432];        // [64][128][4096] fp16 = 64 MB
__device__ float  g_ipart[Bn * 32 * Mm];
__device__ float  g_logits[Bn * Nn];
__device__ float  g_afpart[Bn * 16 * Mm];

// fast tanh: rel err ~1e-6
__device__ __forceinline__ float ftanh(float x) {
    x = fminf(fmaxf(x, -15.f), 15.f);
    float e = __expf(2.f * x);
    return __fdividef(e - 1.f, e + 1.f);
}

__device__ __forceinline__ void mma_f16(float d[4], const unsigned* a, const unsigned* b) {
    asm volatile("mma.sync.aligned.m16n8k16.row.col.f32.f16.f16.f32 "
                 "{%0,%1,%2,%3}, {%4,%5,%6,%7}, {%8,%9}, {%0,%1,%2,%3};"
                 : "+f"(d[0]), "+f"(d[1]), "+f"(d[2]), "+f"(d[3])
                 : "r"(a[0]), "r"(a[1]), "r"(a[2]), "r"(a[3]), "r"(b[0]), "r"(b[1]));
}

// legacy permuted A index (m16n8k16): per slice (16k) per mi (16m) per lane,
// one uint4 = 8 halves = the full A fragment
__device__ __forceinline__ int permh_idx(int m, int k) {
    int s = k >> 4, kk = k & 15;
    int khalf = kk >> 3, tig = (kk & 7) >> 1, kp = kk & 1;
    int mi = m >> 4, ml = m & 15, h = ml >> 3, g = ml & 7;
    return ((s * 8 + mi) * 32 + g * 4 + tig) * 8 + khalf * 4 + h * 2 + kp;
}

// fragment-major r-position within a group of 8 k-pairs: pair (r, r+4) adjacent
__device__ __forceinline__ int rpos(int r) { return ((r & 3) << 1) + ((r & 7) >> 2); }

// ---------------- prep ----------------
__global__ void prep_kernel(const float* __restrict__ Wimg, const float* __restrict__ Wtxt,
                            const float* __restrict__ Wipc, const float* __restrict__ Wqpc)
{
    int i = blockIdx.x * blockDim.x + threadIdx.x;   // 0..65535
    { int m = i >> 9, k = i & 511; g_WtxtP[permh_idx(m, k)] = __float2half(Wtxt[i]); }
    if (i < Mm * Cc) { int m = i >> 8, k = i & 255; g_WimgP[permh_idx(m, k)] = __float2half(Wimg[i]); }
    if (i < Aa * Mm) {
        int a = i >> 7, k = i & 127;
        g_WipcP[permh_idx(a, k)] = __float2half(Wipc[i]);
        g_WqpcP[permh_idx(a, k)] = __float2half(Wqpc[i]);
    }
}

// ---------------- fused dual-GEMM kernel (text MODE=0, img MODE=1) ----------------
// smem byte offsets
// B bufs: 128 n x 10 half2 (positions 0..7 used, stride 10) = 5120 B each
// T1: 128 n x 66 half2 (64 used, stride 66) = 33792 B
#define SB_B0  0
#define SB_B1  5120
#define SB_T1  10240
#define SB_RED 44032    // 640 floats
#define SB_Q   46592    // 128 floats
#define SB_W   47104    // 128 floats
#define SB_TOT 47616

template<int K1, int LDB, int MODE>
__global__ void __launch_bounds__(256, 2) fused_kernel(
    const float* __restrict__ Bsrc,   // img_feat or text_feat
    const float* __restrict__ Wx,     // Watt (img) / Wqfc (text)
    __half* __restrict__ out1)        // g_inifeat / g_inqfeat (fp16)
{
    extern __shared__ char smc[];
    __half2* T1  = (__half2*)(smc + SB_T1);
    float* redm = (float*)(smc + SB_RED);
    float* qbuf = (float*)(smc + SB_Q);
    float* wbuf = (float*)(smc + SB_W);

    const int tid  = threadIdx.x;
    const int lane = tid & 31;
    const int w    = tid >> 5;
    const int g    = lane >> 2;
    const int tig  = lane & 3;
    const int wm   = w >> 2;          // 0..1
    const int wn   = w & 3;           // 0..3
    const int mb   = wm * 64;
    const int nb   = wn * 32;

    const int b  = (MODE == 1) ? blockIdx.y : blockIdx.x;
    const int nt = (MODE == 1) ? blockIdx.x : 0;
    const int n0 = nt * 128;

    const uint4* A1P = (const uint4*)((MODE == 1) ? g_WimgP : g_WtxtP);
    const uint4* A2P = (const uint4*)((MODE == 1) ? g_WipcP : g_WqpcP);
    const float* Bb0 = Bsrc + (size_t)b * K1 * LDB + n0;

    if (MODE == 1 && tid < 128) {
        qbuf[tid] = g_qfeatatt[b * Aa + tid];
        wbuf[tid] = Wx[tid];
    }

    // B producer coords
    const int kk2  = tid & 7;                 // k-pair r within slice
    const int nq   = (tid >> 3) * 4;          // n base
    const int poff = rpos(kk2);               // fragment-major position
    const int mi0  = wm * 4;
    const int nn0  = nb + g;

    float acc[4][4][4];
#pragma unroll
    for (int i = 0; i < 4; i++)
#pragma unroll
        for (int j = 0; j < 4; j++)
#pragma unroll
            for (int q = 0; q < 4; q++) acc[i][j][q] = 0.f;

    // ================= GEMM1 (single sync per slice, 2-buffer rotation) =================
    const int NS1 = K1 / 16;
    float4 bx0, bx1;
    {
        const float* bp = Bb0 + (size_t)(2 * kk2) * LDB + nq;
        bx0 = *(const float4*)bp;
        bx1 = *(const float4*)(bp + LDB);
    }

    for (int s = 0; s < NS1; s++) {
        __half2* Bb = (__half2*)(smc + ((s & 1) ? SB_B1 : SB_B0));
        Bb[(nq + 0) * 10 + poff] = __floats2half2_rn(bx0.x, bx1.x);
        Bb[(nq + 1) * 10 + poff] = __floats2half2_rn(bx0.y, bx1.y);
        Bb[(nq + 2) * 10 + poff] = __floats2half2_rn(bx0.z, bx1.z);
        Bb[(nq + 3) * 10 + poff] = __floats2half2_rn(bx0.w, bx1.w);
        __syncthreads();
        if (s + 1 < NS1) {
            const float* bp = Bb0 + (size_t)((s + 1) * 16 + 2 * kk2) * LDB + nq;
            bx0 = *(const float4*)bp;
            bx1 = *(const float4*)(bp + LDB);
        }
        uint4 af[4];
#pragma unroll
        for (int mf = 0; mf < 4; mf++)
            af[mf] = A1P[(s * 8 + mi0 + mf) * 32 + lane];
        const unsigned* Bu = (const unsigned*)Bb;
#pragma unroll
        for (int nf = 0; nf < 4; nf++) {
            int nn = nn0 + nf * 8;
            uint2 bf = *(const uint2*)(Bu + nn * 10 + tig * 2);
#pragma unroll
            for (int mf = 0; mf < 4; mf++)
                mma_f16(acc[mf][nf], (const unsigned*)&af[mf], (const unsigned*)&bf);
        }
    }
    __syncthreads();

    // ============ mid-epilogue: tanh, store out1 fp16 + T1 fp16 (fragment-major), row sums ============
    float rp[8];
#pragma unroll
    for (int q = 0; q < 8; q++) rp[q] = 0.f;

#pragma unroll
    for (int mf = 0; mf < 4; mf++) {
        int m0 = mb + mf * 16 + g;
        int kp0 = m0 >> 1;            // even g: pair (m0, m0+1)
        int kp1 = (m0 + 7) >> 1;      // odd g: pair (m0+7, m0+8)
        int o0 = ((kp0 >> 3) << 3) + rpos(kp0);
        int o1 = ((kp1 >> 3) << 3) + rpos(kp1);
#pragma unroll
        for (int nf = 0; nf < 4; nf++) {
            int nl = nb + nf * 8 + tig * 2;
            float v0 = ftanh(acc[mf][nf][0]);
            float v1 = ftanh(acc[mf][nf][1]);
            float v2 = ftanh(acc[mf][nf][2]);
            float v3 = ftanh(acc[mf][nf][3]);
            __half* gr0 = out1 + ((size_t)(b * Mm + m0)) * LDB + n0 + nl;
            __half* gr1 = out1 + ((size_t)(b * Mm + m0 + 8)) * LDB + n0 + nl;
            *(__half2*)gr0 = __floats2half2_rn(v0, v1);
            *(__half2*)gr1 = __floats2half2_rn(v2, v3);
            __half2 h01 = __floats2half2_rn(v0, v1);
            __half2 h23 = __floats2half2_rn(v2, v3);
            unsigned u01 = __shfl_xor_sync(0xffffffffu, *(unsigned*)&h01, 4);
            unsigned u23 = __shfl_xor_sync(0xffffffffu, *(unsigned*)&h23, 4);
            __half2 p01 = *(__half2*)&u01;
            __half2 p23 = *(__half2*)&u23;
            if ((g & 1) == 0) {
                // pair rows (m0, m0+1): c0 -> n=nl, c1 -> n=nl+1
                __half2 c0 = __lows2half2(h01, p01);
                __half2 c1 = __highs2half2(h01, p01);
                T1[nl * 66 + o0]       = c0;
                T1[(nl + 1) * 66 + o0] = c1;
            } else {
                // pair rows (m0+7, m0+8)
                __half2 c0 = __lows2half2(p23, h23);
                __half2 c1 = __highs2half2(p23, h23);
                T1[nl * 66 + o1]       = c0;
                T1[(nl + 1) * 66 + o1] = c1;
            }
            rp[mf * 2]     += v0 + v1;
            rp[mf * 2 + 1] += v2 + v3;
        }
    }
#pragma unroll
    for (int q = 0; q < 8; q++) {
        rp[q] += __shfl_xor_sync(0xffffffffu, rp[q], 1);
        rp[q] += __shfl_xor_sync(0xffffffffu, rp[q], 2);
    }
    if (tig == 0) {
#pragma unroll
        for (int mf = 0; mf < 4; mf++) {
            redm[(mb + mf * 16 + g) * 5 + wn]     = rp[mf * 2];
            redm[(mb + mf * 16 + g + 8) * 5 + wn] = rp[mf * 2 + 1];
        }
    }
    __syncthreads();
    if (tid < 128) {
        float s = redm[tid * 5] + redm[tid * 5 + 1] + redm[tid * 5 + 2] + redm[tid * 5 + 3];
        if (MODE == 1) g_ipart[(b * 32 + nt) * 128 + tid] = s;
        else           qbuf[tid] = s * (1.f / (float)Tt);
    }
    __syncthreads();
    if (MODE == 0 && tid < 128) {  // qfeatatt[a] = Wqfc[a,:] . qmean
        float s = 0.f;
        const float* wp = Wx + tid * Mm;
#pragma unroll 8
        for (int m = 0; m < Mm; m++) s += wp[m] * qbuf[m];
        g_qfeatatt[b * Aa + tid] = s;
    }

    // ================= GEMM2 (K=128): A global (L2-hot), B = T1, sync-free =================
#pragma unroll
    for (int i = 0; i < 4; i++)
#pragma unroll
        for (int j = 0; j < 4; j++)
#pragma unroll
            for (int q = 0; q < 4; q++) acc[i][j][q] = 0.f;

    const unsigned* T1u = (const unsigned*)T1;
    for (int s2 = 0; s2 < 8; s2++) {
        uint4 af[4];
#pragma unroll
        for (int mf = 0; mf < 4; mf++)
            af[mf] = A2P[(s2 * 8 + mi0 + mf) * 32 + lane];
#pragma unroll
        for (int nf = 0; nf < 4; nf++) {
            int nn = nn0 + nf * 8;
            uint2 bf = *(const uint2*)(T1u + nn * 66 + s2 * 8 + tig * 2);
#pragma unroll
            for (int mf = 0; mf < 4; mf++)
                mma_f16(acc[mf][nf], (const unsigned*)&af[mf], (const unsigned*)&bf);
        }
    }
    __syncthreads();

    // ================= final epilogue =================
    if (MODE == 1) {
        float p[4][2];
#pragma unroll
        for (int nf = 0; nf < 4; nf++) { p[nf][0] = 0.f; p[nf][1] = 0.f; }
#pragma unroll
        for (int mf = 0; mf < 4; mf++) {
            int a0 = mb + mf * 16 + g, a1 = a0 + 8;
            float w0 = wbuf[a0], q0 = qbuf[a0];
            float w1 = wbuf[a1], q1 = qbuf[a1];
#pragma unroll
            for (int nf = 0; nf < 4; nf++) {
                p[nf][0] += w0 * ftanh(q0 + acc[mf][nf][0]) + w1 * ftanh(q1 + acc[mf][nf][2]);
                p[nf][1] += w0 * ftanh(q0 + acc[mf][nf][1]) + w1 * ftanh(q1 + acc[mf][nf][3]);
            }
        }
#pragma unroll
        for (int nf = 0; nf < 4; nf++)
#pragma unroll
            for (int q = 0; q < 2; q++) {
                p[nf][q] += __shfl_xor_sync(0xffffffffu, p[nf][q], 4);
                p[nf][q] += __shfl_xor_sync(0xffffffffu, p[nf][q], 8);
                p[nf][q] += __shfl_xor_sync(0xffffffffu, p[nf][q], 16);
            }
        if (g == 0) {
#pragma unroll
            for (int nf = 0; nf < 4; nf++) {
                int n = nb + nf * 8 + tig * 2;
                redm[n * 2 + wm]       = p[nf][0];
                redm[(n + 1) * 2 + wm] = p[nf][1];
            }
        }
        __syncthreads();
        if (tid < 128)
            g_logits[b * Nn + n0 + tid] = redm[tid * 2] + redm[tid * 2 + 1];
    } else {
        // store qfeatproj fp32 [a][t]
#pragma unroll
        for (int mf = 0; mf < 4; mf++) {
            int a0 = mb + mf * 16 + g;
#pragma unroll
            for (int nf = 0; nf < 4; nf++) {
                int t = nb + nf * 8 + tig * 2;
                float* p0 = g_qfeatproj + b * (Aa * Tt) + a0 * Tt + t;
                float* p1 = g_qfeatproj + b * (Aa * Tt) + (a0 + 8) * Tt + t;
                *(float2*)p0 = make_float2(acc[mf][nf][0], acc[mf][nf][1]);
                *(float2*)p1 = make_float2(acc[mf][nf][2], acc[mf][nf][3]);
            }
        }
    }
}

// ---------------- k3: imean, ifeatatt, lq, softmax -> att in out ----------------
__global__ void __launch_bounds__(1024) k3_kernel(const float* __restrict__ Wifc,
                                                  const float* __restrict__ Watt,
                                                  float* __restrict__ out)
{
    __shared__ __align__(16) float att_s[NTOT];
    __shared__ float im[128], ia[128], lq[128];
    __shared__ float red[1024];
    __shared__ float r2[32];

    const int tid = threadIdx.x;
    const int b = blockIdx.x;
    const int m = tid & 127, c = tid >> 7;

    {
        float s = 0.f;
#pragma unroll
        for (int j = c * 4; j < c * 4 + 4; j++) s += g_ipart[(b * 32 + j) * 128 + m];
        red[tid] = s;
    }
    __syncthreads();
    if (tid < 128) {
        float t = 0.f;
#pragma unroll
        for (int cc = 0; cc < 8; cc++) t += red[cc * 128 + tid];
        im[tid] = t * (1.f / (float)Nn);
    }
    __syncthreads();
    {
        float t = 0.f;
        const float* wp = Wifc + m * Mm + c * 16;
#pragma unroll
        for (int j = 0; j < 16; j++) t += wp[j] * im[c * 16 + j];
        red[tid] = t;
    }
    __syncthreads();
    if (tid < 128) {
        float t = 0.f;
#pragma unroll
        for (int cc = 0; cc < 8; cc++) t += red[cc * 128 + tid];
        ia[tid] = t;
    }
    __syncthreads();
    {
        float t = 0.f;
        const float* qp = g_qfeatproj + b * (Aa * Tt) + (c * 16) * Tt + m;
#pragma unroll
        for (int j = 0; j < 16; j++)
            t += Watt[c * 16 + j] * ftanh(ia[c * 16 + j] + qp[j * Tt]);
        red[tid] = t;
    }
    __syncthreads();
    if (tid < 128) {
        float t = 0.f;
#pragma unroll
        for (int cc = 0; cc < 8; cc++) t += red[cc * 128 + tid];
        lq[tid] = t;
    }
    __syncthreads();

    float mx = -1e30f;
    for (int j = tid; j < NTOT; j += 1024) {
        float v = (j < Nn) ? g_logits[b * Nn + j] : lq[j - Nn];
        mx = fmaxf(mx, v);
    }
#pragma unroll
    for (int o = 16; o; o >>= 1) mx = fmaxf(mx, __shfl_xor_sync(0xffffffffu, mx, o));
    if ((tid & 31) == 0) r2[tid >> 5] = mx;
    __syncthreads();
    if (tid < 32) {
        float v = r2[tid];
#pragma unroll
        for (int o = 16; o; o >>= 1) v = fmaxf(v, __shfl_xor_sync(0xffffffffu, v, o));
        r2[tid] = v;
    }
    __syncthreads();
    mx = r2[0];
    __syncthreads();

    float sum = 0.f;
    for (int j = tid; j < NTOT; j += 1024) {
        float v = (j < Nn) ? g_logits[b * Nn + j] : lq[j - Nn];
        float e = expf(v - mx);
        att_s[j] = e;
        sum += e;
    }
#pragma unroll
    for (int o = 16; o; o >>= 1) sum += __shfl_xor_sync(0xffffffffu, sum, o);
    if ((tid & 31) == 0) r2[tid >> 5] = sum;
    __syncthreads();
    if (tid < 32) {
        float v = r2[tid];
#pragma unroll
        for (int o = 16; o; o >>= 1) v += __shfl_xor_sync(0xffffffffu, v, o);
        r2[tid] = v;
    }
    __syncthreads();
    float inv = 1.f / r2[0];
    float* att_g = out + Bn * Mm + b * NTOT;
    for (int j = tid; j < NTOT; j += 1024) att_g[j] = att_s[j] * inv;
}

// ---------------- k4: att_feat partials over n-chunks (fp16 joint feat) ----------------
__global__ void __launch_bounds__(256) k4_kernel(const float* __restrict__ out)
{
    __shared__ __align__(16) float att_s[256 + 128];
    const int ch = blockIdx.x;      // 0..15
    const int b  = blockIdx.y;
    const int tid = threadIdx.x;

    const float* att = out + Bn * Mm + b * NTOT;
    att_s[tid] = att[ch * 256 + tid];
    if (ch == 15 && tid < 128) att_s[256 + tid] = att[Nn + tid];
    __syncthreads();

    const int warp = tid >> 5, lane = tid & 31;
    const float4* a4 = (const float4*)att_s;
#pragma unroll 1
    for (int i = 0; i < 16; i++) {
        int m = warp * 16 + i;
        const uint4* row = (const uint4*)(g_inifeat + ((size_t)(b * Mm + m)) * Nn + ch * 256);
        uint4 hv = row[lane];                   // 8 halves: n = ch*256 + lane*8 ..
        const __half2* hp = (const __half2*)&hv;
        float4 a0 = a4[lane * 2], a1 = a4[lane * 2 + 1];
        float2 f0 = __half22float2(hp[0]);
        float2 f1 = __half22float2(hp[1]);
        float2 f2 = __half22float2(hp[2]);
        float2 f3 = __half22float2(hp[3]);
        float s = f0.x * a0.x + f0.y * a0.y + f1.x * a0.z + f1.y * a0.w
                + f2.x * a1.x + f2.y * a1.y + f3.x * a1.z + f3.y * a1.w;
        if (ch == 15) {
            const uint2* qr = (const uint2*)(g_inqfeat + (size_t)(b * Mm + m) * Tt);
            uint2 qv = qr[lane];                // 4 halves: t = lane*4 ..
            const __half2* qp = (const __half2*)&qv;
            float2 q0 = __half22float2(qp[0]);
            float2 q1 = __half22float2(qp[1]);
            float4 aq = a4[64 + lane];
            s += q0.x * aq.x + q0.y * aq.y + q1.x * aq.z + q1.y * aq.w;
        }
#pragma unroll
        for (int o = 16; o; o >>= 1) s += __shfl_down_sync(0xffffffffu, s, o);
        if (lane == 0) g_afpart[(b * 16 + ch) * 128 + m] = s;
    }
}

// ---------------- k5: reduce partials ----------------
__global__ void __launch_bounds__(128) k5_kernel(float* __restrict__ out)
{
    const int b = blockIdx.x, m = threadIdx.x;
    float s = 0.f;
#pragma unroll
    for (int ch = 0; ch < 16; ch++) s += g_afpart[(b * 16 + ch) * 128 + m];
    out[b * Mm + m] = s;
}

// ---------------- launch ----------------
extern "C" void kernel_launch(void* const* d_in, const int* in_sizes, int n_in,
                              void* d_out, int out_size)
{
    (void)in_sizes; (void)n_in; (void)out_size;
    const float* img  = (const float*)d_in[0];
    const float* text = (const float*)d_in[1];
    const float* Wimg = (const float*)d_in[2];
    const float* Wtxt = (const float*)d_in[3];
    const float* Wqfc = (const float*)d_in[4];
    const float* Wifc = (const float*)d_in[5];
    const float* Wipc = (const float*)d_in[6];
    const float* Wqpc = (const float*)d_in[7];
    const float* Watt = (const float*)d_in[8];
    float* out = (float*)d_out;

    __half* inq = nullptr; cudaGetSymbolAddress((void**)&inq, g_inqfeat);
    __half* inf = nullptr; cudaGetSymbolAddress((void**)&inf, g_inifeat);

    cudaFuncSetAttribute(fused_kernel<HIDn, Tt, 0>, cudaFuncAttributeMaxDynamicSharedMemorySize, SB_TOT);
    cudaFuncSetAttribute(fused_kernel<Cc, Nn, 1>,   cudaFuncAttributeMaxDynamicSharedMemorySize, SB_TOT);

    prep_kernel<<<256, 256>>>(Wimg, Wtxt, Wipc, Wqpc);
    fused_kernel<HIDn, Tt, 0><<<Bn, 256, SB_TOT>>>(text, Wqfc, inq);
    fused_kernel<Cc, Nn, 1><<<dim3(32, Bn), 256, SB_TOT>>>(img, Watt, inf);
    k3_kernel<<<Bn, 1024>>>(Wifc, Watt, out);
    k4_kernel<<<dim3(16, Bn), 256>>>(out);
    k5_kernel<<<Bn, 128>>>(out);
}

// round 8
// speedup vs baseline: 2.6062x; 1.0386x over previous
#include <cuda_runtime.h>
#include <cuda_fp16.h>
#include <math.h>
#include <cstdint>

// Problem constants
#define Bn   64
#define Cc   256
#define Nn   4096
#define HIDn 512
#define Tt   128
#define Mm   128
#define Aa   128
#define NTOT 4224   // Nn + Tt

// -------- device scratch (allocation-free: __device__ globals) --------
__device__ __half g_WimgP[Mm * Cc];       // permuted fp16 A, img GEMM1
__device__ __half g_WtxtP[Mm * HIDn];     // permuted fp16 A, text GEMM1
__device__ __half g_WipcP[Aa * Mm];       // permuted fp16 A, img GEMM2
__device__ __half g_WqpcP[Aa * Mm];       // permuted fp16 A, text GEMM2
__device__ __half g_inqfeat[Bn * Mm * Tt];    // 2 MB fp16
__device__ float  g_qfeatproj[Bn * Tt * Aa];  // TRANSPOSED [b][t][a], 4 MB
__device__ float  g_qfeatatt[Bn * Aa];
__device__ __half g_inifeat[33554432];        // [64][128][4096] fp16 = 64 MB
__device__ float  g_ipart[Bn * 32 * Mm];
__device__ float  g_logits[Bn * Nn];
__device__ float  g_afpart[Bn * 16 * Mm];

// fast fp32 tanh for low-volume paths
__device__ __forceinline__ float ftanh(float x) {
    x = fminf(fmaxf(x, -15.f), 15.f);
    float e = __expf(2.f * x);
    return __fdividef(e - 1.f, e + 1.f);
}

// HW tanh on packed fp16 pairs: 1 MUFU per 2 values
__device__ __forceinline__ __half2 h2tanh_hw(__half2 x) {
    __half2 r;
    asm("tanh.approx.f16x2 %0, %1;" : "=r"(*(unsigned*)&r) : "r"(*(unsigned*)&x));
    return r;
}

__device__ __forceinline__ void mma_f16(float d[4], const unsigned* a, const unsigned* b) {
    asm volatile("mma.sync.aligned.m16n8k16.row.col.f32.f16.f16.f32 "
                 "{%0,%1,%2,%3}, {%4,%5,%6,%7}, {%8,%9}, {%0,%1,%2,%3};"
                 : "+f"(d[0]), "+f"(d[1]), "+f"(d[2]), "+f"(d[3])
                 : "r"(a[0]), "r"(a[1]), "r"(a[2]), "r"(a[3]), "r"(b[0]), "r"(b[1]));
}

// legacy permuted A index (m16n8k16): one uint4 per (slice, mi, lane) = full A fragment
__device__ __forceinline__ int permh_idx(int m, int k) {
    int s = k >> 4, kk = k & 15;
    int khalf = kk >> 3, tig = (kk & 7) >> 1, kp = kk & 1;
    int mi = m >> 4, ml = m & 15, h = ml >> 3, g = ml & 7;
    return ((s * 8 + mi) * 32 + g * 4 + tig) * 8 + khalf * 4 + h * 2 + kp;
}

// fragment-major r-position within a group of 8 k-pairs: pair (r, r+4) adjacent
__device__ __forceinline__ int rpos(int r) { return ((r & 3) << 1) + ((r & 7) >> 2); }

// ---------------- prep ----------------
__global__ void prep_kernel(const float* __restrict__ Wimg, const float* __restrict__ Wtxt,
                            const float* __restrict__ Wipc, const float* __restrict__ Wqpc)
{
    int i = blockIdx.x * blockDim.x + threadIdx.x;   // 0..65535
    { int m = i >> 9, k = i & 511; g_WtxtP[permh_idx(m, k)] = __float2half(Wtxt[i]); }
    if (i < Mm * Cc) { int m = i >> 8, k = i & 255; g_WimgP[permh_idx(m, k)] = __float2half(Wimg[i]); }
    if (i < Aa * Mm) {
        int a = i >> 7, k = i & 127;
        g_WipcP[permh_idx(a, k)] = __float2half(Wipc[i]);
        g_WqpcP[permh_idx(a, k)] = __float2half(Wqpc[i]);
    }
}

// ---------------- fused dual-GEMM kernel (text MODE=0, img MODE=1) ----------------
#define SB_B0  0
#define SB_B1  5120
#define SB_T1  10240
#define SB_RED 44032    // 640 floats
#define SB_Q   46592    // 128 floats
#define SB_W   47104    // 128 floats
#define SB_TOT 47616

template<int K1, int LDB, int MODE>
__global__ void __launch_bounds__(256, 2) fused_kernel(
    const float* __restrict__ Bsrc,   // img_feat or text_feat
    const float* __restrict__ Wx,     // Watt (img) / Wqfc (text)
    __half* __restrict__ out1)        // g_inifeat / g_inqfeat (fp16)
{
    extern __shared__ char smc[];
    __half2* T1  = (__half2*)(smc + SB_T1);
    float* redm = (float*)(smc + SB_RED);
    float* qbuf = (float*)(smc + SB_Q);
    float* wbuf = (float*)(smc + SB_W);

    const int tid  = threadIdx.x;
    const int lane = tid & 31;
    const int w    = tid >> 5;
    const int g    = lane >> 2;
    const int tig  = lane & 3;
    const int wm   = w >> 2;          // 0..1
    const int wn   = w & 3;           // 0..3
    const int mb   = wm * 64;
    const int nb   = wn * 32;

    const int b  = (MODE == 1) ? blockIdx.y : blockIdx.x;
    const int nt = (MODE == 1) ? blockIdx.x : 0;
    const int n0 = nt * 128;

    const uint4* A1P = (const uint4*)((MODE == 1) ? g_WimgP : g_WtxtP);
    const uint4* A2P = (const uint4*)((MODE == 1) ? g_WipcP : g_WqpcP);
    const float* Bb0 = Bsrc + (size_t)b * K1 * LDB + n0;

    if (MODE == 1 && tid < 128) {
        qbuf[tid] = g_qfeatatt[b * Aa + tid];
        wbuf[tid] = Wx[tid];
    }

    // B producer coords
    const int kk2  = tid & 7;
    const int nq   = (tid >> 3) * 4;
    const int poff = rpos(kk2);
    const int mi0  = wm * 4;
    const int nn0  = nb + g;

    float acc[4][4][4];
#pragma unroll
    for (int i = 0; i < 4; i++)
#pragma unroll
        for (int j = 0; j < 4; j++)
#pragma unroll
            for (int q = 0; q < 4; q++) acc[i][j][q] = 0.f;

    // ================= GEMM1 (single sync per slice, 2-buffer rotation) =================
    const int NS1 = K1 / 16;
    float4 bx0, bx1;
    {
        const float* bp = Bb0 + (size_t)(2 * kk2) * LDB + nq;
        bx0 = *(const float4*)bp;
        bx1 = *(const float4*)(bp + LDB);
    }

    for (int s = 0; s < NS1; s++) {
        __half2* Bb = (__half2*)(smc + ((s & 1) ? SB_B1 : SB_B0));
        Bb[(nq + 0) * 10 + poff] = __floats2half2_rn(bx0.x, bx1.x);
        Bb[(nq + 1) * 10 + poff] = __floats2half2_rn(bx0.y, bx1.y);
        Bb[(nq + 2) * 10 + poff] = __floats2half2_rn(bx0.z, bx1.z);
        Bb[(nq + 3) * 10 + poff] = __floats2half2_rn(bx0.w, bx1.w);
        __syncthreads();
        if (s + 1 < NS1) {
            const float* bp = Bb0 + (size_t)((s + 1) * 16 + 2 * kk2) * LDB + nq;
            bx0 = *(const float4*)bp;
            bx1 = *(const float4*)(bp + LDB);
        }
        uint4 af[4];
#pragma unroll
        for (int mf = 0; mf < 4; mf++)
            af[mf] = A1P[(s * 8 + mi0 + mf) * 32 + lane];
        const unsigned* Bu = (const unsigned*)Bb;
#pragma unroll
        for (int nf = 0; nf < 4; nf++) {
            int nn = nn0 + nf * 8;
            uint2 bf = *(const uint2*)(Bu + nn * 10 + tig * 2);
#pragma unroll
            for (int mf = 0; mf < 4; mf++)
                mma_f16(acc[mf][nf], (const unsigned*)&af[mf], (const unsigned*)&bf);
        }
    }
    __syncthreads();

    // ============ mid-epilogue: f16x2 tanh, store out1 fp16 + T1 fp16, row sums ============
    float rp[8];
#pragma unroll
    for (int q = 0; q < 8; q++) rp[q] = 0.f;

#pragma unroll
    for (int mf = 0; mf < 4; mf++) {
        int m0 = mb + mf * 16 + g;
        int kp0 = m0 >> 1;            // even g: pair (m0, m0+1)
        int kp1 = (m0 + 7) >> 1;      // odd g: pair (m0+7, m0+8)
        int o0 = ((kp0 >> 3) << 3) + rpos(kp0);
        int o1 = ((kp1 >> 3) << 3) + rpos(kp1);
#pragma unroll
        for (int nf = 0; nf < 4; nf++) {
            int nl = nb + nf * 8 + tig * 2;
            __half2 h01 = h2tanh_hw(__floats2half2_rn(acc[mf][nf][0], acc[mf][nf][1]));
            __half2 h23 = h2tanh_hw(__floats2half2_rn(acc[mf][nf][2], acc[mf][nf][3]));
            __half* gr0 = out1 + ((size_t)(b * Mm + m0)) * LDB + n0 + nl;
            __half* gr1 = out1 + ((size_t)(b * Mm + m0 + 8)) * LDB + n0 + nl;
            *(__half2*)gr0 = h01;
            *(__half2*)gr1 = h23;
            float2 f01 = __half22float2(h01);
            float2 f23 = __half22float2(h23);
            unsigned u01 = __shfl_xor_sync(0xffffffffu, *(unsigned*)&h01, 4);
            unsigned u23 = __shfl_xor_sync(0xffffffffu, *(unsigned*)&h23, 4);
            __half2 p01 = *(__half2*)&u01;
            __half2 p23 = *(__half2*)&u23;
            if ((g & 1) == 0) {
                __half2 c0 = __lows2half2(h01, p01);
                __half2 c1 = __highs2half2(h01, p01);
                T1[nl * 66 + o0]       = c0;
                T1[(nl + 1) * 66 + o0] = c1;
            } else {
                __half2 c0 = __lows2half2(p23, h23);
                __half2 c1 = __highs2half2(p23, h23);
                T1[nl * 66 + o1]       = c0;
                T1[(nl + 1) * 66 + o1] = c1;
            }
            rp[mf * 2]     += f01.x + f01.y;
            rp[mf * 2 + 1] += f23.x + f23.y;
        }
    }
#pragma unroll
    for (int q = 0; q < 8; q++) {
        rp[q] += __shfl_xor_sync(0xffffffffu, rp[q], 1);
        rp[q] += __shfl_xor_sync(0xffffffffu, rp[q], 2);
    }
    if (tig == 0) {
#pragma unroll
        for (int mf = 0; mf < 4; mf++) {
            redm[(mb + mf * 16 + g) * 5 + wn]     = rp[mf * 2];
            redm[(mb + mf * 16 + g + 8) * 5 + wn] = rp[mf * 2 + 1];
        }
    }
    __syncthreads();
    if (tid < 128) {
        float s = redm[tid * 5] + redm[tid * 5 + 1] + redm[tid * 5 + 2] + redm[tid * 5 + 3];
        if (MODE == 1) g_ipart[(b * 32 + nt) * 128 + tid] = s;
        else           qbuf[tid] = s * (1.f / (float)Tt);
    }
    __syncthreads();
    if (MODE == 0 && tid < 128) {  // qfeatatt[a] = Wqfc[a,:] . qmean
        float s = 0.f;
        const float* wp = Wx + tid * Mm;
#pragma unroll 8
        for (int m = 0; m < Mm; m++) s += wp[m] * qbuf[m];
        g_qfeatatt[b * Aa + tid] = s;
    }

    // ================= GEMM2 (K=128): A global (L2-hot), B = T1, sync-free =================
#pragma unroll
    for (int i = 0; i < 4; i++)
#pragma unroll
        for (int j = 0; j < 4; j++)
#pragma unroll
            for (int q = 0; q < 4; q++) acc[i][j][q] = 0.f;

    const unsigned* T1u = (const unsigned*)T1;
    for (int s2 = 0; s2 < 8; s2++) {
        uint4 af[4];
#pragma unroll
        for (int mf = 0; mf < 4; mf++)
            af[mf] = A2P[(s2 * 8 + mi0 + mf) * 32 + lane];
#pragma unroll
        for (int nf = 0; nf < 4; nf++) {
            int nn = nn0 + nf * 8;
            uint2 bf = *(const uint2*)(T1u + nn * 66 + s2 * 8 + tig * 2);
#pragma unroll
            for (int mf = 0; mf < 4; mf++)
                mma_f16(acc[mf][nf], (const unsigned*)&af[mf], (const unsigned*)&bf);
        }
    }
    __syncthreads();

    // ================= final epilogue =================
    if (MODE == 1) {
        float p[4][2];
#pragma unroll
        for (int nf = 0; nf < 4; nf++) { p[nf][0] = 0.f; p[nf][1] = 0.f; }
#pragma unroll
        for (int mf = 0; mf < 4; mf++) {
            int a0 = mb + mf * 16 + g, a1 = a0 + 8;
            float w0 = wbuf[a0], q0 = qbuf[a0];
            float w1 = wbuf[a1], q1 = qbuf[a1];
#pragma unroll
            for (int nf = 0; nf < 4; nf++) {
                __half2 t0 = h2tanh_hw(__floats2half2_rn(q0 + acc[mf][nf][0], q0 + acc[mf][nf][1]));
                __half2 t1 = h2tanh_hw(__floats2half2_rn(q1 + acc[mf][nf][2], q1 + acc[mf][nf][3]));
                float2 f0 = __half22float2(t0);
                float2 f1 = __half22float2(t1);
                p[nf][0] += w0 * f0.x + w1 * f1.x;
                p[nf][1] += w0 * f0.y + w1 * f1.y;
            }
        }
#pragma unroll
        for (int nf = 0; nf < 4; nf++)
#pragma unroll
            for (int q = 0; q < 2; q++) {
                p[nf][q] += __shfl_xor_sync(0xffffffffu, p[nf][q], 4);
                p[nf][q] += __shfl_xor_sync(0xffffffffu, p[nf][q], 8);
                p[nf][q] += __shfl_xor_sync(0xffffffffu, p[nf][q], 16);
            }
        if (g == 0) {
#pragma unroll
            for (int nf = 0; nf < 4; nf++) {
                int n = nb + nf * 8 + tig * 2;
                redm[n * 2 + wm]       = p[nf][0];
                redm[(n + 1) * 2 + wm] = p[nf][1];
            }
        }
        __syncthreads();
        if (tid < 128)
            g_logits[b * Nn + n0 + tid] = redm[tid * 2] + redm[tid * 2 + 1];
    } else {
        // store qfeatproj TRANSPOSED fp32 [t][a]
        float* qT = g_qfeatproj + b * (Tt * Aa);
#pragma unroll
        for (int mf = 0; mf < 4; mf++) {
            int a0 = mb + mf * 16 + g;
#pragma unroll
            for (int nf = 0; nf < 4; nf++) {
                int t = nb + nf * 8 + tig * 2;
                qT[t * Aa + a0]           = acc[mf][nf][0];
                qT[(t + 1) * Aa + a0]     = acc[mf][nf][1];
                qT[t * Aa + a0 + 8]       = acc[mf][nf][2];
                qT[(t + 1) * Aa + a0 + 8] = acc[mf][nf][3];
            }
        }
    }
}

// ---------------- k3: imean, ifeatatt, lq, softmax -> att in out ----------------
__global__ void __launch_bounds__(1024) k3_kernel(const float* __restrict__ Wifc,
                                                  const float* __restrict__ Watt,
                                                  float* __restrict__ out)
{
    __shared__ __align__(16) float att_s[NTOT];
    __shared__ float im[128], ia[128], lq[128];
    __shared__ float red[1024];
    __shared__ float r2[32];

    const int tid = threadIdx.x;
    const int b = blockIdx.x;
    const int m = tid & 127, c = tid >> 7;

    {
        float s = 0.f;
#pragma unroll
        for (int j = c * 4; j < c * 4 + 4; j++) s += g_ipart[(b * 32 + j) * 128 + m];
        red[tid] = s;
    }
    __syncthreads();
    if (tid < 128) {
        float t = 0.f;
#pragma unroll
        for (int cc = 0; cc < 8; cc++) t += red[cc * 128 + tid];
        im[tid] = t * (1.f / (float)Nn);
    }
    __syncthreads();
    {
        float t = 0.f;
        const float* wp = Wifc + m * Mm + c * 16;
#pragma unroll
        for (int j = 0; j < 16; j++) t += wp[j] * im[c * 16 + j];
        red[tid] = t;
    }
    __syncthreads();
    if (tid < 128) {
        float t = 0.f;
#pragma unroll
        for (int cc = 0; cc < 8; cc++) t += red[cc * 128 + tid];
        ia[tid] = t;
    }
    __syncthreads();
    {
        // lq partial: transposed qfeatproj -> contiguous 16 floats per thread
        float t = 0.f;
        const float4* qp = (const float4*)(g_qfeatproj + b * (Tt * Aa) + m * Aa + c * 16);
#pragma unroll
        for (int j4 = 0; j4 < 4; j4++) {
            float4 v = qp[j4];
            int j = c * 16 + j4 * 4;
            t += Watt[j]     * ftanh(ia[j]     + v.x);
            t += Watt[j + 1] * ftanh(ia[j + 1] + v.y);
            t += Watt[j + 2] * ftanh(ia[j + 2] + v.z);
            t += Watt[j + 3] * ftanh(ia[j + 3] + v.w);
        }
        red[tid] = t;
    }
    __syncthreads();
    if (tid < 128) {
        float t = 0.f;
#pragma unroll
        for (int cc = 0; cc < 8; cc++) t += red[cc * 128 + tid];
        lq[tid] = t;
    }
    __syncthreads();

    float mx = -1e30f;
    for (int j = tid; j < NTOT; j += 1024) {
        float v = (j < Nn) ? g_logits[b * Nn + j] : lq[j - Nn];
        mx = fmaxf(mx, v);
    }
#pragma unroll
    for (int o = 16; o; o >>= 1) mx = fmaxf(mx, __shfl_xor_sync(0xffffffffu, mx, o));
    if ((tid & 31) == 0) r2[tid >> 5] = mx;
    __syncthreads();
    if (tid < 32) {
        float v = r2[tid];
#pragma unroll
        for (int o = 16; o; o >>= 1) v = fmaxf(v, __shfl_xor_sync(0xffffffffu, v, o));
        r2[tid] = v;
    }
    __syncthreads();
    mx = r2[0];
    __syncthreads();

    float sum = 0.f;
    for (int j = tid; j < NTOT; j += 1024) {
        float v = (j < Nn) ? g_logits[b * Nn + j] : lq[j - Nn];
        float e = expf(v - mx);
        att_s[j] = e;
        sum += e;
    }
#pragma unroll
    for (int o = 16; o; o >>= 1) sum += __shfl_xor_sync(0xffffffffu, sum, o);
    if ((tid & 31) == 0) r2[tid >> 5] = sum;
    __syncthreads();
    if (tid < 32) {
        float v = r2[tid];
#pragma unroll
        for (int o = 16; o; o >>= 1) v += __shfl_xor_sync(0xffffffffu, v, o);
        r2[tid] = v;
    }
    __syncthreads();
    float inv = 1.f / r2[0];
    float* att_g = out + Bn * Mm + b * NTOT;
    for (int j = tid; j < NTOT; j += 1024) att_g[j] = att_s[j] * inv;
}

// ---------------- k4: att_feat partials over n-chunks (fp16 joint feat) ----------------
__global__ void __launch_bounds__(256) k4_kernel(const float* __restrict__ out)
{
    __shared__ __align__(16) float att_s[256 + 128];
    const int ch = blockIdx.x;      // 0..15
    const int b  = blockIdx.y;
    const int tid = threadIdx.x;

    const float* att = out + Bn * Mm + b * NTOT;
    att_s[tid] = att[ch * 256 + tid];
    if (ch == 15 && tid < 128) att_s[256 + tid] = att[Nn + tid];
    __syncthreads();

    const int warp = tid >> 5, lane = tid & 31;
    const float4* a4 = (const float4*)att_s;
#pragma unroll 1
    for (int i = 0; i < 16; i++) {
        int m = warp * 16 + i;
        const uint4* row = (const uint4*)(g_inifeat + ((size_t)(b * Mm + m)) * Nn + ch * 256);
        uint4 hv = row[lane];
        const __half2* hp = (const __half2*)&hv;
        float4 a0 = a4[lane * 2], a1 = a4[lane * 2 + 1];
        float2 f0 = __half22float2(hp[0]);
        float2 f1 = __half22float2(hp[1]);
        float2 f2 = __half22float2(hp[2]);
        float2 f3 = __half22float2(hp[3]);
        float s = f0.x * a0.x + f0.y * a0.y + f1.x * a0.z + f1.y * a0.w
                + f2.x * a1.x + f2.y * a1.y + f3.x * a1.z + f3.y * a1.w;
        if (ch == 15) {
            const uint2* qr = (const uint2*)(g_inqfeat + (size_t)(b * Mm + m) * Tt);
            uint2 qv = qr[lane];
            const __half2* qp = (const __half2*)&qv;
            float2 q0 = __half22float2(qp[0]);
            float2 q1 = __half22float2(qp[1]);
            float4 aq = a4[64 + lane];
            s += q0.x * aq.x + q0.y * aq.y + q1.x * aq.z + q1.y * aq.w;
        }
#pragma unroll
        for (int o = 16; o; o >>= 1) s += __shfl_down_sync(0xffffffffu, s, o);
        if (lane == 0) g_afpart[(b * 16 + ch) * 128 + m] = s;
    }
}

// ---------------- k5: reduce partials ----------------
__global__ void __launch_bounds__(128) k5_kernel(float* __restrict__ out)
{
    const int b = blockIdx.x, m = threadIdx.x;
    float s = 0.f;
#pragma unroll
    for (int ch = 0; ch < 16; ch++) s += g_afpart[(b * 16 + ch) * 128 + m];
    out[b * Mm + m] = s;
}

// ---------------- launch ----------------
extern "C" void kernel_launch(void* const* d_in, const int* in_sizes, int n_in,
                              void* d_out, int out_size)
{
    (void)in_sizes; (void)n_in; (void)out_size;
    const float* img  = (const float*)d_in[0];
    const float* text = (const float*)d_in[1];
    const float* Wimg = (const float*)d_in[2];
    const float* Wtxt = (const float*)d_in[3];
    const float* Wqfc = (const float*)d_in[4];
    const float* Wifc = (const float*)d_in[5];
    const float* Wipc = (const float*)d_in[6];
    const float* Wqpc = (const float*)d_in[7];
    const float* Watt = (const float*)d_in[8];
    float* out = (float*)d_out;

    __half* inq = nullptr; cudaGetSymbolAddress((void**)&inq, g_inqfeat);
    __half* inf = nullptr; cudaGetSymbolAddress((void**)&inf, g_inifeat);

    cudaFuncSetAttribute(fused_kernel<HIDn, Tt, 0>, cudaFuncAttributeMaxDynamicSharedMemorySize, SB_TOT);
    cudaFuncSetAttribute(fused_kernel<Cc, Nn, 1>,   cudaFuncAttributeMaxDynamicSharedMemorySize, SB_TOT);

    prep_kernel<<<256, 256>>>(Wimg, Wtxt, Wipc, Wqpc);
    fused_kernel<HIDn, Tt, 0><<<Bn, 256, SB_TOT>>>(text, Wqfc, inq);
    fused_kernel<Cc, Nn, 1><<<dim3(32, Bn), 256, SB_TOT>>>(img, Watt, inf);
    k3_kernel<<<Bn, 1024>>>(Wifc, Watt, out);
    k4_kernel<<<dim3(16, Bn), 256>>>(out);
    k5_kernel<<<Bn, 128>>>(out);
}

// round 9
// speedup vs baseline: 2.7480x; 1.0544x over previous
#include <cuda_runtime.h>
#include <cuda_fp16.h>
#include <math.h>
#include <cstdint>

// Problem constants
#define Bn   64
#define Cc   256
#define Nn   4096
#define HIDn 512
#define Tt   128
#define Mm   128
#define Aa   128
#define NTOT 4224   // Nn + Tt

// -------- device scratch (allocation-free: __device__ globals) --------
__device__ __half g_WimgP[Mm * Cc];       // permuted fp16 A, img GEMM1
__device__ __half g_WtxtP[Mm * HIDn];     // permuted fp16 A, text GEMM1
__device__ __half g_WipcP[Aa * Mm];       // permuted fp16 A, img GEMM2
__device__ __half g_WqpcP[Aa * Mm];       // permuted fp16 A, text GEMM2
__device__ __half g_inqfeat[Bn * Mm * Tt];    // 2 MB fp16
__device__ float  g_qfeatproj[Bn * Tt * Aa];  // TRANSPOSED [b][t][a], 4 MB
__device__ float  g_qfeatatt[Bn * Aa];
__device__ __half g_inifeat[33554432];        // [64][128][4096] fp16 = 64 MB
__device__ float  g_ipart[Bn * 32 * Mm];
__device__ float  g_logits[Bn * Nn];
__device__ float  g_afpart[Bn * 16 * Mm];

// fast fp32 tanh for low-volume paths
__device__ __forceinline__ float ftanh(float x) {
    x = fminf(fmaxf(x, -15.f), 15.f);
    float e = __expf(2.f * x);
    return __fdividef(e - 1.f, e + 1.f);
}

// HW tanh on packed fp16 pairs: 1 MUFU per 2 values
__device__ __forceinline__ __half2 h2tanh_hw(__half2 x) {
    __half2 r;
    asm("tanh.approx.f16x2 %0, %1;" : "=r"(*(unsigned*)&r) : "r"(*(unsigned*)&x));
    return r;
}

__device__ __forceinline__ void mma_f16(float d[4], const unsigned* a, const unsigned* b) {
    asm volatile("mma.sync.aligned.m16n8k16.row.col.f32.f16.f16.f32 "
                 "{%0,%1,%2,%3}, {%4,%5,%6,%7}, {%8,%9}, {%0,%1,%2,%3};"
                 : "+f"(d[0]), "+f"(d[1]), "+f"(d[2]), "+f"(d[3])
                 : "r"(a[0]), "r"(a[1]), "r"(a[2]), "r"(a[3]), "r"(b[0]), "r"(b[1]));
}

// legacy permuted A index (m16n8k16): one uint4 per (slice, mi, lane) = full A fragment
__device__ __forceinline__ int permh_idx(int m, int k) {
    int s = k >> 4, kk = k & 15;
    int khalf = kk >> 3, tig = (kk & 7) >> 1, kp = kk & 1;
    int mi = m >> 4, ml = m & 15, h = ml >> 3, g = ml & 7;
    return ((s * 8 + mi) * 32 + g * 4 + tig) * 8 + khalf * 4 + h * 2 + kp;
}

// fragment-major r-position within a group of 8 k-pairs: pair (r, r+4) adjacent
__device__ __forceinline__ int rpos(int r) { return ((r & 3) << 1) + ((r & 7) >> 2); }

// ---------------- prep (split in two so img is the 4th launch -> gets profiled) ----------------
__global__ void prep_a_kernel(const float* __restrict__ Wtxt)
{
    int i = blockIdx.x * blockDim.x + threadIdx.x;   // 0..65535
    int m = i >> 9, k = i & 511;
    g_WtxtP[permh_idx(m, k)] = __float2half(Wtxt[i]);
}

__global__ void prep_b_kernel(const float* __restrict__ Wimg,
                              const float* __restrict__ Wipc, const float* __restrict__ Wqpc)
{
    int i = blockIdx.x * blockDim.x + threadIdx.x;   // 0..32767
    { int m = i >> 8, k = i & 255; g_WimgP[permh_idx(m, k)] = __float2half(Wimg[i]); }
    if (i < Aa * Mm) {
        int a = i >> 7, k = i & 127;
        g_WipcP[permh_idx(a, k)] = __float2half(Wipc[i]);
        g_WqpcP[permh_idx(a, k)] = __float2half(Wqpc[i]);
    }
}

// ---------------- fused dual-GEMM kernel (text MODE=0, img MODE=1) ----------------
#define SB_B0  0
#define SB_B1  5120
#define SB_T1  10240
#define SB_RED 44032    // 640 floats
#define SB_Q   46592    // 128 floats
#define SB_W   47104    // 128 floats
#define SB_TOT 47616

template<int K1, int LDB, int MODE>
__global__ void __launch_bounds__(256, 2) fused_kernel(
    const float* __restrict__ Bsrc,   // img_feat or text_feat
    const float* __restrict__ Wx,     // Watt (img) / Wqfc (text)
    __half* __restrict__ out1)        // g_inifeat / g_inqfeat (fp16)
{
    extern __shared__ char smc[];
    __half2* T1  = (__half2*)(smc + SB_T1);
    float* redm = (float*)(smc + SB_RED);
    float* qbuf = (float*)(smc + SB_Q);
    float* wbuf = (float*)(smc + SB_W);

    const int tid  = threadIdx.x;
    const int lane = tid & 31;
    const int w    = tid >> 5;
    const int g    = lane >> 2;
    const int tig  = lane & 3;
    const int wm   = w >> 2;          // 0..1
    const int wn   = w & 3;           // 0..3
    const int mb   = wm * 64;
    const int nb   = wn * 32;

    const int b  = (MODE == 1) ? blockIdx.y : blockIdx.x;
    const int nt = (MODE == 1) ? blockIdx.x : 0;
    const int n0 = nt * 128;

    const uint4* A1P = (const uint4*)((MODE == 1) ? g_WimgP : g_WtxtP);
    const uint4* A2P = (const uint4*)((MODE == 1) ? g_WipcP : g_WqpcP);
    const float* Bb0 = Bsrc + (size_t)b * K1 * LDB + n0;

    if (MODE == 1 && tid < 128) {
        qbuf[tid] = g_qfeatatt[b * Aa + tid];
        wbuf[tid] = Wx[tid];
    }

    // B producer coords
    const int kk2  = tid & 7;
    const int nq   = (tid >> 3) * 4;
    const int poff = rpos(kk2);
    const int mi0  = wm * 4;
    const int nn0  = nb + g;

    float acc[4][4][4];
#pragma unroll
    for (int i = 0; i < 4; i++)
#pragma unroll
        for (int j = 0; j < 4; j++)
#pragma unroll
            for (int q = 0; q < 4; q++) acc[i][j][q] = 0.f;

    // ================= GEMM1 (single sync per slice, depth-2 B prefetch) =================
    const int NS1 = K1 / 16;
    float4 pf[2][2];
    {
        const float* bp0 = Bb0 + (size_t)(2 * kk2) * LDB + nq;
        pf[0][0] = *(const float4*)bp0;
        pf[0][1] = *(const float4*)(bp0 + LDB);
        const float* bp1 = Bb0 + (size_t)(16 + 2 * kk2) * LDB + nq;
        pf[1][0] = *(const float4*)bp1;
        pf[1][1] = *(const float4*)(bp1 + LDB);
    }

#pragma unroll 2
    for (int s = 0; s < NS1; s++) {
        __half2* Bb = (__half2*)(smc + ((s & 1) ? SB_B1 : SB_B0));
        float4 bx0 = pf[s & 1][0];
        float4 bx1 = pf[s & 1][1];
        Bb[(nq + 0) * 10 + poff] = __floats2half2_rn(bx0.x, bx1.x);
        Bb[(nq + 1) * 10 + poff] = __floats2half2_rn(bx0.y, bx1.y);
        Bb[(nq + 2) * 10 + poff] = __floats2half2_rn(bx0.z, bx1.z);
        Bb[(nq + 3) * 10 + poff] = __floats2half2_rn(bx0.w, bx1.w);
        __syncthreads();
        if (s + 2 < NS1) {
            const float* bp = Bb0 + (size_t)((s + 2) * 16 + 2 * kk2) * LDB + nq;
            pf[s & 1][0] = *(const float4*)bp;
            pf[s & 1][1] = *(const float4*)(bp + LDB);
        }
        uint4 af[4];
#pragma unroll
        for (int mf = 0; mf < 4; mf++)
            af[mf] = A1P[(s * 8 + mi0 + mf) * 32 + lane];
        const unsigned* Bu = (const unsigned*)Bb;
#pragma unroll
        for (int nf = 0; nf < 4; nf++) {
            int nn = nn0 + nf * 8;
            uint2 bf = *(const uint2*)(Bu + nn * 10 + tig * 2);
#pragma unroll
            for (int mf = 0; mf < 4; mf++)
                mma_f16(acc[mf][nf], (const unsigned*)&af[mf], (const unsigned*)&bf);
        }
    }
    __syncthreads();

    // ============ mid-epilogue: f16x2 tanh, store out1 fp16 + T1 fp16, row sums ============
    float rp[8];
#pragma unroll
    for (int q = 0; q < 8; q++) rp[q] = 0.f;

#pragma unroll
    for (int mf = 0; mf < 4; mf++) {
        int m0 = mb + mf * 16 + g;
        int kp0 = m0 >> 1;            // even g: pair (m0, m0+1)
        int kp1 = (m0 + 7) >> 1;      // odd g: pair (m0+7, m0+8)
        int o0 = ((kp0 >> 3) << 3) + rpos(kp0);
        int o1 = ((kp1 >> 3) << 3) + rpos(kp1);
#pragma unroll
        for (int nf = 0; nf < 4; nf++) {
            int nl = nb + nf * 8 + tig * 2;
            __half2 h01 = h2tanh_hw(__floats2half2_rn(acc[mf][nf][0], acc[mf][nf][1]));
            __half2 h23 = h2tanh_hw(__floats2half2_rn(acc[mf][nf][2], acc[mf][nf][3]));
            __half* gr0 = out1 + ((size_t)(b * Mm + m0)) * LDB + n0 + nl;
            __half* gr1 = out1 + ((size_t)(b * Mm + m0 + 8)) * LDB + n0 + nl;
            *(__half2*)gr0 = h01;
            *(__half2*)gr1 = h23;
            float2 f01 = __half22float2(h01);
            float2 f23 = __half22float2(h23);
            unsigned u01 = __shfl_xor_sync(0xffffffffu, *(unsigned*)&h01, 4);
            unsigned u23 = __shfl_xor_sync(0xffffffffu, *(unsigned*)&h23, 4);
            __half2 p01 = *(__half2*)&u01;
            __half2 p23 = *(__half2*)&u23;
            if ((g & 1) == 0) {
                __half2 c0 = __lows2half2(h01, p01);
                __half2 c1 = __highs2half2(h01, p01);
                T1[nl * 66 + o0]       = c0;
                T1[(nl + 1) * 66 + o0] = c1;
            } else {
                __half2 c0 = __lows2half2(p23, h23);
                __half2 c1 = __highs2half2(p23, h23);
                T1[nl * 66 + o1]       = c0;
                T1[(nl + 1) * 66 + o1] = c1;
            }
            rp[mf * 2]     += f01.x + f01.y;
            rp[mf * 2 + 1] += f23.x + f23.y;
        }
    }
#pragma unroll
    for (int q = 0; q < 8; q++) {
        rp[q] += __shfl_xor_sync(0xffffffffu, rp[q], 1);
        rp[q] += __shfl_xor_sync(0xffffffffu, rp[q], 2);
    }
    if (tig == 0) {
#pragma unroll
        for (int mf = 0; mf < 4; mf++) {
            redm[(mb + mf * 16 + g) * 5 + wn]     = rp[mf * 2];
            redm[(mb + mf * 16 + g + 8) * 5 + wn] = rp[mf * 2 + 1];
        }
    }
    __syncthreads();
    if (tid < 128) {
        float s = redm[tid * 5] + redm[tid * 5 + 1] + redm[tid * 5 + 2] + redm[tid * 5 + 3];
        if (MODE == 1) g_ipart[(b * 32 + nt) * 128 + tid] = s;
        else           qbuf[tid] = s * (1.f / (float)Tt);
    }
    __syncthreads();
    if (MODE == 0 && tid < 128) {  // qfeatatt[a] = Wqfc[a,:] . qmean
        float s = 0.f;
        const float* wp = Wx + tid * Mm;
#pragma unroll 8
        for (int m = 0; m < Mm; m++) s += wp[m] * qbuf[m];
        g_qfeatatt[b * Aa + tid] = s;
    }

    // ================= GEMM2 (K=128): A global (L1/L2-hot), B = T1, sync-free =================
#pragma unroll
    for (int i = 0; i < 4; i++)
#pragma unroll
        for (int j = 0; j < 4; j++)
#pragma unroll
            for (int q = 0; q < 4; q++) acc[i][j][q] = 0.f;

    const unsigned* T1u = (const unsigned*)T1;
    for (int s2 = 0; s2 < 8; s2++) {
        uint4 af[4];
#pragma unroll
        for (int mf = 0; mf < 4; mf++)
            af[mf] = A2P[(s2 * 8 + mi0 + mf) * 32 + lane];
#pragma unroll
        for (int nf = 0; nf < 4; nf++) {
            int nn = nn0 + nf * 8;
            uint2 bf = *(const uint2*)(T1u + nn * 66 + s2 * 8 + tig * 2);
#pragma unroll
            for (int mf = 0; mf < 4; mf++)
                mma_f16(acc[mf][nf], (const unsigned*)&af[mf], (const unsigned*)&bf);
        }
    }
    __syncthreads();

    // ================= final epilogue =================
    if (MODE == 1) {
        float p[4][2];
#pragma unroll
        for (int nf = 0; nf < 4; nf++) { p[nf][0] = 0.f; p[nf][1] = 0.f; }
#pragma unroll
        for (int mf = 0; mf < 4; mf++) {
            int a0 = mb + mf * 16 + g, a1 = a0 + 8;
            float w0 = wbuf[a0], q0 = qbuf[a0];
            float w1 = wbuf[a1], q1 = qbuf[a1];
#pragma unroll
            for (int nf = 0; nf < 4; nf++) {
                __half2 t0 = h2tanh_hw(__floats2half2_rn(q0 + acc[mf][nf][0], q0 + acc[mf][nf][1]));
                __half2 t1 = h2tanh_hw(__floats2half2_rn(q1 + acc[mf][nf][2], q1 + acc[mf][nf][3]));
                float2 f0 = __half22float2(t0);
                float2 f1 = __half22float2(t1);
                p[nf][0] += w0 * f0.x + w1 * f1.x;
                p[nf][1] += w0 * f0.y + w1 * f1.y;
            }
        }
#pragma unroll
        for (int nf = 0; nf < 4; nf++)
#pragma unroll
            for (int q = 0; q < 2; q++) {
                p[nf][q] += __shfl_xor_sync(0xffffffffu, p[nf][q], 4);
                p[nf][q] += __shfl_xor_sync(0xffffffffu, p[nf][q], 8);
                p[nf][q] += __shfl_xor_sync(0xffffffffu, p[nf][q], 16);
            }
        if (g == 0) {
#pragma unroll
            for (int nf = 0; nf < 4; nf++) {
                int n = nb + nf * 8 + tig * 2;
                redm[n * 2 + wm]       = p[nf][0];
                redm[(n + 1) * 2 + wm] = p[nf][1];
            }
        }
        __syncthreads();
        if (tid < 128)
            g_logits[b * Nn + n0 + tid] = redm[tid * 2] + redm[tid * 2 + 1];
    } else {
        // store qfeatproj TRANSPOSED fp32 [t][a]
        float* qT = g_qfeatproj + b * (Tt * Aa);
#pragma unroll
        for (int mf = 0; mf < 4; mf++) {
            int a0 = mb + mf * 16 + g;
#pragma unroll
            for (int nf = 0; nf < 4; nf++) {
                int t = nb + nf * 8 + tig * 2;
                qT[t * Aa + a0]           = acc[mf][nf][0];
                qT[(t + 1) * Aa + a0]     = acc[mf][nf][1];
                qT[t * Aa + a0 + 8]       = acc[mf][nf][2];
                qT[(t + 1) * Aa + a0 + 8] = acc[mf][nf][3];
            }
        }
    }
}

// ---------------- k3: imean, ifeatatt, lq, softmax -> att in out ----------------
__global__ void __launch_bounds__(1024) k3_kernel(const float* __restrict__ Wifc,
                                                  const float* __restrict__ Watt,
                                                  float* __restrict__ out)
{
    __shared__ __align__(16) float att_s[NTOT];
    __shared__ float im[128], ia[128], lq[128];
    __shared__ float red[1024];
    __shared__ float r2[32];

    const int tid = threadIdx.x;
    const int b = blockIdx.x;
    const int m = tid & 127, c = tid >> 7;

    {
        float s = 0.f;
#pragma unroll
        for (int j = c * 4; j < c * 4 + 4; j++) s += g_ipart[(b * 32 + j) * 128 + m];
        red[tid] = s;
    }
    __syncthreads();
    if (tid < 128) {
        float t = 0.f;
#pragma unroll
        for (int cc = 0; cc < 8; cc++) t += red[cc * 128 + tid];
        im[tid] = t * (1.f / (float)Nn);
    }
    __syncthreads();
    {
        float t = 0.f;
        const float* wp = Wifc + m * Mm + c * 16;
#pragma unroll
        for (int j = 0; j < 16; j++) t += wp[j] * im[c * 16 + j];
        red[tid] = t;
    }
    __syncthreads();
    if (tid < 128) {
        float t = 0.f;
#pragma unroll
        for (int cc = 0; cc < 8; cc++) t += red[cc * 128 + tid];
        ia[tid] = t;
    }
    __syncthreads();
    {
        // lq partial: transposed qfeatproj -> contiguous 16 floats per thread; f16x2 tanh
        float t = 0.f;
        const float4* qp = (const float4*)(g_qfeatproj + b * (Tt * Aa) + m * Aa + c * 16);
#pragma unroll
        for (int j4 = 0; j4 < 4; j4++) {
            float4 v = qp[j4];
            int j = c * 16 + j4 * 4;
            __half2 t0 = h2tanh_hw(__floats2half2_rn(ia[j] + v.x, ia[j + 1] + v.y));
            __half2 t1 = h2tanh_hw(__floats2half2_rn(ia[j + 2] + v.z, ia[j + 3] + v.w));
            float2 f0 = __half22float2(t0);
            float2 f1 = __half22float2(t1);
            t += Watt[j]     * f0.x + Watt[j + 1] * f0.y
               + Watt[j + 2] * f1.x + Watt[j + 3] * f1.y;
        }
        red[tid] = t;
    }
    __syncthreads();
    if (tid < 128) {
        float t = 0.f;
#pragma unroll
        for (int cc = 0; cc < 8; cc++) t += red[cc * 128 + tid];
        lq[tid] = t;
    }
    __syncthreads();

    float mx = -1e30f;
    for (int j = tid; j < NTOT; j += 1024) {
        float v = (j < Nn) ? g_logits[b * Nn + j] : lq[j - Nn];
        mx = fmaxf(mx, v);
    }
#pragma unroll
    for (int o = 16; o; o >>= 1) mx = fmaxf(mx, __shfl_xor_sync(0xffffffffu, mx, o));
    if ((tid & 31) == 0) r2[tid >> 5] = mx;
    __syncthreads();
    if (tid < 32) {
        float v = r2[tid];
#pragma unroll
        for (int o = 16; o; o >>= 1) v = fmaxf(v, __shfl_xor_sync(0xffffffffu, v, o));
        r2[tid] = v;
    }
    __syncthreads();
    mx = r2[0];
    __syncthreads();

    float sum = 0.f;
    for (int j = tid; j < NTOT; j += 1024) {
        float v = (j < Nn) ? g_logits[b * Nn + j] : lq[j - Nn];
        float e = expf(v - mx);
        att_s[j] = e;
        sum += e;
    }
#pragma unroll
    for (int o = 16; o; o >>= 1) sum += __shfl_xor_sync(0xffffffffu, sum, o);
    if ((tid & 31) == 0) r2[tid >> 5] = sum;
    __syncthreads();
    if (tid < 32) {
        float v = r2[tid];
#pragma unroll
        for (int o = 16; o; o >>= 1) v += __shfl_xor_sync(0xffffffffu, v, o);
        r2[tid] = v;
    }
    __syncthreads();
    float inv = 1.f / r2[0];
    float* att_g = out + Bn * Mm + b * NTOT;
    for (int j = tid; j < NTOT; j += 1024) att_g[j] = att_s[j] * inv;
}

// ---------------- k4: att_feat partials over n-chunks (fp16 joint feat) ----------------
__global__ void __launch_bounds__(256) k4_kernel(const float* __restrict__ out)
{
    __shared__ __align__(16) float att_s[256 + 128];
    const int ch = blockIdx.x;      // 0..15
    const int b  = blockIdx.y;
    const int tid = threadIdx.x;

    const float* att = out + Bn * Mm + b * NTOT;
    att_s[tid] = att[ch * 256 + tid];
    if (ch == 15 && tid < 128) att_s[256 + tid] = att[Nn + tid];
    __syncthreads();

    const int warp = tid >> 5, lane = tid & 31;
    const float4* a4 = (const float4*)att_s;
#pragma unroll 1
    for (int i = 0; i < 16; i++) {
        int m = warp * 16 + i;
        const uint4* row = (const uint4*)(g_inifeat + ((size_t)(b * Mm + m)) * Nn + ch * 256);
        uint4 hv = row[lane];
        const __half2* hp = (const __half2*)&hv;
        float4 a0 = a4[lane * 2], a1 = a4[lane * 2 + 1];
        float2 f0 = __half22float2(hp[0]);
        float2 f1 = __half22float2(hp[1]);
        float2 f2 = __half22float2(hp[2]);
        float2 f3 = __half22float2(hp[3]);
        float s = f0.x * a0.x + f0.y * a0.y + f1.x * a0.z + f1.y * a0.w
                + f2.x * a1.x + f2.y * a1.y + f3.x * a1.z + f3.y * a1.w;
        if (ch == 15) {
            const uint2* qr = (const uint2*)(g_inqfeat + (size_t)(b * Mm + m) * Tt);
            uint2 qv = qr[lane];
            const __half2* qp = (const __half2*)&qv;
            float2 q0 = __half22float2(qp[0]);
            float2 q1 = __half22float2(qp[1]);
            float4 aq = a4[64 + lane];
            s += q0.x * aq.x + q0.y * aq.y + q1.x * aq.z + q1.y * aq.w;
        }
#pragma unroll
        for (int o = 16; o; o >>= 1) s += __shfl_down_sync(0xffffffffu, s, o);
        if (lane == 0) g_afpart[(b * 16 + ch) * 128 + m] = s;
    }
}

// ---------------- k5: reduce partials ----------------
__global__ void __launch_bounds__(128) k5_kernel(float* __restrict__ out)
{
    const int b = blockIdx.x, m = threadIdx.x;
    float s = 0.f;
#pragma unroll
    for (int ch = 0; ch < 16; ch++) s += g_afpart[(b * 16 + ch) * 128 + m];
    out[b * Mm + m] = s;
}

// ---------------- launch ----------------
extern "C" void kernel_launch(void* const* d_in, const int* in_sizes, int n_in,
                              void* d_out, int out_size)
{
    (void)in_sizes; (void)n_in; (void)out_size;
    const float* img  = (const float*)d_in[0];
    const float* text = (const float*)d_in[1];
    const float* Wimg = (const float*)d_in[2];
    const float* Wtxt = (const float*)d_in[3];
    const float* Wqfc = (const float*)d_in[4];
    const float* Wifc = (const float*)d_in[5];
    const float* Wipc = (const float*)d_in[6];
    const float* Wqpc = (const float*)d_in[7];
    const float* Watt = (const float*)d_in[8];
    float* out = (float*)d_out;

    __half* inq = nullptr; cudaGetSymbolAddress((void**)&inq, g_inqfeat);
    __half* inf = nullptr; cudaGetSymbolAddress((void**)&inf, g_inifeat);

    cudaFuncSetAttribute(fused_kernel<HIDn, Tt, 0>, cudaFuncAttributeMaxDynamicSharedMemorySize, SB_TOT);
    cudaFuncSetAttribute(fused_kernel<Cc, Nn, 1>,   cudaFuncAttributeMaxDynamicSharedMemorySize, SB_TOT);

    prep_a_kernel<<<256, 256>>>(Wtxt);                                   // 1st
    prep_b_kernel<<<128, 256>>>(Wimg, Wipc, Wqpc);                       // 2nd
    fused_kernel<HIDn, Tt, 0><<<Bn, 256, SB_TOT>>>(text, Wqfc, inq);     // 3rd
    fused_kernel<Cc, Nn, 1><<<dim3(32, Bn), 256, SB_TOT>>>(img, Watt, inf); // 4th (profiled)
    k3_kernel<<<Bn, 1024>>>(Wifc, Watt, out);                            // 5th
    k4_kernel<<<dim3(16, Bn), 256>>>(out);                               // 6th
    k5_kernel<<<Bn, 128>>>(out);                                         // 7th
}

// round 10
// speedup vs baseline: 2.7765x; 1.0104x over previous
#include <cuda_runtime.h>
#include <cuda_fp16.h>
#include <math.h>
#include <cstdint>

// Problem constants
#define Bn   64
#define Cc   256
#define Nn   4096
#define HIDn 512
#define Tt   128
#define Mm   128
#define Aa   128
#define NTOT 4224   // Nn + Tt

// -------- device scratch (allocation-free: __device__ globals) --------
__device__ __half g_WimgP[Mm * Cc];       // permuted fp16 A, img GEMM1
__device__ __half g_WtxtP[Mm * HIDn];     // permuted fp16 A, text GEMM1
__device__ __half g_WipcP[Aa * Mm];       // permuted fp16 A, img GEMM2
__device__ __half g_WqpcP[Aa * Mm];       // permuted fp16 A, text GEMM2
__device__ __half g_inqfeat[Bn * Mm * Tt];    // [b][m][t] fp16, 2 MB
__device__ float  g_qfeatproj[Bn * Tt * Aa];  // TRANSPOSED [b][t][a], 4 MB
__device__ float  g_qfeatatt[Bn * Aa];
__device__ __half g_inifeat[33554432];        // [b][n][mperm] fp16 = 64 MB
__device__ float  g_ipart[Bn * 32 * Mm];
__device__ float  g_logits[Bn * Nn];
__device__ float  g_afpart[Bn * 16 * Mm];

// fast fp32 tanh for low-volume paths
__device__ __forceinline__ float ftanh(float x) {
    x = fminf(fmaxf(x, -15.f), 15.f);
    float e = __expf(2.f * x);
    return __fdividef(e - 1.f, e + 1.f);
}

// HW tanh on packed fp16 pairs: 1 MUFU per 2 values
__device__ __forceinline__ __half2 h2tanh_hw(__half2 x) {
    __half2 r;
    asm("tanh.approx.f16x2 %0, %1;" : "=r"(*(unsigned*)&r) : "r"(*(unsigned*)&x));
    return r;
}

__device__ __forceinline__ void mma_f16(float d[4], const unsigned* a, const unsigned* b) {
    asm volatile("mma.sync.aligned.m16n8k16.row.col.f32.f16.f16.f32 "
                 "{%0,%1,%2,%3}, {%4,%5,%6,%7}, {%8,%9}, {%0,%1,%2,%3};"
                 : "+f"(d[0]), "+f"(d[1]), "+f"(d[2]), "+f"(d[3])
                 : "r"(a[0]), "r"(a[1]), "r"(a[2]), "r"(a[3]), "r"(b[0]), "r"(b[1]));
}

// legacy permuted A index (m16n8k16): one uint4 per (slice, mi, lane) = full A fragment
__device__ __forceinline__ int permh_idx(int m, int k) {
    int s = k >> 4, kk = k & 15;
    int khalf = kk >> 3, tig = (kk & 7) >> 1, kp = kk & 1;
    int mi = m >> 4, ml = m & 15, h = ml >> 3, g = ml & 7;
    return ((s * 8 + mi) * 32 + g * 4 + tig) * 8 + khalf * 4 + h * 2 + kp;
}

// fragment-major r-position within a group of 8 k-pairs: pair (r, r+4) adjacent
__device__ __forceinline__ int rpos(int r) { return ((r & 3) << 1) + ((r & 7) >> 2); }

// ---------------- prep (split so img is the 4th launch -> profiled) ----------------
__global__ void prep_a_kernel(const float* __restrict__ Wtxt)
{
    int i = blockIdx.x * blockDim.x + threadIdx.x;   // 0..65535
    int m = i >> 9, k = i & 511;
    g_WtxtP[permh_idx(m, k)] = __float2half(Wtxt[i]);
}

__global__ void prep_b_kernel(const float* __restrict__ Wimg,
                              const float* __restrict__ Wipc, const float* __restrict__ Wqpc)
{
    int i = blockIdx.x * blockDim.x + threadIdx.x;   // 0..32767
    { int m = i >> 8, k = i & 255; g_WimgP[permh_idx(m, k)] = __float2half(Wimg[i]); }
    if (i < Aa * Mm) {
        int a = i >> 7, k = i & 127;
        g_WipcP[permh_idx(a, k)] = __float2half(Wipc[i]);
        g_WqpcP[permh_idx(a, k)] = __float2half(Wqpc[i]);
    }
}

// ---------------- fused dual-GEMM kernel (text MODE=0, img MODE=1) ----------------
// B bufs: 128 n x 18 half2 (positions 0..7 used; stride 18 -> conflict-free both sides) = 9216 B
// T1: 128 n x 68 half2 (64 used; stride 68 -> conflict-free + 16B-aligned rows) = 34816 B
#define SB_B0  0
#define SB_B1  9216
#define SB_T1  18432
#define SB_RED 53248    // 640 floats
#define SB_Q   55808    // 128 floats
#define SB_W   56320    // 128 floats
#define SB_TOT 56832

template<int K1, int LDB, int MODE>
__global__ void __launch_bounds__(256, 2) fused_kernel(
    const float* __restrict__ Bsrc,   // img_feat or text_feat
    const float* __restrict__ Wx,     // Watt (img) / Wqfc (text)
    __half* __restrict__ out1)        // g_inifeat ([n][mperm]) / g_inqfeat ([m][t])
{
    extern __shared__ char smc[];
    __half2* T1  = (__half2*)(smc + SB_T1);
    float* redm = (float*)(smc + SB_RED);
    float* qbuf = (float*)(smc + SB_Q);
    float* wbuf = (float*)(smc + SB_W);

    const int tid  = threadIdx.x;
    const int lane = tid & 31;
    const int w    = tid >> 5;
    const int g    = lane >> 2;
    const int tig  = lane & 3;
    const int wm   = w >> 2;          // 0..1
    const int wn   = w & 3;           // 0..3
    const int mb   = wm * 64;
    const int nb   = wn * 32;

    const int b  = (MODE == 1) ? blockIdx.y : blockIdx.x;
    const int nt = (MODE == 1) ? blockIdx.x : 0;
    const int n0 = nt * 128;

    const uint4* A1P = (const uint4*)((MODE == 1) ? g_WimgP : g_WtxtP);
    const uint4* A2P = (const uint4*)((MODE == 1) ? g_WipcP : g_WqpcP);
    const float* Bb0 = Bsrc + (size_t)b * K1 * LDB + n0;

    if (MODE == 1 && tid < 128) {
        qbuf[tid] = g_qfeatatt[b * Aa + tid];
        wbuf[tid] = Wx[tid];
    }

    // B producer coords
    const int kk2  = tid & 7;
    const int nq   = (tid >> 3) * 4;
    const int poff = rpos(kk2);
    const int mi0  = wm * 4;
    const int nn0  = nb + g;

    float acc[4][4][4];
#pragma unroll
    for (int i = 0; i < 4; i++)
#pragma unroll
        for (int j = 0; j < 4; j++)
#pragma unroll
            for (int q = 0; q < 4; q++) acc[i][j][q] = 0.f;

    // ================= GEMM1 (single sync per slice, depth-2 B prefetch) =================
    const int NS1 = K1 / 16;
    float4 pf[2][2];
    {
        const float* bp0 = Bb0 + (size_t)(2 * kk2) * LDB + nq;
        pf[0][0] = *(const float4*)bp0;
        pf[0][1] = *(const float4*)(bp0 + LDB);
        const float* bp1 = Bb0 + (size_t)(16 + 2 * kk2) * LDB + nq;
        pf[1][0] = *(const float4*)bp1;
        pf[1][1] = *(const float4*)(bp1 + LDB);
    }

#pragma unroll 2
    for (int s = 0; s < NS1; s++) {
        __half2* Bb = (__half2*)(smc + ((s & 1) ? SB_B1 : SB_B0));
        float4 bx0 = pf[s & 1][0];
        float4 bx1 = pf[s & 1][1];
        Bb[(nq + 0) * 18 + poff] = __floats2half2_rn(bx0.x, bx1.x);
        Bb[(nq + 1) * 18 + poff] = __floats2half2_rn(bx0.y, bx1.y);
        Bb[(nq + 2) * 18 + poff] = __floats2half2_rn(bx0.z, bx1.z);
        Bb[(nq + 3) * 18 + poff] = __floats2half2_rn(bx0.w, bx1.w);
        __syncthreads();
        if (s + 2 < NS1) {
            const float* bp = Bb0 + (size_t)((s + 2) * 16 + 2 * kk2) * LDB + nq;
            pf[s & 1][0] = *(const float4*)bp;
            pf[s & 1][1] = *(const float4*)(bp + LDB);
        }
        uint4 af[4];
#pragma unroll
        for (int mf = 0; mf < 4; mf++)
            af[mf] = A1P[(s * 8 + mi0 + mf) * 32 + lane];
        const unsigned* Bu = (const unsigned*)Bb;
#pragma unroll
        for (int nf = 0; nf < 4; nf++) {
            int nn = nn0 + nf * 8;
            uint2 bf = *(const uint2*)(Bu + nn * 18 + tig * 2);
#pragma unroll
            for (int mf = 0; mf < 4; mf++)
                mma_f16(acc[mf][nf], (const unsigned*)&af[mf], (const unsigned*)&bf);
        }
    }
    __syncthreads();

    // ============ mid-epilogue: f16x2 tanh, T1 fp16 (fragment-major), row sums ============
    float rp[8];
#pragma unroll
    for (int q = 0; q < 8; q++) rp[q] = 0.f;

#pragma unroll
    for (int mf = 0; mf < 4; mf++) {
        int m0 = mb + mf * 16 + g;
        int kp0 = m0 >> 1;            // even g: pair (m0, m0+1)
        int kp1 = (m0 + 7) >> 1;      // odd g: pair (m0+7, m0+8)
        int o0 = ((kp0 >> 3) << 3) + rpos(kp0);
        int o1 = ((kp1 >> 3) << 3) + rpos(kp1);
#pragma unroll
        for (int nf = 0; nf < 4; nf++) {
            int nl = nb + nf * 8 + tig * 2;
            __half2 h01 = h2tanh_hw(__floats2half2_rn(acc[mf][nf][0], acc[mf][nf][1]));
            __half2 h23 = h2tanh_hw(__floats2half2_rn(acc[mf][nf][2], acc[mf][nf][3]));
            if (MODE == 0) {
                __half* gr0 = out1 + ((size_t)(b * Mm + m0)) * LDB + n0 + nl;
                __half* gr1 = out1 + ((size_t)(b * Mm + m0 + 8)) * LDB + n0 + nl;
                *(__half2*)gr0 = h01;
                *(__half2*)gr1 = h23;
            }
            float2 f01 = __half22float2(h01);
            float2 f23 = __half22float2(h23);
            unsigned u01 = __shfl_xor_sync(0xffffffffu, *(unsigned*)&h01, 4);
            unsigned u23 = __shfl_xor_sync(0xffffffffu, *(unsigned*)&h23, 4);
            __half2 p01 = *(__half2*)&u01;
            __half2 p23 = *(__half2*)&u23;
            if ((g & 1) == 0) {
                __half2 c0 = __lows2half2(h01, p01);
                __half2 c1 = __highs2half2(h01, p01);
                T1[nl * 68 + o0]       = c0;
                T1[(nl + 1) * 68 + o0] = c1;
            } else {
                __half2 c0 = __lows2half2(p23, h23);
                __half2 c1 = __highs2half2(p23, h23);
                T1[nl * 68 + o1]       = c0;
                T1[(nl + 1) * 68 + o1] = c1;
            }
            rp[mf * 2]     += f01.x + f01.y;
            rp[mf * 2 + 1] += f23.x + f23.y;
        }
    }
#pragma unroll
    for (int q = 0; q < 8; q++) {
        rp[q] += __shfl_xor_sync(0xffffffffu, rp[q], 1);
        rp[q] += __shfl_xor_sync(0xffffffffu, rp[q], 2);
    }
    if (tig == 0) {
#pragma unroll
        for (int mf = 0; mf < 4; mf++) {
            redm[(mb + mf * 16 + g) * 5 + wn]     = rp[mf * 2];
            redm[(mb + mf * 16 + g + 8) * 5 + wn] = rp[mf * 2 + 1];
        }
    }
    __syncthreads();
    if (tid < 128) {
        float s = redm[tid * 5] + redm[tid * 5 + 1] + redm[tid * 5 + 2] + redm[tid * 5 + 3];
        if (MODE == 1) g_ipart[(b * 32 + nt) * 128 + tid] = s;
        else           qbuf[tid] = s * (1.f / (float)Tt);
    }
    __syncthreads();
    if (MODE == 0 && tid < 128) {  // qfeatatt[a] = Wqfc[a,:] . qmean
        float s = 0.f;
        const float* wp = Wx + tid * Mm;
#pragma unroll 8
        for (int m = 0; m < Mm; m++) s += wp[m] * qbuf[m];
        g_qfeatatt[b * Aa + tid] = s;
    }

    // ================= GEMM2 (K=128): A global (L1/L2-hot), B = T1, sync-free =================
#pragma unroll
    for (int i = 0; i < 4; i++)
#pragma unroll
        for (int j = 0; j < 4; j++)
#pragma unroll
            for (int q = 0; q < 4; q++) acc[i][j][q] = 0.f;

    const unsigned* T1u = (const unsigned*)T1;
    for (int s2 = 0; s2 < 8; s2++) {
        uint4 af[4];
#pragma unroll
        for (int mf = 0; mf < 4; mf++)
            af[mf] = A2P[(s2 * 8 + mi0 + mf) * 32 + lane];
#pragma unroll
        for (int nf = 0; nf < 4; nf++) {
            int nn = nn0 + nf * 8;
            uint2 bf = *(const uint2*)(T1u + nn * 68 + s2 * 8 + tig * 2);
#pragma unroll
            for (int mf = 0; mf < 4; mf++)
                mma_f16(acc[mf][nf], (const unsigned*)&af[mf], (const unsigned*)&bf);
        }
    }
    __syncthreads();

    // ===== coalesced store: T1 -> g_inifeat[b][n][mperm], whole 128B lines per 8 lanes =====
    if (MODE == 1) {
        const char* t1base = smc + SB_T1;
        const int q = tid & 7;
#pragma unroll
        for (int it = 0; it < 4; it++) {
            int row = (tid >> 3) + it * 32;
            const uint4* src = (const uint4*)(t1base + row * 272);   // 272 = 68 half2 * 4B
            uint4 v0 = src[q * 2];
            uint4 v1 = src[q * 2 + 1];
            uint4* dst = (uint4*)(out1 + ((size_t)b * Nn + n0 + row) * 128 + q * 16);
            dst[0] = v0;
            dst[1] = v1;
        }
    }

    // ================= final epilogue =================
    if (MODE == 1) {
        float p[4][2];
#pragma unroll
        for (int nf = 0; nf < 4; nf++) { p[nf][0] = 0.f; p[nf][1] = 0.f; }
#pragma unroll
        for (int mf = 0; mf < 4; mf++) {
            int a0 = mb + mf * 16 + g, a1 = a0 + 8;
            float w0 = wbuf[a0], q0 = qbuf[a0];
            float w1 = wbuf[a1], q1 = qbuf[a1];
#pragma unroll
            for (int nf = 0; nf < 4; nf++) {
                __half2 t0 = h2tanh_hw(__floats2half2_rn(q0 + acc[mf][nf][0], q0 + acc[mf][nf][1]));
                __half2 t1 = h2tanh_hw(__floats2half2_rn(q1 + acc[mf][nf][2], q1 + acc[mf][nf][3]));
                float2 f0 = __half22float2(t0);
                float2 f1 = __half22float2(t1);
                p[nf][0] += w0 * f0.x + w1 * f1.x;
                p[nf][1] += w0 * f0.y + w1 * f1.y;
            }
        }
#pragma unroll
        for (int nf = 0; nf < 4; nf++)
#pragma unroll
            for (int q = 0; q < 2; q++) {
                p[nf][q] += __shfl_xor_sync(0xffffffffu, p[nf][q], 4);
                p[nf][q] += __shfl_xor_sync(0xffffffffu, p[nf][q], 8);
                p[nf][q] += __shfl_xor_sync(0xffffffffu, p[nf][q], 16);
            }
        if (g == 0) {
#pragma unroll
            for (int nf = 0; nf < 4; nf++) {
                int n = nb + nf * 8 + tig * 2;
                redm[n * 2 + wm]       = p[nf][0];
                redm[(n + 1) * 2 + wm] = p[nf][1];
            }
        }
        __syncthreads();
        if (tid < 128)
            g_logits[b * Nn + n0 + tid] = redm[tid * 2] + redm[tid * 2 + 1];
    } else {
        // store qfeatproj TRANSPOSED fp32 [t][a]
        float* qT = g_qfeatproj + b * (Tt * Aa);
#pragma unroll
        for (int mf = 0; mf < 4; mf++) {
            int a0 = mb + mf * 16 + g;
#pragma unroll
            for (int nf = 0; nf < 4; nf++) {
                int t = nb + nf * 8 + tig * 2;
                qT[t * Aa + a0]           = acc[mf][nf][0];
                qT[(t + 1) * Aa + a0]     = acc[mf][nf][1];
                qT[t * Aa + a0 + 8]       = acc[mf][nf][2];
                qT[(t + 1) * Aa + a0 + 8] = acc[mf][nf][3];
            }
        }
    }
}

// ---------------- k3: imean, ifeatatt, lq, softmax -> att in out ----------------
__global__ void __launch_bounds__(1024) k3_kernel(const float* __restrict__ Wifc,
                                                  const float* __restrict__ Watt,
                                                  float* __restrict__ out)
{
    __shared__ __align__(16) float att_s[NTOT];
    __shared__ float im[128], ia[128], lq[128];
    __shared__ float red[1024];
    __shared__ float r2[32];

    const int tid = threadIdx.x;
    const int b = blockIdx.x;
    const int m = tid & 127, c = tid >> 7;

    {
        float s = 0.f;
#pragma unroll
        for (int j = c * 4; j < c * 4 + 4; j++) s += g_ipart[(b * 32 + j) * 128 + m];
        red[tid] = s;
    }
    __syncthreads();
    if (tid < 128) {
        float t = 0.f;
#pragma unroll
        for (int cc = 0; cc < 8; cc++) t += red[cc * 128 + tid];
        im[tid] = t * (1.f / (float)Nn);
    }
    __syncthreads();
    {
        float t = 0.f;
        const float* wp = Wifc + m * Mm + c * 16;
#pragma unroll
        for (int j = 0; j < 16; j++) t += wp[j] * im[c * 16 + j];
        red[tid] = t;
    }
    __syncthreads();
    if (tid < 128) {
        float t = 0.f;
#pragma unroll
        for (int cc = 0; cc < 8; cc++) t += red[cc * 128 + tid];
        ia[tid] = t;
    }
    __syncthreads();
    {
        float t = 0.f;
        const float4* qp = (const float4*)(g_qfeatproj + b * (Tt * Aa) + m * Aa + c * 16);
#pragma unroll
        for (int j4 = 0; j4 < 4; j4++) {
            float4 v = qp[j4];
            int j = c * 16 + j4 * 4;
            __half2 t0 = h2tanh_hw(__floats2half2_rn(ia[j] + v.x, ia[j + 1] + v.y));
            __half2 t1 = h2tanh_hw(__floats2half2_rn(ia[j + 2] + v.z, ia[j + 3] + v.w));
            float2 f0 = __half22float2(t0);
            float2 f1 = __half22float2(t1);
            t += Watt[j]     * f0.x + Watt[j + 1] * f0.y
               + Watt[j + 2] * f1.x + Watt[j + 3] * f1.y;
        }
        red[tid] = t;
    }
    __syncthreads();
    if (tid < 128) {
        float t = 0.f;
#pragma unroll
        for (int cc = 0; cc < 8; cc++) t += red[cc * 128 + tid];
        lq[tid] = t;
    }
    __syncthreads();

    float mx = -1e30f;
    for (int j = tid; j < NTOT; j += 1024) {
        float v = (j < Nn) ? g_logits[b * Nn + j] : lq[j - Nn];
        mx = fmaxf(mx, v);
    }
#pragma unroll
    for (int o = 16; o; o >>= 1) mx = fmaxf(mx, __shfl_xor_sync(0xffffffffu, mx, o));
    if ((tid & 31) == 0) r2[tid >> 5] = mx;
    __syncthreads();
    if (tid < 32) {
        float v = r2[tid];
#pragma unroll
        for (int o = 16; o; o >>= 1) v = fmaxf(v, __shfl_xor_sync(0xffffffffu, v, o));
        r2[tid] = v;
    }
    __syncthreads();
    mx = r2[0];
    __syncthreads();

    float sum = 0.f;
    for (int j = tid; j < NTOT; j += 1024) {
        float v = (j < Nn) ? g_logits[b * Nn + j] : lq[j - Nn];
        float e = expf(v - mx);
        att_s[j] = e;
        sum += e;
    }
#pragma unroll
    for (int o = 16; o; o >>= 1) sum += __shfl_xor_sync(0xffffffffu, sum, o);
    if ((tid & 31) == 0) r2[tid >> 5] = sum;
    __syncthreads();
    if (tid < 32) {
        float v = r2[tid];
#pragma unroll
        for (int o = 16; o; o >>= 1) v += __shfl_xor_sync(0xffffffffu, v, o);
        r2[tid] = v;
    }
    __syncthreads();
    float inv = 1.f / r2[0];
    float* att_g = out + Bn * Mm + b * NTOT;
    for (int j = tid; j < NTOT; j += 1024) att_g[j] = att_s[j] * inv;
}

// ---------------- k4: att_feat partials, n-major coalesced, inverse perm at write ----------------
__global__ void __launch_bounds__(256) k4_kernel(const float* __restrict__ out)
{
    __shared__ float att_s[256];
    __shared__ __align__(16) float buf[8][128];
    const int ch = blockIdx.x;      // 0..15
    const int b  = blockIdx.y;
    const int tid = threadIdx.x, lane = tid & 31, wid = tid >> 5;

    att_s[tid] = out[Bn * Mm + b * NTOT + ch * 256 + tid];
    __syncthreads();

    float a0 = 0.f, a1 = 0.f, a2 = 0.f, a3 = 0.f;
    const __half* base = g_inifeat + ((size_t)b * Nn + ch * 256 + wid * 32) * 128 + lane * 4;
#pragma unroll 8
    for (int r = 0; r < 32; r++) {
        uint2 hv = *(const uint2*)(base + (size_t)r * 128);
        float a = att_s[wid * 32 + r];
        float2 f0 = __half22float2(*(__half2*)&hv.x);
        float2 f1 = __half22float2(*(__half2*)&hv.y);
        a0 += a * f0.x; a1 += a * f0.y; a2 += a * f1.x; a3 += a * f1.y;
    }
    *(float4*)&buf[wid][lane * 4] = make_float4(a0, a1, a2, a3);
    __syncthreads();

    if (tid < 128) {
        float s = 0.f;
#pragma unroll
        for (int w = 0; w < 8; w++) s += buf[w][tid];
        // inverse perm: h -> real m
        int p = tid >> 1, par = tid & 1, w3 = p & 7;
        int kp = ((p >> 3) << 3) | ((w3 & 1) << 2) | (w3 >> 1);
        g_afpart[(b * 16 + ch) * 128 + kp * 2 + par] = s;
    }
}

// ---------------- k5: reduce partials + text tail ----------------
__global__ void __launch_bounds__(128) k5_kernel(float* __restrict__ out)
{
    __shared__ float att_t[128];
    const int b = blockIdx.x, m = threadIdx.x;
    att_t[m] = out[Bn * Mm + b * NTOT + Nn + m];
    __syncthreads();

    float s = 0.f;
#pragma unroll
    for (int ch = 0; ch < 16; ch++) s += g_afpart[(b * 16 + ch) * 128 + m];

    const uint4* q = (const uint4*)(g_inqfeat + (size_t)(b * Mm + m) * Tt);
#pragma unroll
    for (int i = 0; i < 16; i++) {
        uint4 hv = q[i];
        const __half2* hp = (const __half2*)&hv;
#pragma unroll
        for (int j = 0; j < 4; j++) {
            float2 f = __half22float2(hp[j]);
            s += f.x * att_t[i * 8 + j * 2] + f.y * att_t[i * 8 + j * 2 + 1];
        }
    }
    out[b * Mm + m] = s;
}

// ---------------- launch ----------------
extern "C" void kernel_launch(void* const* d_in, const int* in_sizes, int n_in,
                              void* d_out, int out_size)
{
    (void)in_sizes; (void)n_in; (void)out_size;
    const float* img  = (const float*)d_in[0];
    const float* text = (const float*)d_in[1];
    const float* Wimg = (const float*)d_in[2];
    const float* Wtxt = (const float*)d_in[3];
    const float* Wqfc = (const float*)d_in[4];
    const float* Wifc = (const float*)d_in[5];
    const float* Wipc = (const float*)d_in[6];
    const float* Wqpc = (const float*)d_in[7];
    const float* Watt = (const float*)d_in[8];
    float* out = (float*)d_out;

    __half* inq = nullptr; cudaGetSymbolAddress((void**)&inq, g_inqfeat);
    __half* inf = nullptr; cudaGetSymbolAddress((void**)&inf, g_inifeat);

    cudaFuncSetAttribute(fused_kernel<HIDn, Tt, 0>, cudaFuncAttributeMaxDynamicSharedMemorySize, SB_TOT);
    cudaFuncSetAttribute(fused_kernel<Cc, Nn, 1>,   cudaFuncAttributeMaxDynamicSharedMemorySize, SB_TOT);

    prep_a_kernel<<<256, 256>>>(Wtxt);                                      // 1st
    prep_b_kernel<<<128, 256>>>(Wimg, Wipc, Wqpc);                          // 2nd
    fused_kernel<HIDn, Tt, 0><<<Bn, 256, SB_TOT>>>(text, Wqfc, inq);        // 3rd
    fused_kernel<Cc, Nn, 1><<<dim3(32, Bn), 256, SB_TOT>>>(img, Watt, inf); // 4th (profiled)
    k3_kernel<<<Bn, 1024>>>(Wifc, Watt, out);                               // 5th
    k4_kernel<<<dim3(16, Bn), 256>>>(out);                                  // 6th
    k5_kernel<<<Bn, 128>>>(out);                                            // 7th
}

// round 11
// speedup vs baseline: 3.4111x; 1.2285x over previous
#include <cuda_runtime.h>
#include <cuda_fp16.h>
#include <math.h>
#include <cstdint>

// Problem constants
#define Bn   64
#define Cc   256
#define Nn   4096
#define HIDn 512
#define Tt   128
#define Mm   128
#define Aa   128
#define NTOT 4224   // Nn + Tt

// -------- device scratch (allocation-free: __device__ globals) --------
__device__ __half g_WimgP[Mm * Cc];       // permuted fp16 A, img GEMM1
__device__ __half g_WtxtP[Mm * HIDn];     // permuted fp16 A, text GEMM1
__device__ __half g_WipcP[Aa * Mm];       // permuted fp16 A, img GEMM2
__device__ __half g_WqpcP[Aa * Mm];       // permuted fp16 A, text GEMM2
__device__ __half g_inqfeat[Bn * Mm * Tt];    // [b][m][t] fp16, 2 MB
__device__ float  g_qfeatproj[Bn * Tt * Aa];  // TRANSPOSED [b][t][a], 4 MB
__device__ float  g_qfeatatt[Bn * Aa];
__device__ __half g_inifeat[33554432];        // [b][n][mperm] fp16 = 64 MB
__device__ float  g_ipart[Bn * 32 * Mm];
__device__ float  g_logits[Bn * Nn];
__device__ float  g_afpart[Bn * 16 * Mm];

// fast fp32 tanh for low-volume paths
__device__ __forceinline__ float ftanh(float x) {
    x = fminf(fmaxf(x, -15.f), 15.f);
    float e = __expf(2.f * x);
    return __fdividef(e - 1.f, e + 1.f);
}

// HW tanh on packed fp16 pairs: 1 MUFU per 2 values
__device__ __forceinline__ __half2 h2tanh_hw(__half2 x) {
    __half2 r;
    asm("tanh.approx.f16x2 %0, %1;" : "=r"(*(unsigned*)&r) : "r"(*(unsigned*)&x));
    return r;
}

__device__ __forceinline__ void mma_f16(float d[4], const unsigned* a, const unsigned* b) {
    asm volatile("mma.sync.aligned.m16n8k16.row.col.f32.f16.f16.f32 "
                 "{%0,%1,%2,%3}, {%4,%5,%6,%7}, {%8,%9}, {%0,%1,%2,%3};"
                 : "+f"(d[0]), "+f"(d[1]), "+f"(d[2]), "+f"(d[3])
                 : "r"(a[0]), "r"(a[1]), "r"(a[2]), "r"(a[3]), "r"(b[0]), "r"(b[1]));
}

__device__ __forceinline__ uint32_t smem_u32(const void* p) {
    uint32_t r;
    asm("{ .reg .u64 t; cvta.to.shared.u64 t, %1; cvt.u32.u64 %0, t; }" : "=r"(r) : "l"(p));
    return r;
}

// legacy permuted A index (m16n8k16): one uint4 per (slice, mi, lane) = full A fragment
__device__ __forceinline__ int permh_idx(int m, int k) {
    int s = k >> 4, kk = k & 15;
    int khalf = kk >> 3, tig = (kk & 7) >> 1, kp = kk & 1;
    int mi = m >> 4, ml = m & 15, h = ml >> 3, g = ml & 7;
    return ((s * 8 + mi) * 32 + g * 4 + tig) * 8 + khalf * 4 + h * 2 + kp;
}

// fragment-major r-position within a group of 8 k-pairs: pair (r, r+4) adjacent
__device__ __forceinline__ int rpos(int r) { return ((r & 3) << 1) + ((r & 7) >> 2); }

// ---------------- prep (split so img is the 4th launch -> profiled) ----------------
__global__ void prep_a_kernel(const float* __restrict__ Wtxt)
{
    int i = blockIdx.x * blockDim.x + threadIdx.x;   // 0..65535
    int m = i >> 9, k = i & 511;
    g_WtxtP[permh_idx(m, k)] = __float2half(Wtxt[i]);
}

__global__ void prep_b_kernel(const float* __restrict__ Wimg,
                              const float* __restrict__ Wipc, const float* __restrict__ Wqpc)
{
    int i = blockIdx.x * blockDim.x + threadIdx.x;   // 0..32767
    { int m = i >> 8, k = i & 255; g_WimgP[permh_idx(m, k)] = __float2half(Wimg[i]); }
    if (i < Aa * Mm) {
        int a = i >> 7, k = i & 127;
        g_WipcP[permh_idx(a, k)] = __float2half(Wipc[i]);
        g_WqpcP[permh_idx(a, k)] = __float2half(Wqpc[i]);
    }
}

// ---------------- fused dual-GEMM kernel (text MODE=0, img MODE=1) ----------------
// raw fp32 staging: 3 slices x (16 rows x 132 floats = 528 B/row) = 3 x 8448
// B bufs: 128 n x 18 half2 = 9216 B each ; T1: 128 n x 68 half2 = 34816 B
#define SB_RAW 0
#define SB_B0  25344
#define SB_B1  34560
#define SB_T1  43776
#define SB_RED 78592    // 640 floats
#define SB_Q   81152    // 128 floats
#define SB_W   81664    // 128 floats
#define SB_TOT 82176

template<int K1, int LDB, int MODE>
__global__ void __launch_bounds__(256, 2) fused_kernel(
    const float* __restrict__ Bsrc,   // img_feat or text_feat
    const float* __restrict__ Wx,     // Watt (img) / Wqfc (text)
    __half* __restrict__ out1)        // g_inifeat ([n][mperm]) / g_inqfeat ([m][t])
{
    extern __shared__ char smc[];
    __half2* T1  = (__half2*)(smc + SB_T1);
    float* redm = (float*)(smc + SB_RED);
    float* qbuf = (float*)(smc + SB_Q);
    float* wbuf = (float*)(smc + SB_W);

    const int tid  = threadIdx.x;
    const int lane = tid & 31;
    const int w    = tid >> 5;
    const int g    = lane >> 2;
    const int tig  = lane & 3;
    const int wm   = w >> 2;          // 0..1
    const int wn   = w & 3;           // 0..3
    const int mb   = wm * 64;
    const int nb   = wn * 32;

    const int b  = (MODE == 1) ? blockIdx.y : blockIdx.x;
    const int nt = (MODE == 1) ? blockIdx.x : 0;
    const int n0 = nt * 128;

    const uint4* A1P = (const uint4*)((MODE == 1) ? g_WimgP : g_WtxtP);
    const uint4* A2P = (const uint4*)((MODE == 1) ? g_WipcP : g_WqpcP);
    const float* Bb0 = Bsrc + (size_t)b * K1 * LDB + n0;

    if (MODE == 1 && tid < 128) {
        qbuf[tid] = g_qfeatatt[b * Aa + tid];
        wbuf[tid] = Wx[tid];
    }

    // producer / consumer coords
    const int kk2  = tid & 7;
    const int nq   = (tid >> 3) * 4;
    const int poff = rpos(kk2);
    const int mi0  = wm * 4;
    const int nn0  = nb + g;
    const int prow = tid >> 4;                // 0..15 (cp.async row)
    const int pcol = (tid & 15) * 8;          // float column (32 B per thread)
    const uint32_t raw_base = smem_u32(smc) + SB_RAW + prow * 528 + (tid & 15) * 32;

    float acc[4][4][4];
#pragma unroll
    for (int i = 0; i < 4; i++)
#pragma unroll
        for (int j = 0; j < 4; j++)
#pragma unroll
            for (int q = 0; q < 4; q++) acc[i][j][q] = 0.f;

    // ================= GEMM1: cp.async depth-3 pipeline =================
    const int NS1 = K1 / 16;
#pragma unroll
    for (int d = 0; d < 3; d++) {
        const float* src = Bb0 + (size_t)(d * 16 + prow) * LDB + pcol;
        uint32_t dst = raw_base + d * 8448;
        asm volatile("cp.async.cg.shared.global [%0], [%1], 16;\n\t"
                     "cp.async.cg.shared.global [%2], [%3], 16;\n\t"
                     "cp.async.commit_group;"
                     :: "r"(dst), "l"(src), "r"(dst + 16), "l"(src + 4) : "memory");
    }

    for (int s = 0; s < NS1; s++) {
        asm volatile("cp.async.wait_group 2;" ::: "memory");
        __syncthreads();
        const float* raw = (const float*)(smc + SB_RAW + (s % 3) * 8448);
        float4 r0 = *(const float4*)(raw + (2 * kk2) * 132 + nq);
        float4 r1 = *(const float4*)(raw + (2 * kk2 + 1) * 132 + nq);
        __half2* Bb = (__half2*)(smc + ((s & 1) ? SB_B1 : SB_B0));
        Bb[(nq + 0) * 18 + poff] = __floats2half2_rn(r0.x, r1.x);
        Bb[(nq + 1) * 18 + poff] = __floats2half2_rn(r0.y, r1.y);
        Bb[(nq + 2) * 18 + poff] = __floats2half2_rn(r0.z, r1.z);
        Bb[(nq + 3) * 18 + poff] = __floats2half2_rn(r0.w, r1.w);
        __syncthreads();
        if (s + 3 < NS1) {
            const float* src = Bb0 + (size_t)((s + 3) * 16 + prow) * LDB + pcol;
            uint32_t dst = raw_base + (s % 3) * 8448;
            asm volatile("cp.async.cg.shared.global [%0], [%1], 16;\n\t"
                         "cp.async.cg.shared.global [%2], [%3], 16;\n\t"
                         "cp.async.commit_group;"
                         :: "r"(dst), "l"(src), "r"(dst + 16), "l"(src + 4) : "memory");
        } else {
            asm volatile("cp.async.commit_group;" ::: "memory");
        }
        uint4 af[4];
#pragma unroll
        for (int mf = 0; mf < 4; mf++)
            af[mf] = A1P[(s * 8 + mi0 + mf) * 32 + lane];
        const unsigned* Bu = (const unsigned*)Bb;
#pragma unroll
        for (int nf = 0; nf < 4; nf++) {
            int nn = nn0 + nf * 8;
            uint2 bf = *(const uint2*)(Bu + nn * 18 + tig * 2);
#pragma unroll
            for (int mf = 0; mf < 4; mf++)
                mma_f16(acc[mf][nf], (const unsigned*)&af[mf], (const unsigned*)&bf);
        }
    }
    __syncthreads();

    // ============ mid-epilogue: f16x2 tanh, T1 fp16 (fragment-major), row sums ============
    float rp[8];
#pragma unroll
    for (int q = 0; q < 8; q++) rp[q] = 0.f;

#pragma unroll
    for (int mf = 0; mf < 4; mf++) {
        int m0 = mb + mf * 16 + g;
        int kp0 = m0 >> 1;            // even g: pair (m0, m0+1)
        int kp1 = (m0 + 7) >> 1;      // odd g: pair (m0+7, m0+8)
        int o0 = ((kp0 >> 3) << 3) + rpos(kp0);
        int o1 = ((kp1 >> 3) << 3) + rpos(kp1);
#pragma unroll
        for (int nf = 0; nf < 4; nf++) {
            int nl = nb + nf * 8 + tig * 2;
            __half2 h01 = h2tanh_hw(__floats2half2_rn(acc[mf][nf][0], acc[mf][nf][1]));
            __half2 h23 = h2tanh_hw(__floats2half2_rn(acc[mf][nf][2], acc[mf][nf][3]));
            if (MODE == 0) {
                __half* gr0 = out1 + ((size_t)(b * Mm + m0)) * LDB + n0 + nl;
                __half* gr1 = out1 + ((size_t)(b * Mm + m0 + 8)) * LDB + n0 + nl;
                *(__half2*)gr0 = h01;
                *(__half2*)gr1 = h23;
            }
            float2 f01 = __half22float2(h01);
            float2 f23 = __half22float2(h23);
            unsigned u01 = __shfl_xor_sync(0xffffffffu, *(unsigned*)&h01, 4);
            unsigned u23 = __shfl_xor_sync(0xffffffffu, *(unsigned*)&h23, 4);
            __half2 p01 = *(__half2*)&u01;
            __half2 p23 = *(__half2*)&u23;
            if ((g & 1) == 0) {
                __half2 c0 = __lows2half2(h01, p01);
                __half2 c1 = __highs2half2(h01, p01);
                T1[nl * 68 + o0]       = c0;
                T1[(nl + 1) * 68 + o0] = c1;
            } else {
                __half2 c0 = __lows2half2(p23, h23);
                __half2 c1 = __highs2half2(p23, h23);
                T1[nl * 68 + o1]       = c0;
                T1[(nl + 1) * 68 + o1] = c1;
            }
            rp[mf * 2]     += f01.x + f01.y;
            rp[mf * 2 + 1] += f23.x + f23.y;
        }
    }
#pragma unroll
    for (int q = 0; q < 8; q++) {
        rp[q] += __shfl_xor_sync(0xffffffffu, rp[q], 1);
        rp[q] += __shfl_xor_sync(0xffffffffu, rp[q], 2);
    }
    if (tig == 0) {
#pragma unroll
        for (int mf = 0; mf < 4; mf++) {
            redm[(mb + mf * 16 + g) * 5 + wn]     = rp[mf * 2];
            redm[(mb + mf * 16 + g + 8) * 5 + wn] = rp[mf * 2 + 1];
        }
    }
    __syncthreads();
    if (tid < 128) {
        float s = redm[tid * 5] + redm[tid * 5 + 1] + redm[tid * 5 + 2] + redm[tid * 5 + 3];
        if (MODE == 1) g_ipart[(b * 32 + nt) * 128 + tid] = s;
        else           qbuf[tid] = s * (1.f / (float)Tt);
    }
    __syncthreads();
    if (MODE == 0 && tid < 128) {  // qfeatatt[a] = Wqfc[a,:] . qmean
        float s = 0.f;
        const float* wp = Wx + tid * Mm;
#pragma unroll 8
        for (int m = 0; m < Mm; m++) s += wp[m] * qbuf[m];
        g_qfeatatt[b * Aa + tid] = s;
    }

    // ================= GEMM2 (K=128): A global (L1/L2-hot), B = T1, sync-free =================
#pragma unroll
    for (int i = 0; i < 4; i++)
#pragma unroll
        for (int j = 0; j < 4; j++)
#pragma unroll
            for (int q = 0; q < 4; q++) acc[i][j][q] = 0.f;

    const unsigned* T1u = (const unsigned*)T1;
    for (int s2 = 0; s2 < 8; s2++) {
        uint4 af[4];
#pragma unroll
        for (int mf = 0; mf < 4; mf++)
            af[mf] = A2P[(s2 * 8 + mi0 + mf) * 32 + lane];
#pragma unroll
        for (int nf = 0; nf < 4; nf++) {
            int nn = nn0 + nf * 8;
            uint2 bf = *(const uint2*)(T1u + nn * 68 + s2 * 8 + tig * 2);
#pragma unroll
            for (int mf = 0; mf < 4; mf++)
                mma_f16(acc[mf][nf], (const unsigned*)&af[mf], (const unsigned*)&bf);
        }
    }
    __syncthreads();

    // ===== coalesced store: T1 -> g_inifeat[b][n][mperm], whole 128B lines per 8 lanes =====
    if (MODE == 1) {
        const char* t1base = smc + SB_T1;
        const int q = tid & 7;
#pragma unroll
        for (int it = 0; it < 4; it++) {
            int row = (tid >> 3) + it * 32;
            const uint4* src = (const uint4*)(t1base + row * 272);   // 272 = 68 half2 * 4B
            uint4 v0 = src[q * 2];
            uint4 v1 = src[q * 2 + 1];
            uint4* dst = (uint4*)(out1 + ((size_t)b * Nn + n0 + row) * 128 + q * 16);
            dst[0] = v0;
            dst[1] = v1;
        }
    }

    // ================= final epilogue =================
    if (MODE == 1) {
        float p[4][2];
#pragma unroll
        for (int nf = 0; nf < 4; nf++) { p[nf][0] = 0.f; p[nf][1] = 0.f; }
#pragma unroll
        for (int mf = 0; mf < 4; mf++) {
            int a0 = mb + mf * 16 + g, a1 = a0 + 8;
            float w0 = wbuf[a0], q0 = qbuf[a0];
            float w1 = wbuf[a1], q1 = qbuf[a1];
#pragma unroll
            for (int nf = 0; nf < 4; nf++) {
                __half2 t0 = h2tanh_hw(__floats2half2_rn(q0 + acc[mf][nf][0], q0 + acc[mf][nf][1]));
                __half2 t1 = h2tanh_hw(__floats2half2_rn(q1 + acc[mf][nf][2], q1 + acc[mf][nf][3]));
                float2 f0 = __half22float2(t0);
                float2 f1 = __half22float2(t1);
                p[nf][0] += w0 * f0.x + w1 * f1.x;
                p[nf][1] += w0 * f0.y + w1 * f1.y;
            }
        }
#pragma unroll
        for (int nf = 0; nf < 4; nf++)
#pragma unroll
            for (int q = 0; q < 2; q++) {
                p[nf][q] += __shfl_xor_sync(0xffffffffu, p[nf][q], 4);
                p[nf][q] += __shfl_xor_sync(0xffffffffu, p[nf][q], 8);
                p[nf][q] += __shfl_xor_sync(0xffffffffu, p[nf][q], 16);
            }
        if (g == 0) {
#pragma unroll
            for (int nf = 0; nf < 4; nf++) {
                int n = nb + nf * 8 + tig * 2;
                redm[n * 2 + wm]       = p[nf][0];
                redm[(n + 1) * 2 + wm] = p[nf][1];
            }
        }
        __syncthreads();
        if (tid < 128)
            g_logits[b * Nn + n0 + tid] = redm[tid * 2] + redm[tid * 2 + 1];
    } else {
        // store qfeatproj TRANSPOSED fp32 [t][a]
        float* qT = g_qfeatproj + b * (Tt * Aa);
#pragma unroll
        for (int mf = 0; mf < 4; mf++) {
            int a0 = mb + mf * 16 + g;
#pragma unroll
            for (int nf = 0; nf < 4; nf++) {
                int t = nb + nf * 8 + tig * 2;
                qT[t * Aa + a0]           = acc[mf][nf][0];
                qT[(t + 1) * Aa + a0]     = acc[mf][nf][1];
                qT[t * Aa + a0 + 8]       = acc[mf][nf][2];
                qT[(t + 1) * Aa + a0 + 8] = acc[mf][nf][3];
            }
        }
    }
}

// ---------------- k3: imean, ifeatatt, lq, softmax -> att in out ----------------
__global__ void __launch_bounds__(1024) k3_kernel(const float* __restrict__ Wifc,
                                                  const float* __restrict__ Watt,
                                                  float* __restrict__ out)
{
    __shared__ __align__(16) float att_s[NTOT];
    __shared__ float im[128], ia[128], lq[128];
    __shared__ float red[1024];
    __shared__ float r2[32];

    const int tid = threadIdx.x;
    const int b = blockIdx.x;
    const int m = tid & 127, c = tid >> 7;

    {
        float s = 0.f;
#pragma unroll
        for (int j = c * 4; j < c * 4 + 4; j++) s += g_ipart[(b * 32 + j) * 128 + m];
        red[tid] = s;
    }
    __syncthreads();
    if (tid < 128) {
        float t = 0.f;
#pragma unroll
        for (int cc = 0; cc < 8; cc++) t += red[cc * 128 + tid];
        im[tid] = t * (1.f / (float)Nn);
    }
    __syncthreads();
    {
        float t = 0.f;
        const float* wp = Wifc + m * Mm + c * 16;
#pragma unroll
        for (int j = 0; j < 16; j++) t += wp[j] * im[c * 16 + j];
        red[tid] = t;
    }
    __syncthreads();
    if (tid < 128) {
        float t = 0.f;
#pragma unroll
        for (int cc = 0; cc < 8; cc++) t += red[cc * 128 + tid];
        ia[tid] = t;
    }
    __syncthreads();
    {
        float t = 0.f;
        const float4* qp = (const float4*)(g_qfeatproj + b * (Tt * Aa) + m * Aa + c * 16);
#pragma unroll
        for (int j4 = 0; j4 < 4; j4++) {
            float4 v = qp[j4];
            int j = c * 16 + j4 * 4;
            __half2 t0 = h2tanh_hw(__floats2half2_rn(ia[j] + v.x, ia[j + 1] + v.y));
            __half2 t1 = h2tanh_hw(__floats2half2_rn(ia[j + 2] + v.z, ia[j + 3] + v.w));
            float2 f0 = __half22float2(t0);
            float2 f1 = __half22float2(t1);
            t += Watt[j]     * f0.x + Watt[j + 1] * f0.y
               + Watt[j + 2] * f1.x + Watt[j + 3] * f1.y;
        }
        red[tid] = t;
    }
    __syncthreads();
    if (tid < 128) {
        float t = 0.f;
#pragma unroll
        for (int cc = 0; cc < 8; cc++) t += red[cc * 128 + tid];
        lq[tid] = t;
    }
    __syncthreads();

    float mx = -1e30f;
    for (int j = tid; j < NTOT; j += 1024) {
        float v = (j < Nn) ? g_logits[b * Nn + j] : lq[j - Nn];
        mx = fmaxf(mx, v);
    }
#pragma unroll
    for (int o = 16; o; o >>= 1) mx = fmaxf(mx, __shfl_xor_sync(0xffffffffu, mx, o));
    if ((tid & 31) == 0) r2[tid >> 5] = mx;
    __syncthreads();
    if (tid < 32) {
        float v = r2[tid];
#pragma unroll
        for (int o = 16; o; o >>= 1) v = fmaxf(v, __shfl_xor_sync(0xffffffffu, v, o));
        r2[tid] = v;
    }
    __syncthreads();
    mx = r2[0];
    __syncthreads();

    float sum = 0.f;
    for (int j = tid; j < NTOT; j += 1024) {
        float v = (j < Nn) ? g_logits[b * Nn + j] : lq[j - Nn];
        float e = expf(v - mx);
        att_s[j] = e;
        sum += e;
    }
#pragma unroll
    for (int o = 16; o; o >>= 1) sum += __shfl_xor_sync(0xffffffffu, sum, o);
    if ((tid & 31) == 0) r2[tid >> 5] = sum;
    __syncthreads();
    if (tid < 32) {
        float v = r2[tid];
#pragma unroll
        for (int o = 16; o; o >>= 1) v += __shfl_xor_sync(0xffffffffu, v, o);
        r2[tid] = v;
    }
    __syncthreads();
    float inv = 1.f / r2[0];
    float* att_g = out + Bn * Mm + b * NTOT;
    for (int j = tid; j < NTOT; j += 1024) att_g[j] = att_s[j] * inv;
}

// ---------------- k4: att_feat partials, n-major coalesced, inverse perm at write ----------------
__global__ void __launch_bounds__(256) k4_kernel(const float* __restrict__ out)
{
    __shared__ float att_s[256];
    __shared__ __align__(16) float buf[8][128];
    const int ch = blockIdx.x;      // 0..15
    const int b  = blockIdx.y;
    const int tid = threadIdx.x, lane = tid & 31, wid = tid >> 5;

    att_s[tid] = out[Bn * Mm + b * NTOT + ch * 256 + tid];
    __syncthreads();

    float a0 = 0.f, a1 = 0.f, a2 = 0.f, a3 = 0.f;
    const __half* base = g_inifeat + ((size_t)b * Nn + ch * 256 + wid * 32) * 128 + lane * 4;
#pragma unroll 8
    for (int r = 0; r < 32; r++) {
        uint2 hv = *(const uint2*)(base + (size_t)r * 128);
        float a = att_s[wid * 32 + r];
        float2 f0 = __half22float2(*(__half2*)&hv.x);
        float2 f1 = __half22float2(*(__half2*)&hv.y);
        a0 += a * f0.x; a1 += a * f0.y; a2 += a * f1.x; a3 += a * f1.y;
    }
    *(float4*)&buf[wid][lane * 4] = make_float4(a0, a1, a2, a3);
    __syncthreads();

    if (tid < 128) {
        float s = 0.f;
#pragma unroll
        for (int w = 0; w < 8; w++) s += buf[w][tid];
        // inverse perm: h -> real m
        int p = tid >> 1, par = tid & 1, w3 = p & 7;
        int kp = ((p >> 3) << 3) | ((w3 & 1) << 2) | (w3 >> 1);
        g_afpart[(b * 16 + ch) * 128 + kp * 2 + par] = s;
    }
}

// ---------------- k5: reduce partials + text tail ----------------
__global__ void __launch_bounds__(128) k5_kernel(float* __restrict__ out)
{
    __shared__ float att_t[128];
    const int b = blockIdx.x, m = threadIdx.x;
    att_t[m] = out[Bn * Mm + b * NTOT + Nn + m];
    __syncthreads();

    float s = 0.f;
#pragma unroll
    for (int ch = 0; ch < 16; ch++) s += g_afpart[(b * 16 + ch) * 128 + m];

    const uint4* q = (const uint4*)(g_inqfeat + (size_t)(b * Mm + m) * Tt);
#pragma unroll
    for (int i = 0; i < 16; i++) {
        uint4 hv = q[i];
        const __half2* hp = (const __half2*)&hv;
#pragma unroll
        for (int j = 0; j < 4; j++) {
            float2 f = __half22float2(hp[j]);
            s += f.x * att_t[i * 8 + j * 2] + f.y * att_t[i * 8 + j * 2 + 1];
        }
    }
    out[b * Mm + m] = s;
}

// ---------------- launch ----------------
extern "C" void kernel_launch(void* const* d_in, const int* in_sizes, int n_in,
                              void* d_out, int out_size)
{
    (void)in_sizes; (void)n_in; (void)out_size;
    const float* img  = (const float*)d_in[0];
    const float* text = (const float*)d_in[1];
    const float* Wimg = (const float*)d_in[2];
    const float* Wtxt = (const float*)d_in[3];
    const float* Wqfc = (const float*)d_in[4];
    const float* Wifc = (const float*)d_in[5];
    const float* Wipc = (const float*)d_in[6];
    const float* Wqpc = (const float*)d_in[7];
    const float* Watt = (const float*)d_in[8];
    float* out = (float*)d_out;

    __half* inq = nullptr; cudaGetSymbolAddress((void**)&inq, g_inqfeat);
    __half* inf = nullptr; cudaGetSymbolAddress((void**)&inf, g_inifeat);

    cudaFuncSetAttribute(fused_kernel<HIDn, Tt, 0>, cudaFuncAttributeMaxDynamicSharedMemorySize, SB_TOT);
    cudaFuncSetAttribute(fused_kernel<Cc, Nn, 1>,   cudaFuncAttributeMaxDynamicSharedMemorySize, SB_TOT);

    prep_a_kernel<<<256, 256>>>(Wtxt);                                      // 1st
    prep_b_kernel<<<128, 256>>>(Wimg, Wipc, Wqpc);                          // 2nd
    fused_kernel<HIDn, Tt, 0><<<Bn, 256, SB_TOT>>>(text, Wqfc, inq);        // 3rd
    fused_kernel<Cc, Nn, 1><<<dim3(32, Bn), 256, SB_TOT>>>(img, Watt, inf); // 4th (profiled)
    k3_kernel<<<Bn, 1024>>>(Wifc, Watt, out);                               // 5th
    k4_kernel<<<dim3(16, Bn), 256>>>(out);                                  // 6th
    k5_kernel<<<Bn, 128>>>(out);                                            // 7th
}